// round 1
// baseline (speedup 1.0000x reference)
#include <cuda_runtime.h>
#include <math.h>

#define S_LEN 4096
#define DIM   1536
#define NHEAD 12
#define HDIM  128

// scratch (device globals: no cudaMalloc allowed)
__device__ float g_Q[S_LEN * DIM];
__device__ float g_K[S_LEN * DIM];
__device__ float g_V[S_LEN * DIM];
__device__ float g_A[S_LEN * DIM];

// ---------------------------------------------------------------------------
// GEMM:  C[M,N] = A[M,K] @ B[N,K]^T + bias[N]     (both operands K-major)
// BM=BN=64, BK=16, 256 threads, 4x4 microtile per thread
// ---------------------------------------------------------------------------
__global__ void gemm_nt_kernel(const float* __restrict__ A,
                               const float* __restrict__ B,
                               const float* __restrict__ bias,
                               float* __restrict__ C,
                               int M, int N, int K) {
    const int BM = 64, BN = 64, BK = 16;
    __shared__ float As[BK][BM];
    __shared__ float Bs[BK][BN];

    const int tid = threadIdx.x;
    const int bm  = blockIdx.y * BM;
    const int bn  = blockIdx.x * BN;
    const int tr  = tid / 16;      // 0..15 -> rows tr*4..tr*4+3
    const int tc  = tid % 16;      // 0..15 -> cols tc*4..tc*4+3

    const int lm = tid / 4;        // 0..63  (tile row to load)
    const int lk = (tid % 4) * 4;  // 0,4,8,12

    float acc[4][4] = {};

    for (int k0 = 0; k0 < K; k0 += BK) {
        float4 a4 = *(const float4*)&A[(size_t)(bm + lm) * K + k0 + lk];
        float4 b4 = *(const float4*)&B[(size_t)(bn + lm) * K + k0 + lk];
        As[lk + 0][lm] = a4.x; As[lk + 1][lm] = a4.y;
        As[lk + 2][lm] = a4.z; As[lk + 3][lm] = a4.w;
        Bs[lk + 0][lm] = b4.x; Bs[lk + 1][lm] = b4.y;
        Bs[lk + 2][lm] = b4.z; Bs[lk + 3][lm] = b4.w;
        __syncthreads();

        #pragma unroll
        for (int kk = 0; kk < BK; kk++) {
            float4 av = *(const float4*)&As[kk][tr * 4];
            float4 bv = *(const float4*)&Bs[kk][tc * 4];
            float a[4] = {av.x, av.y, av.z, av.w};
            float b[4] = {bv.x, bv.y, bv.z, bv.w};
            #pragma unroll
            for (int i = 0; i < 4; i++)
                #pragma unroll
                for (int j = 0; j < 4; j++)
                    acc[i][j] = fmaf(a[i], b[j], acc[i][j]);
        }
        __syncthreads();
    }

    #pragma unroll
    for (int i = 0; i < 4; i++) {
        int row = bm + tr * 4 + i;
        int col = bn + tc * 4;
        float4 o;
        o.x = acc[i][0] + bias[col + 0];
        o.y = acc[i][1] + bias[col + 1];
        o.z = acc[i][2] + bias[col + 2];
        o.w = acc[i][3] + bias[col + 3];
        *(float4*)&C[(size_t)row * N + col] = o;
    }
}

// ---------------------------------------------------------------------------
// Fused RMSNorm (over full DIM) + RoPE (per 128-dim head, rotate-half)
// One block per sequence row.
// ---------------------------------------------------------------------------
__global__ void rmsnorm_rope_kernel(float* __restrict__ X,
                                    const float* __restrict__ g,
                                    const float* __restrict__ fc,
                                    const float* __restrict__ fs) {
    const int s = blockIdx.x;
    __shared__ float buf[DIM];
    __shared__ float red[8];
    __shared__ float s_scale;

    float* row = X + (size_t)s * DIM;

    float ss = 0.f;
    for (int i = threadIdx.x; i < DIM; i += blockDim.x) {
        float v = row[i];
        buf[i] = v;
        ss += v * v;
    }
    #pragma unroll
    for (int o = 16; o > 0; o >>= 1) ss += __shfl_xor_sync(0xFFFFFFFFu, ss, o);
    if ((threadIdx.x & 31) == 0) red[threadIdx.x >> 5] = ss;
    __syncthreads();
    if (threadIdx.x == 0) {
        float t = 0.f;
        #pragma unroll
        for (int w = 0; w < 8; w++) t += red[w];
        s_scale = rsqrtf(t / (float)DIM + 1e-6f);
    }
    __syncthreads();
    const float scale = s_scale;

    const float* fcs = fc + (size_t)s * HDIM;
    const float* fss = fs + (size_t)s * HDIM;

    for (int i = threadIdx.x; i < DIM; i += blockDim.x) {
        int j = i & (HDIM - 1);            // position within head
        float v = buf[i] * scale * g[i];
        float out;
        if (j < HDIM / 2) {
            float other = buf[i + HDIM / 2] * scale * g[i + HDIM / 2];
            out = v * fcs[j] - other * fss[j];
        } else {
            float other = buf[i - HDIM / 2] * scale * g[i - HDIM / 2];
            out = v * fcs[j] + other * fss[j];
        }
        row[i] = out;
    }
}

// ---------------------------------------------------------------------------
// Flash attention (fp32, online softmax). Br=Bc=64, 256 threads.
// Q/K/V stored [S, DIM], head h occupies columns h*128..h*128+127.
// ---------------------------------------------------------------------------
#define BR 64
#define BC 64
#define QPAD 132   // 128 + 4 pad (float4-aligned, conflict-free)
#define SPAD 65

__global__ void attn_kernel(const float* __restrict__ Q,
                            const float* __restrict__ K,
                            const float* __restrict__ V,
                            float* __restrict__ O) {
    extern __shared__ float sm[];
    float* Qs = sm;                      // BR x QPAD
    float* Ks = Qs + BR * QPAD;          // BC x QPAD
    float* Vs = Ks + BC * QPAD;          // BC x QPAD
    float* Sc = Vs + BC * QPAD;          // BR x SPAD
    float* rm = Sc + BR * SPAD;          // BR
    float* rl = rm + BR;                 // BR
    float* ral = rl + BR;                // BR

    const int h   = blockIdx.y;
    const int q0  = blockIdx.x * BR;
    const int tid = threadIdx.x;
    const float inv_sqrt_d = 0.08838834764831845f;   // 1/sqrt(128)

    // load Q tile
    for (int i = tid; i < BR * (HDIM / 4); i += 256) {
        int r  = i / 32;
        int c4 = (i % 32) * 4;
        float4 v = *(const float4*)&Q[(size_t)(q0 + r) * DIM + h * HDIM + c4];
        *(float4*)&Qs[r * QPAD + c4] = v;
    }
    if (tid < BR) { rm[tid] = -1e30f; rl[tid] = 0.f; }

    const int rs = (tid / 16) * 4;   // 4 S rows / PV rows
    const int cs = (tid % 16) * 4;   // 4 S cols
    const int db = (tid % 16) * 8;   // 8 PV dims

    float acc[4][8] = {};

    for (int kt = 0; kt < S_LEN / BC; kt++) {
        __syncthreads();   // previous PV reads of Ks/Vs/Sc done
        // load K,V tiles
        for (int i = tid; i < BC * (HDIM / 4); i += 256) {
            int r  = i / 32;
            int c4 = (i % 32) * 4;
            size_t gr = (size_t)(kt * BC + r) * DIM + h * HDIM + c4;
            *(float4*)&Ks[r * QPAD + c4] = *(const float4*)&K[gr];
            *(float4*)&Vs[r * QPAD + c4] = *(const float4*)&V[gr];
        }
        __syncthreads();

        // S = Q @ K^T * scale   (4x4 microtile)
        float sacc[4][4] = {};
        #pragma unroll 4
        for (int k = 0; k < HDIM; k += 4) {
            float4 qv[4], kv[4];
            #pragma unroll
            for (int i = 0; i < 4; i++) qv[i] = *(const float4*)&Qs[(rs + i) * QPAD + k];
            #pragma unroll
            for (int j = 0; j < 4; j++) kv[j] = *(const float4*)&Ks[(cs + j) * QPAD + k];
            #pragma unroll
            for (int i = 0; i < 4; i++)
                #pragma unroll
                for (int j = 0; j < 4; j++) {
                    sacc[i][j] = fmaf(qv[i].x, kv[j].x, sacc[i][j]);
                    sacc[i][j] = fmaf(qv[i].y, kv[j].y, sacc[i][j]);
                    sacc[i][j] = fmaf(qv[i].z, kv[j].z, sacc[i][j]);
                    sacc[i][j] = fmaf(qv[i].w, kv[j].w, sacc[i][j]);
                }
        }
        #pragma unroll
        for (int i = 0; i < 4; i++)
            #pragma unroll
            for (int j = 0; j < 4; j++)
                Sc[(rs + i) * SPAD + cs + j] = sacc[i][j] * inv_sqrt_d;
        __syncthreads();

        // online softmax per row (64 threads, one row each)
        if (tid < BR) {
            float m  = rm[tid];
            float mx = m;
            #pragma unroll 8
            for (int c = 0; c < BC; c++) mx = fmaxf(mx, Sc[tid * SPAD + c]);
            float al = __expf(m - mx);
            float l  = rl[tid] * al;
            #pragma unroll 8
            for (int c = 0; c < BC; c++) {
                float p = __expf(Sc[tid * SPAD + c] - mx);
                Sc[tid * SPAD + c] = p;
                l += p;
            }
            rm[tid] = mx; rl[tid] = l; ral[tid] = al;
        }
        __syncthreads();

        // rescale accumulators, then acc += P @ V
        float alpha[4];
        #pragma unroll
        for (int i = 0; i < 4; i++) alpha[i] = ral[rs + i];
        #pragma unroll
        for (int i = 0; i < 4; i++)
            #pragma unroll
            for (int j = 0; j < 8; j++) acc[i][j] *= alpha[i];

        #pragma unroll 4
        for (int c = 0; c < BC; c++) {
            float p[4];
            #pragma unroll
            for (int i = 0; i < 4; i++) p[i] = Sc[(rs + i) * SPAD + c];
            float4 v0 = *(const float4*)&Vs[c * QPAD + db];
            float4 v1 = *(const float4*)&Vs[c * QPAD + db + 4];
            #pragma unroll
            for (int i = 0; i < 4; i++) {
                acc[i][0] = fmaf(p[i], v0.x, acc[i][0]);
                acc[i][1] = fmaf(p[i], v0.y, acc[i][1]);
                acc[i][2] = fmaf(p[i], v0.z, acc[i][2]);
                acc[i][3] = fmaf(p[i], v0.w, acc[i][3]);
                acc[i][4] = fmaf(p[i], v1.x, acc[i][4]);
                acc[i][5] = fmaf(p[i], v1.y, acc[i][5]);
                acc[i][6] = fmaf(p[i], v1.z, acc[i][6]);
                acc[i][7] = fmaf(p[i], v1.w, acc[i][7]);
            }
        }
    }

    // write out (divide by l)
    #pragma unroll
    for (int i = 0; i < 4; i++) {
        float inv_l = 1.f / rl[rs + i];
        float4 o0, o1;
        o0.x = acc[i][0] * inv_l; o0.y = acc[i][1] * inv_l;
        o0.z = acc[i][2] * inv_l; o0.w = acc[i][3] * inv_l;
        o1.x = acc[i][4] * inv_l; o1.y = acc[i][5] * inv_l;
        o1.z = acc[i][6] * inv_l; o1.w = acc[i][7] * inv_l;
        size_t base = (size_t)(q0 + rs + i) * DIM + h * HDIM + db;
        *(float4*)&O[base]     = o0;
        *(float4*)&O[base + 4] = o1;
    }
}

// ---------------------------------------------------------------------------
extern "C" void kernel_launch(void* const* d_in, const int* in_sizes, int n_in,
                              void* d_out, int out_size) {
    const float* x   = (const float*)d_in[0];
    const float* fc  = (const float*)d_in[1];
    const float* fs  = (const float*)d_in[2];
    const float* Wq  = (const float*)d_in[3];
    const float* bq  = (const float*)d_in[4];
    const float* Wk  = (const float*)d_in[5];
    const float* bk  = (const float*)d_in[6];
    const float* Wv  = (const float*)d_in[7];
    const float* bv  = (const float*)d_in[8];
    const float* Wo  = (const float*)d_in[9];
    const float* bo  = (const float*)d_in[10];
    const float* gq  = (const float*)d_in[11];
    const float* gk  = (const float*)d_in[12];
    float* out = (float*)d_out;

    float *dQ, *dK, *dV, *dA;
    cudaGetSymbolAddress((void**)&dQ, g_Q);
    cudaGetSymbolAddress((void**)&dK, g_K);
    cudaGetSymbolAddress((void**)&dV, g_V);
    cudaGetSymbolAddress((void**)&dA, g_A);

    dim3 ggrid(DIM / 64, S_LEN / 64);
    gemm_nt_kernel<<<ggrid, 256>>>(x, Wq, bq, dQ, S_LEN, DIM, DIM);
    gemm_nt_kernel<<<ggrid, 256>>>(x, Wk, bk, dK, S_LEN, DIM, DIM);
    gemm_nt_kernel<<<ggrid, 256>>>(x, Wv, bv, dV, S_LEN, DIM, DIM);

    rmsnorm_rope_kernel<<<S_LEN, 256>>>(dQ, gq, fc, fs);
    rmsnorm_rope_kernel<<<S_LEN, 256>>>(dK, gk, fc, fs);

    size_t smem = (size_t)(BR * QPAD + 2 * BC * QPAD + BR * SPAD + 3 * BR) * sizeof(float);
    static int attn_attr_set = 0;
    if (!attn_attr_set) {
        cudaFuncSetAttribute(attn_kernel, cudaFuncAttributeMaxDynamicSharedMemorySize,
                             (int)smem);
        attn_attr_set = 1;
    }
    dim3 agrid(S_LEN / BR, NHEAD);
    attn_kernel<<<agrid, 256, smem>>>(dQ, dK, dV, dA);

    gemm_nt_kernel<<<ggrid, 256>>>(dA, Wo, bo, out, S_LEN, DIM, DIM);
}

// round 3
// speedup vs baseline: 1.2461x; 1.2461x over previous
#include <cuda_runtime.h>
#include <cuda_bf16.h>
#include <math.h>
#include <stdint.h>

#define S_LEN 4096
#define DIM   1536
#define NHEAD 12
#define HDIM  128

// ---------------------------------------------------------------------------
// scratch (device globals: no cudaMalloc allowed)
// ---------------------------------------------------------------------------
__device__ float g_Q[S_LEN * DIM];
__device__ float g_K[S_LEN * DIM];
__device__ float g_V[S_LEN * DIM];
__device__ float g_A[S_LEN * DIM];

__device__ __align__(128) __nv_bfloat16 g_xh[S_LEN * DIM];
__device__ __align__(128) __nv_bfloat16 g_xl[S_LEN * DIM];
__device__ __align__(128) __nv_bfloat16 g_Ah[S_LEN * DIM];
__device__ __align__(128) __nv_bfloat16 g_Al[S_LEN * DIM];
__device__ __align__(128) __nv_bfloat16 g_Wqh[DIM * DIM];
__device__ __align__(128) __nv_bfloat16 g_Wql[DIM * DIM];
__device__ __align__(128) __nv_bfloat16 g_Wkh[DIM * DIM];
__device__ __align__(128) __nv_bfloat16 g_Wkl[DIM * DIM];
__device__ __align__(128) __nv_bfloat16 g_Wvh[DIM * DIM];
__device__ __align__(128) __nv_bfloat16 g_Wvl[DIM * DIM];
__device__ __align__(128) __nv_bfloat16 g_Woh[DIM * DIM];
__device__ __align__(128) __nv_bfloat16 g_Wol[DIM * DIM];

__device__ __forceinline__ uint32_t smem_u32(const void* p) {
    uint32_t a;
    asm("{ .reg .u64 t; cvta.to.shared.u64 t, %1; cvt.u32.u64 %0, t; }"
        : "=r"(a) : "l"(p));
    return a;
}

__device__ __forceinline__ void ldm_x4(uint32_t* r, uint32_t addr) {
    asm volatile("ldmatrix.sync.aligned.m8n8.x4.shared.b16 {%0,%1,%2,%3}, [%4];"
        : "=r"(r[0]), "=r"(r[1]), "=r"(r[2]), "=r"(r[3]) : "r"(addr));
}

__device__ __forceinline__ void mma_bf16(float* c, const uint32_t* a,
                                         uint32_t b0, uint32_t b1) {
    asm volatile(
        "mma.sync.aligned.m16n8k16.row.col.f32.bf16.bf16.f32 "
        "{%0,%1,%2,%3}, {%4,%5,%6,%7}, {%8,%9}, {%0,%1,%2,%3};"
        : "+f"(c[0]), "+f"(c[1]), "+f"(c[2]), "+f"(c[3])
        : "r"(a[0]), "r"(a[1]), "r"(a[2]), "r"(a[3]), "r"(b0), "r"(b1));
}

#define CP_ASYNC16(saddr, gptr) \
    asm volatile("cp.async.cg.shared.global [%0], [%1], 16;" :: "r"(saddr), "l"(gptr))
#define CP_COMMIT()  asm volatile("cp.async.commit_group;" ::: "memory")
#define CP_WAIT1()   asm volatile("cp.async.wait_group 1;" ::: "memory")
#define CP_WAIT0()   asm volatile("cp.async.wait_group 0;" ::: "memory")

// ---------------------------------------------------------------------------
// split fp32 -> (bf16 hi, bf16 lo)
// ---------------------------------------------------------------------------
__global__ void split_bf16_kernel(const float* __restrict__ src,
                                  __nv_bfloat16* __restrict__ hi,
                                  __nv_bfloat16* __restrict__ lo, int n4) {
    int i = blockIdx.x * blockDim.x + threadIdx.x;
    if (i >= n4) return;
    float4 v = ((const float4*)src)[i];
    __nv_bfloat16 h0 = __float2bfloat16(v.x);
    __nv_bfloat16 h1 = __float2bfloat16(v.y);
    __nv_bfloat16 h2 = __float2bfloat16(v.z);
    __nv_bfloat16 h3 = __float2bfloat16(v.w);
    __nv_bfloat16 l0 = __float2bfloat16(v.x - __bfloat162float(h0));
    __nv_bfloat16 l1 = __float2bfloat16(v.y - __bfloat162float(h1));
    __nv_bfloat16 l2 = __float2bfloat16(v.z - __bfloat162float(h2));
    __nv_bfloat16 l3 = __float2bfloat16(v.w - __bfloat162float(h3));
    ushort4 h4, l4;
    h4.x = __bfloat16_as_ushort(h0); h4.y = __bfloat16_as_ushort(h1);
    h4.z = __bfloat16_as_ushort(h2); h4.w = __bfloat16_as_ushort(h3);
    l4.x = __bfloat16_as_ushort(l0); l4.y = __bfloat16_as_ushort(l1);
    l4.z = __bfloat16_as_ushort(l2); l4.w = __bfloat16_as_ushort(l3);
    *(ushort4*)(hi + 4 * (size_t)i) = h4;
    *(ushort4*)(lo + 4 * (size_t)i) = l4;
}

// ---------------------------------------------------------------------------
// mma.sync bf16x3 GEMM: C[4096,1536] = A @ B^T + bias, A/B as bf16 hi/lo.
// CTA 128x128, BK=32, 8 warps (warp tile 64x32), cp.async double buffer.
// ---------------------------------------------------------------------------
#define GBM 128
#define GBN 128
#define GBK 32
#define G_NC (DIM / GBK)          // 48
#define G_ROWB 80                 // 32 bf16 + 8 pad = 80 bytes per row
#define G_TILEB (128 * G_ROWB)    // 10240
#define G_STAGEB (4 * G_TILEB)    // 40960
#define G_SMEM (2 * G_STAGEB)     // 81920

__global__ __launch_bounds__(256)
void gemm_tc_kernel(const __nv_bfloat16* __restrict__ Ah,
                    const __nv_bfloat16* __restrict__ Al,
                    const __nv_bfloat16* __restrict__ Bh,
                    const __nv_bfloat16* __restrict__ Bl,
                    const float* __restrict__ bias,
                    float* __restrict__ C) {
    extern __shared__ char smem[];
    const uint32_t sbase = smem_u32(smem);
    const int tid  = threadIdx.x;
    const int wid  = tid >> 5;
    const int lane = tid & 31;
    const int bm   = blockIdx.y * GBM;
    const int bn   = blockIdx.x * GBN;
    const int warp_m = wid & 1;    // 0..1 (64 rows each)
    const int warp_n = wid >> 1;   // 0..3 (32 cols each)

    const __nv_bfloat16* basep[4] = {
        Ah + (size_t)bm * DIM, Al + (size_t)bm * DIM,
        Bh + (size_t)bn * DIM, Bl + (size_t)bn * DIM };

    // per-thread copy mapping: 8 x 16B per stage
    const int cp_row[2] = { tid >> 2, (tid + 256) >> 2 };
    const int cp_c4     = tid & 3;

    auto copy_chunk = [&](int c, uint32_t stage) {
        #pragma unroll
        for (int t = 0; t < 4; t++) {
            #pragma unroll
            for (int half = 0; half < 2; half++) {
                const int row = cp_row[half];
                const __nv_bfloat16* g = basep[t] + (size_t)row * DIM + c * GBK + cp_c4 * 8;
                uint32_t s = stage + t * G_TILEB + row * G_ROWB + cp_c4 * 16;
                CP_ASYNC16(s, g);
            }
        }
    };

    float acc[4][4][4] = {};

    copy_chunk(0, sbase);
    CP_COMMIT();

    for (int c = 0; c < G_NC; c++) {
        __syncthreads();   // readers of stage (c+1)&1 (iter c-1) are done
        if (c + 1 < G_NC) {
            copy_chunk(c + 1, sbase + ((c + 1) & 1) * G_STAGEB);
            CP_COMMIT();
            CP_WAIT1();
        } else {
            CP_WAIT0();
        }
        __syncthreads();

        const uint32_t st = sbase + (c & 1) * G_STAGEB;
        const uint32_t aH = st;
        const uint32_t aL = st + G_TILEB;
        const uint32_t bH = st + 2 * G_TILEB;
        const uint32_t bL = st + 3 * G_TILEB;

        #pragma unroll
        for (int kk = 0; kk < GBK; kk += 16) {
            // B fragments (hi & lo): 4 n-tiles, 2 regs each
            uint32_t bhf[8], blf[8];
            #pragma unroll
            for (int nt2 = 0; nt2 < 2; nt2++) {
                const int n  = warp_n * 32 + nt2 * 16 + (lane & 7) + ((lane >> 4) << 3);
                const int kc = kk + (((lane >> 3) & 1) << 3);
                ldm_x4(&bhf[nt2 * 4], bH + n * G_ROWB + kc * 2);
                ldm_x4(&blf[nt2 * 4], bL + n * G_ROWB + kc * 2);
            }
            // A hi fragments: 4 m-tiles, 4 regs each
            uint32_t af[16];
            {
                const int rbase = warp_m * 64 + (lane & 15);
                const int kc    = kk + ((lane >> 4) << 3);
                #pragma unroll
                for (int mt = 0; mt < 4; mt++)
                    ldm_x4(&af[mt * 4], aH + (rbase + mt * 16) * G_ROWB + kc * 2);
            }
            // pass 1: Ah * Bh
            #pragma unroll
            for (int mt = 0; mt < 4; mt++)
                #pragma unroll
                for (int nt = 0; nt < 4; nt++) {
                    const int bi = (nt >> 1) * 4 + (nt & 1) * 2;
                    mma_bf16(acc[mt][nt], &af[mt * 4], bhf[bi], bhf[bi + 1]);
                }
            // pass 2: Ah * Bl
            #pragma unroll
            for (int mt = 0; mt < 4; mt++)
                #pragma unroll
                for (int nt = 0; nt < 4; nt++) {
                    const int bi = (nt >> 1) * 4 + (nt & 1) * 2;
                    mma_bf16(acc[mt][nt], &af[mt * 4], blf[bi], blf[bi + 1]);
                }
            // reload A lo over A hi regs
            {
                const int rbase = warp_m * 64 + (lane & 15);
                const int kc    = kk + ((lane >> 4) << 3);
                #pragma unroll
                for (int mt = 0; mt < 4; mt++)
                    ldm_x4(&af[mt * 4], aL + (rbase + mt * 16) * G_ROWB + kc * 2);
            }
            // pass 3: Al * Bh
            #pragma unroll
            for (int mt = 0; mt < 4; mt++)
                #pragma unroll
                for (int nt = 0; nt < 4; nt++) {
                    const int bi = (nt >> 1) * 4 + (nt & 1) * 2;
                    mma_bf16(acc[mt][nt], &af[mt * 4], bhf[bi], bhf[bi + 1]);
                }
        }
    }

    // epilogue: add bias, write fp32
    #pragma unroll
    for (int mt = 0; mt < 4; mt++) {
        const int row0 = bm + warp_m * 64 + mt * 16 + (lane >> 2);
        #pragma unroll
        for (int nt = 0; nt < 4; nt++) {
            const int col = bn + warp_n * 32 + nt * 8 + ((lane & 3) << 1);
            const float b0 = bias[col], b1 = bias[col + 1];
            float2 v0 = { acc[mt][nt][0] + b0, acc[mt][nt][1] + b1 };
            float2 v1 = { acc[mt][nt][2] + b0, acc[mt][nt][3] + b1 };
            *(float2*)&C[(size_t)row0 * DIM + col]       = v0;
            *(float2*)&C[(size_t)(row0 + 8) * DIM + col] = v1;
        }
    }
}

// ---------------------------------------------------------------------------
// Fused RMSNorm + RoPE
// ---------------------------------------------------------------------------
__global__ void rmsnorm_rope_kernel(float* __restrict__ X,
                                    const float* __restrict__ g,
                                    const float* __restrict__ fc,
                                    const float* __restrict__ fs) {
    const int s = blockIdx.x;
    __shared__ float buf[DIM];
    __shared__ float red[8];
    __shared__ float s_scale;

    float* row = X + (size_t)s * DIM;

    float ss = 0.f;
    for (int i = threadIdx.x; i < DIM; i += blockDim.x) {
        float v = row[i];
        buf[i] = v;
        ss += v * v;
    }
    #pragma unroll
    for (int o = 16; o > 0; o >>= 1) ss += __shfl_xor_sync(0xFFFFFFFFu, ss, o);
    if ((threadIdx.x & 31) == 0) red[threadIdx.x >> 5] = ss;
    __syncthreads();
    if (threadIdx.x == 0) {
        float t = 0.f;
        #pragma unroll
        for (int w = 0; w < 8; w++) t += red[w];
        s_scale = rsqrtf(t / (float)DIM + 1e-6f);
    }
    __syncthreads();
    const float scale = s_scale;

    const float* fcs = fc + (size_t)s * HDIM;
    const float* fss = fs + (size_t)s * HDIM;

    for (int i = threadIdx.x; i < DIM; i += blockDim.x) {
        int j = i & (HDIM - 1);
        float v = buf[i] * scale * g[i];
        float out;
        if (j < HDIM / 2) {
            float other = buf[i + HDIM / 2] * scale * g[i + HDIM / 2];
            out = v * fcs[j] - other * fss[j];
        } else {
            float other = buf[i - HDIM / 2] * scale * g[i - HDIM / 2];
            out = v * fcs[j] + other * fss[j];
        }
        row[i] = out;
    }
}

// ---------------------------------------------------------------------------
// Flash attention (fp32 SIMT)
// ---------------------------------------------------------------------------
#define BR 64
#define BC 64
#define QPAD 132
#define SPAD 65

__global__ void attn_kernel(const float* __restrict__ Q,
                            const float* __restrict__ K,
                            const float* __restrict__ V,
                            float* __restrict__ O) {
    extern __shared__ float sm[];
    float* Qs = sm;
    float* Ks = Qs + BR * QPAD;
    float* Vs = Ks + BC * QPAD;
    float* Sc = Vs + BC * QPAD;
    float* rm = Sc + BR * SPAD;
    float* rl = rm + BR;
    float* ral = rl + BR;

    const int h   = blockIdx.y;
    const int q0  = blockIdx.x * BR;
    const int tid = threadIdx.x;
    const float inv_sqrt_d = 0.08838834764831845f;

    for (int i = tid; i < BR * (HDIM / 4); i += 256) {
        int r  = i / 32;
        int c4 = (i % 32) * 4;
        float4 v = *(const float4*)&Q[(size_t)(q0 + r) * DIM + h * HDIM + c4];
        *(float4*)&Qs[r * QPAD + c4] = v;
    }
    if (tid < BR) { rm[tid] = -1e30f; rl[tid] = 0.f; }

    const int rs = (tid / 16) * 4;
    const int cs = (tid % 16) * 4;
    const int db = (tid % 16) * 8;

    float acc[4][8] = {};

    for (int kt = 0; kt < S_LEN / BC; kt++) {
        __syncthreads();
        for (int i = tid; i < BC * (HDIM / 4); i += 256) {
            int r  = i / 32;
            int c4 = (i % 32) * 4;
            size_t gr = (size_t)(kt * BC + r) * DIM + h * HDIM + c4;
            *(float4*)&Ks[r * QPAD + c4] = *(const float4*)&K[gr];
            *(float4*)&Vs[r * QPAD + c4] = *(const float4*)&V[gr];
        }
        __syncthreads();

        float sacc[4][4] = {};
        #pragma unroll 4
        for (int k = 0; k < HDIM; k += 4) {
            float4 qv[4], kv[4];
            #pragma unroll
            for (int i = 0; i < 4; i++) qv[i] = *(const float4*)&Qs[(rs + i) * QPAD + k];
            #pragma unroll
            for (int j = 0; j < 4; j++) kv[j] = *(const float4*)&Ks[(cs + j) * QPAD + k];
            #pragma unroll
            for (int i = 0; i < 4; i++)
                #pragma unroll
                for (int j = 0; j < 4; j++) {
                    sacc[i][j] = fmaf(qv[i].x, kv[j].x, sacc[i][j]);
                    sacc[i][j] = fmaf(qv[i].y, kv[j].y, sacc[i][j]);
                    sacc[i][j] = fmaf(qv[i].z, kv[j].z, sacc[i][j]);
                    sacc[i][j] = fmaf(qv[i].w, kv[j].w, sacc[i][j]);
                }
        }
        #pragma unroll
        for (int i = 0; i < 4; i++)
            #pragma unroll
            for (int j = 0; j < 4; j++)
                Sc[(rs + i) * SPAD + cs + j] = sacc[i][j] * inv_sqrt_d;
        __syncthreads();

        if (tid < BR) {
            float m  = rm[tid];
            float mx = m;
            #pragma unroll 8
            for (int c = 0; c < BC; c++) mx = fmaxf(mx, Sc[tid * SPAD + c]);
            float al = __expf(m - mx);
            float l  = rl[tid] * al;
            #pragma unroll 8
            for (int c = 0; c < BC; c++) {
                float pp = __expf(Sc[tid * SPAD + c] - mx);
                Sc[tid * SPAD + c] = pp;
                l += pp;
            }
            rm[tid] = mx; rl[tid] = l; ral[tid] = al;
        }
        __syncthreads();

        float alpha[4];
        #pragma unroll
        for (int i = 0; i < 4; i++) alpha[i] = ral[rs + i];
        #pragma unroll
        for (int i = 0; i < 4; i++)
            #pragma unroll
            for (int j = 0; j < 8; j++) acc[i][j] *= alpha[i];

        #pragma unroll 4
        for (int c = 0; c < BC; c++) {
            float pr[4];
            #pragma unroll
            for (int i = 0; i < 4; i++) pr[i] = Sc[(rs + i) * SPAD + c];
            float4 v0 = *(const float4*)&Vs[c * QPAD + db];
            float4 v1 = *(const float4*)&Vs[c * QPAD + db + 4];
            #pragma unroll
            for (int i = 0; i < 4; i++) {
                acc[i][0] = fmaf(pr[i], v0.x, acc[i][0]);
                acc[i][1] = fmaf(pr[i], v0.y, acc[i][1]);
                acc[i][2] = fmaf(pr[i], v0.z, acc[i][2]);
                acc[i][3] = fmaf(pr[i], v0.w, acc[i][3]);
                acc[i][4] = fmaf(pr[i], v1.x, acc[i][4]);
                acc[i][5] = fmaf(pr[i], v1.y, acc[i][5]);
                acc[i][6] = fmaf(pr[i], v1.z, acc[i][6]);
                acc[i][7] = fmaf(pr[i], v1.w, acc[i][7]);
            }
        }
    }

    #pragma unroll
    for (int i = 0; i < 4; i++) {
        float inv_l = 1.f / rl[rs + i];
        float4 o0, o1;
        o0.x = acc[i][0] * inv_l; o0.y = acc[i][1] * inv_l;
        o0.z = acc[i][2] * inv_l; o0.w = acc[i][3] * inv_l;
        o1.x = acc[i][4] * inv_l; o1.y = acc[i][5] * inv_l;
        o1.z = acc[i][6] * inv_l; o1.w = acc[i][7] * inv_l;
        size_t base = (size_t)(q0 + rs + i) * DIM + h * HDIM + db;
        *(float4*)&O[base]     = o0;
        *(float4*)&O[base + 4] = o1;
    }
}

// ---------------------------------------------------------------------------
extern "C" void kernel_launch(void* const* d_in, const int* in_sizes, int n_in,
                              void* d_out, int out_size) {
    const float* x   = (const float*)d_in[0];
    const float* fc  = (const float*)d_in[1];
    const float* fs  = (const float*)d_in[2];
    const float* Wq  = (const float*)d_in[3];
    const float* bq  = (const float*)d_in[4];
    const float* Wk  = (const float*)d_in[5];
    const float* bk  = (const float*)d_in[6];
    const float* Wv  = (const float*)d_in[7];
    const float* bv  = (const float*)d_in[8];
    const float* Wo  = (const float*)d_in[9];
    const float* bo  = (const float*)d_in[10];
    const float* gq  = (const float*)d_in[11];
    const float* gk  = (const float*)d_in[12];
    float* out = (float*)d_out;

    float *dQ, *dK, *dV, *dA;
    cudaGetSymbolAddress((void**)&dQ, g_Q);
    cudaGetSymbolAddress((void**)&dK, g_K);
    cudaGetSymbolAddress((void**)&dV, g_V);
    cudaGetSymbolAddress((void**)&dA, g_A);
    __nv_bfloat16 *xh, *xl, *Ahh, *All;
    __nv_bfloat16 *wqh, *wql, *wkh, *wkl, *wvh, *wvl, *woh, *wol;
    cudaGetSymbolAddress((void**)&xh, g_xh);
    cudaGetSymbolAddress((void**)&xl, g_xl);
    cudaGetSymbolAddress((void**)&Ahh, g_Ah);
    cudaGetSymbolAddress((void**)&All, g_Al);
    cudaGetSymbolAddress((void**)&wqh, g_Wqh);
    cudaGetSymbolAddress((void**)&wql, g_Wql);
    cudaGetSymbolAddress((void**)&wkh, g_Wkh);
    cudaGetSymbolAddress((void**)&wkl, g_Wkl);
    cudaGetSymbolAddress((void**)&wvh, g_Wvh);
    cudaGetSymbolAddress((void**)&wvl, g_Wvl);
    cudaGetSymbolAddress((void**)&woh, g_Woh);
    cudaGetSymbolAddress((void**)&wol, g_Wol);

    const int n4x = S_LEN * DIM / 4;
    const int n4w = DIM * DIM / 4;
    split_bf16_kernel<<<(n4x + 255) / 256, 256>>>(x, xh, xl, n4x);
    split_bf16_kernel<<<(n4w + 255) / 256, 256>>>(Wq, wqh, wql, n4w);
    split_bf16_kernel<<<(n4w + 255) / 256, 256>>>(Wk, wkh, wkl, n4w);
    split_bf16_kernel<<<(n4w + 255) / 256, 256>>>(Wv, wvh, wvl, n4w);
    split_bf16_kernel<<<(n4w + 255) / 256, 256>>>(Wo, woh, wol, n4w);

    cudaFuncSetAttribute(gemm_tc_kernel, cudaFuncAttributeMaxDynamicSharedMemorySize, G_SMEM);
    dim3 ggrid(DIM / GBN, S_LEN / GBM);   // (12, 32)
    gemm_tc_kernel<<<ggrid, 256, G_SMEM>>>(xh, xl, wqh, wql, bq, dQ);
    gemm_tc_kernel<<<ggrid, 256, G_SMEM>>>(xh, xl, wkh, wkl, bk, dK);
    gemm_tc_kernel<<<ggrid, 256, G_SMEM>>>(xh, xl, wvh, wvl, bv, dV);

    rmsnorm_rope_kernel<<<S_LEN, 256>>>(dQ, gq, fc, fs);
    rmsnorm_rope_kernel<<<S_LEN, 256>>>(dK, gk, fc, fs);

    size_t asmem = (size_t)(BR * QPAD + 2 * BC * QPAD + BR * SPAD + 3 * BR) * sizeof(float);
    cudaFuncSetAttribute(attn_kernel, cudaFuncAttributeMaxDynamicSharedMemorySize, (int)asmem);
    dim3 agrid(S_LEN / BR, NHEAD);
    attn_kernel<<<agrid, 256, asmem>>>(dQ, dK, dV, dA);

    split_bf16_kernel<<<(n4x + 255) / 256, 256>>>(dA, Ahh, All, n4x);
    gemm_tc_kernel<<<ggrid, 256, G_SMEM>>>(Ahh, All, woh, wol, bo, out);
}

// round 4
// speedup vs baseline: 3.8183x; 3.0642x over previous
#include <cuda_runtime.h>
#include <cuda_bf16.h>
#include <math.h>
#include <stdint.h>

#define S_LEN 4096
#define DIM   1536
#define NHEAD 12
#define HDIM  128

// ---------------------------------------------------------------------------
// scratch (device globals: no cudaMalloc allowed)
// ---------------------------------------------------------------------------
__device__ float g_Q[S_LEN * DIM];
__device__ float g_K[S_LEN * DIM];
__device__ float g_V[S_LEN * DIM];

__device__ __align__(128) __nv_bfloat16 g_xh[S_LEN * DIM];
__device__ __align__(128) __nv_bfloat16 g_xl[S_LEN * DIM];
__device__ __align__(128) __nv_bfloat16 g_Qh[S_LEN * DIM];
__device__ __align__(128) __nv_bfloat16 g_Ql[S_LEN * DIM];
__device__ __align__(128) __nv_bfloat16 g_Kh[S_LEN * DIM];
__device__ __align__(128) __nv_bfloat16 g_Kl[S_LEN * DIM];
__device__ __align__(128) __nv_bfloat16 g_Vh[S_LEN * DIM];
__device__ __align__(128) __nv_bfloat16 g_Vl[S_LEN * DIM];
__device__ __align__(128) __nv_bfloat16 g_Ah[S_LEN * DIM];
__device__ __align__(128) __nv_bfloat16 g_Al[S_LEN * DIM];
__device__ __align__(128) __nv_bfloat16 g_Wqh[DIM * DIM];
__device__ __align__(128) __nv_bfloat16 g_Wql[DIM * DIM];
__device__ __align__(128) __nv_bfloat16 g_Wkh[DIM * DIM];
__device__ __align__(128) __nv_bfloat16 g_Wkl[DIM * DIM];
__device__ __align__(128) __nv_bfloat16 g_Wvh[DIM * DIM];
__device__ __align__(128) __nv_bfloat16 g_Wvl[DIM * DIM];
__device__ __align__(128) __nv_bfloat16 g_Woh[DIM * DIM];
__device__ __align__(128) __nv_bfloat16 g_Wol[DIM * DIM];

__device__ __forceinline__ uint32_t smem_u32(const void* p) {
    uint32_t a;
    asm("{ .reg .u64 t; cvta.to.shared.u64 t, %1; cvt.u32.u64 %0, t; }"
        : "=r"(a) : "l"(p));
    return a;
}

__device__ __forceinline__ void ldm_x4(uint32_t* r, uint32_t addr) {
    asm volatile("ldmatrix.sync.aligned.m8n8.x4.shared.b16 {%0,%1,%2,%3}, [%4];"
        : "=r"(r[0]), "=r"(r[1]), "=r"(r[2]), "=r"(r[3]) : "r"(addr));
}
__device__ __forceinline__ void ldm_x4_t(uint32_t* r, uint32_t addr) {
    asm volatile("ldmatrix.sync.aligned.m8n8.x4.trans.shared.b16 {%0,%1,%2,%3}, [%4];"
        : "=r"(r[0]), "=r"(r[1]), "=r"(r[2]), "=r"(r[3]) : "r"(addr));
}

__device__ __forceinline__ void mma_bf16(float* c, const uint32_t* a,
                                         uint32_t b0, uint32_t b1) {
    asm volatile(
        "mma.sync.aligned.m16n8k16.row.col.f32.bf16.bf16.f32 "
        "{%0,%1,%2,%3}, {%4,%5,%6,%7}, {%8,%9}, {%0,%1,%2,%3};"
        : "+f"(c[0]), "+f"(c[1]), "+f"(c[2]), "+f"(c[3])
        : "r"(a[0]), "r"(a[1]), "r"(a[2]), "r"(a[3]), "r"(b0), "r"(b1));
}

#define CP_ASYNC16(saddr, gptr) \
    asm volatile("cp.async.cg.shared.global [%0], [%1], 16;" :: "r"(saddr), "l"(gptr))
#define CP_COMMIT()  asm volatile("cp.async.commit_group;" ::: "memory")
#define CP_WAIT1()   asm volatile("cp.async.wait_group 1;" ::: "memory")
#define CP_WAIT0()   asm volatile("cp.async.wait_group 0;" ::: "memory")

__device__ __forceinline__ void split2(float v, __nv_bfloat16& h, __nv_bfloat16& l) {
    h = __float2bfloat16(v);
    l = __float2bfloat16(v - __bfloat162float(h));
}

// ---------------------------------------------------------------------------
// split fp32 -> (bf16 hi, bf16 lo)
// ---------------------------------------------------------------------------
__global__ void split_bf16_kernel(const float* __restrict__ src,
                                  __nv_bfloat16* __restrict__ hi,
                                  __nv_bfloat16* __restrict__ lo, int n4) {
    int i = blockIdx.x * blockDim.x + threadIdx.x;
    if (i >= n4) return;
    float4 v = ((const float4*)src)[i];
    __nv_bfloat16 h0, h1, h2, h3, l0, l1, l2, l3;
    split2(v.x, h0, l0); split2(v.y, h1, l1);
    split2(v.z, h2, l2); split2(v.w, h3, l3);
    ushort4 h4, l4;
    h4.x = __bfloat16_as_ushort(h0); h4.y = __bfloat16_as_ushort(h1);
    h4.z = __bfloat16_as_ushort(h2); h4.w = __bfloat16_as_ushort(h3);
    l4.x = __bfloat16_as_ushort(l0); l4.y = __bfloat16_as_ushort(l1);
    l4.z = __bfloat16_as_ushort(l2); l4.w = __bfloat16_as_ushort(l3);
    *(ushort4*)(hi + 4 * (size_t)i) = h4;
    *(ushort4*)(lo + 4 * (size_t)i) = l4;
}

// ---------------------------------------------------------------------------
// mma.sync bf16x3 GEMM (unchanged from round 3 — verified)
// ---------------------------------------------------------------------------
#define GBM 128
#define GBN 128
#define GBK 32
#define G_NC (DIM / GBK)
#define G_ROWB 80
#define G_TILEB (128 * G_ROWB)
#define G_STAGEB (4 * G_TILEB)
#define G_SMEM (2 * G_STAGEB)

__global__ __launch_bounds__(256)
void gemm_tc_kernel(const __nv_bfloat16* __restrict__ Ah,
                    const __nv_bfloat16* __restrict__ Al,
                    const __nv_bfloat16* __restrict__ Bh,
                    const __nv_bfloat16* __restrict__ Bl,
                    const float* __restrict__ bias,
                    float* __restrict__ C) {
    extern __shared__ char smem[];
    const uint32_t sbase = smem_u32(smem);
    const int tid  = threadIdx.x;
    const int wid  = tid >> 5;
    const int lane = tid & 31;
    const int bm   = blockIdx.y * GBM;
    const int bn   = blockIdx.x * GBN;
    const int warp_m = wid & 1;
    const int warp_n = wid >> 1;

    const __nv_bfloat16* basep[4] = {
        Ah + (size_t)bm * DIM, Al + (size_t)bm * DIM,
        Bh + (size_t)bn * DIM, Bl + (size_t)bn * DIM };

    const int cp_row[2] = { tid >> 2, (tid + 256) >> 2 };
    const int cp_c4     = tid & 3;

    auto copy_chunk = [&](int c, uint32_t stage) {
        #pragma unroll
        for (int t = 0; t < 4; t++) {
            #pragma unroll
            for (int half = 0; half < 2; half++) {
                const int row = cp_row[half];
                const __nv_bfloat16* g = basep[t] + (size_t)row * DIM + c * GBK + cp_c4 * 8;
                uint32_t s = stage + t * G_TILEB + row * G_ROWB + cp_c4 * 16;
                CP_ASYNC16(s, g);
            }
        }
    };

    float acc[4][4][4] = {};

    copy_chunk(0, sbase);
    CP_COMMIT();

    for (int c = 0; c < G_NC; c++) {
        __syncthreads();
        if (c + 1 < G_NC) {
            copy_chunk(c + 1, sbase + ((c + 1) & 1) * G_STAGEB);
            CP_COMMIT();
            CP_WAIT1();
        } else {
            CP_WAIT0();
        }
        __syncthreads();

        const uint32_t st = sbase + (c & 1) * G_STAGEB;
        const uint32_t aH = st;
        const uint32_t aL = st + G_TILEB;
        const uint32_t bH = st + 2 * G_TILEB;
        const uint32_t bL = st + 3 * G_TILEB;

        #pragma unroll
        for (int kk = 0; kk < GBK; kk += 16) {
            uint32_t bhf[8], blf[8];
            #pragma unroll
            for (int nt2 = 0; nt2 < 2; nt2++) {
                const int n  = warp_n * 32 + nt2 * 16 + (lane & 7) + ((lane >> 4) << 3);
                const int kc = kk + (((lane >> 3) & 1) << 3);
                ldm_x4(&bhf[nt2 * 4], bH + n * G_ROWB + kc * 2);
                ldm_x4(&blf[nt2 * 4], bL + n * G_ROWB + kc * 2);
            }
            uint32_t af[16];
            {
                const int rbase = warp_m * 64 + (lane & 15);
                const int kc    = kk + ((lane >> 4) << 3);
                #pragma unroll
                for (int mt = 0; mt < 4; mt++)
                    ldm_x4(&af[mt * 4], aH + (rbase + mt * 16) * G_ROWB + kc * 2);
            }
            #pragma unroll
            for (int mt = 0; mt < 4; mt++)
                #pragma unroll
                for (int nt = 0; nt < 4; nt++) {
                    const int bi = (nt >> 1) * 4 + (nt & 1) * 2;
                    mma_bf16(acc[mt][nt], &af[mt * 4], bhf[bi], bhf[bi + 1]);
                }
            #pragma unroll
            for (int mt = 0; mt < 4; mt++)
                #pragma unroll
                for (int nt = 0; nt < 4; nt++) {
                    const int bi = (nt >> 1) * 4 + (nt & 1) * 2;
                    mma_bf16(acc[mt][nt], &af[mt * 4], blf[bi], blf[bi + 1]);
                }
            {
                const int rbase = warp_m * 64 + (lane & 15);
                const int kc    = kk + ((lane >> 4) << 3);
                #pragma unroll
                for (int mt = 0; mt < 4; mt++)
                    ldm_x4(&af[mt * 4], aL + (rbase + mt * 16) * G_ROWB + kc * 2);
            }
            #pragma unroll
            for (int mt = 0; mt < 4; mt++)
                #pragma unroll
                for (int nt = 0; nt < 4; nt++) {
                    const int bi = (nt >> 1) * 4 + (nt & 1) * 2;
                    mma_bf16(acc[mt][nt], &af[mt * 4], bhf[bi], bhf[bi + 1]);
                }
        }
    }

    #pragma unroll
    for (int mt = 0; mt < 4; mt++) {
        const int row0 = bm + warp_m * 64 + mt * 16 + (lane >> 2);
        #pragma unroll
        for (int nt = 0; nt < 4; nt++) {
            const int col = bn + warp_n * 32 + nt * 8 + ((lane & 3) << 1);
            const float b0 = bias[col], b1 = bias[col + 1];
            float2 v0 = { acc[mt][nt][0] + b0, acc[mt][nt][1] + b1 };
            float2 v1 = { acc[mt][nt][2] + b0, acc[mt][nt][3] + b1 };
            *(float2*)&C[(size_t)row0 * DIM + col]       = v0;
            *(float2*)&C[(size_t)(row0 + 8) * DIM + col] = v1;
        }
    }
}

// ---------------------------------------------------------------------------
// Fused RMSNorm + RoPE, writes bf16 hi/lo splits
// ---------------------------------------------------------------------------
__global__ void rmsnorm_rope_kernel(const float* __restrict__ X,
                                    const float* __restrict__ g,
                                    const float* __restrict__ fc,
                                    const float* __restrict__ fs,
                                    __nv_bfloat16* __restrict__ Oh,
                                    __nv_bfloat16* __restrict__ Ol) {
    const int s = blockIdx.x;
    __shared__ float buf[DIM];
    __shared__ float red[8];
    __shared__ float s_scale;

    const float* row = X + (size_t)s * DIM;

    float ss = 0.f;
    for (int i = threadIdx.x; i < DIM; i += blockDim.x) {
        float v = row[i];
        buf[i] = v;
        ss += v * v;
    }
    #pragma unroll
    for (int o = 16; o > 0; o >>= 1) ss += __shfl_xor_sync(0xFFFFFFFFu, ss, o);
    if ((threadIdx.x & 31) == 0) red[threadIdx.x >> 5] = ss;
    __syncthreads();
    if (threadIdx.x == 0) {
        float t = 0.f;
        #pragma unroll
        for (int w = 0; w < 8; w++) t += red[w];
        s_scale = rsqrtf(t / (float)DIM + 1e-6f);
    }
    __syncthreads();
    const float scale = s_scale;

    const float* fcs = fc + (size_t)s * HDIM;
    const float* fss = fs + (size_t)s * HDIM;

    for (int i = threadIdx.x; i < DIM; i += blockDim.x) {
        int j = i & (HDIM - 1);
        float v = buf[i] * scale * g[i];
        float out;
        if (j < HDIM / 2) {
            float other = buf[i + HDIM / 2] * scale * g[i + HDIM / 2];
            out = v * fcs[j] - other * fss[j];
        } else {
            float other = buf[i - HDIM / 2] * scale * g[i - HDIM / 2];
            out = v * fcs[j] + other * fss[j];
        }
        __nv_bfloat16 h, l;
        split2(out, h, l);
        Oh[(size_t)s * DIM + i] = h;
        Ol[(size_t)s * DIM + i] = l;
    }
}

// ---------------------------------------------------------------------------
// Flash attention on mma.sync bf16x3. BR=BC=64, 8 warps.
// smem: Q hi/lo resident; K/V hi/lo double-buffered (cp.async);
// S fp32; P bf16 hi/lo; online softmax 4 threads/row.
// ---------------------------------------------------------------------------
#define A_PITCH 272               // bytes/row, 128-col bf16 tiles (4-word shift/row)
#define A_TILEB (64 * A_PITCH)    // 17408
#define P_PITCH 144               // bytes/row, 64-col bf16 P tiles
#define OFF_Q    0
#define OFF_KV   (2 * A_TILEB)                      // 34816
#define OFF_S    (OFF_KV + 8 * A_TILEB)             // 174080
#define OFF_PH   (OFF_S + 64 * 66 * 4)              // 190976
#define OFF_PL   (OFF_PH + 64 * P_PITCH)            // 200192
#define OFF_RM   (OFF_PL + 64 * P_PITCH)            // 209408
#define OFF_RL   (OFF_RM + 256)
#define OFF_RAL  (OFF_RL + 256)
#define ATT_SMEM (OFF_RAL + 256)                    // 210176

__global__ __launch_bounds__(256)
void attn_mma_kernel(const __nv_bfloat16* __restrict__ Qh_g,
                     const __nv_bfloat16* __restrict__ Ql_g,
                     const __nv_bfloat16* __restrict__ Kh_g,
                     const __nv_bfloat16* __restrict__ Kl_g,
                     const __nv_bfloat16* __restrict__ Vh_g,
                     const __nv_bfloat16* __restrict__ Vl_g,
                     __nv_bfloat16* __restrict__ Ah_g,
                     __nv_bfloat16* __restrict__ Al_g) {
    extern __shared__ char smem[];
    const uint32_t sb = smem_u32(smem);
    const int tid  = threadIdx.x;
    const int wid  = tid >> 5;
    const int lane = tid & 31;
    const int h    = blockIdx.y;
    const int q0   = blockIdx.x * 64;
    const int warp_m = wid & 1;     // 0..1  (32 S-rows)
    const int warp_n = wid >> 1;    // 0..3  (16 S-cols / 32 O-cols)
    const float inv_sqrt_d = 0.08838834764831845f;

    const uint32_t sQh = sb + OFF_Q;
    const uint32_t sQl = sQh + A_TILEB;
    float* S  = (float*)(smem + OFF_S);
    float* rm = (float*)(smem + OFF_RM);
    float* rl = (float*)(smem + OFF_RL);
    float* ral= (float*)(smem + OFF_RAL);
    const uint32_t sPh = sb + OFF_PH;
    const uint32_t sPl = sb + OFF_PL;

    // ---- prologue loads ----
    {
        const __nv_bfloat16* qsrc[2] = { Qh_g, Ql_g };
        #pragma unroll
        for (int i = 0; i < 8; i++) {
            int cid = i * 256 + tid;
            int tile = cid >> 10, row = (cid >> 4) & 63, c = cid & 15;
            const __nv_bfloat16* gp = qsrc[tile] + (size_t)(q0 + row) * DIM + h * HDIM + c * 8;
            CP_ASYNC16(sQh + tile * A_TILEB + row * A_PITCH + c * 16, gp);
        }
    }
    const __nv_bfloat16* kvsrc[4] = { Kh_g, Kl_g, Vh_g, Vl_g };
    auto load_stage = [&](int kt, int s) {
        uint32_t stb = sb + OFF_KV + s * 4 * A_TILEB;
        #pragma unroll
        for (int i = 0; i < 16; i++) {
            int cid = i * 256 + tid;
            int tile = cid >> 10, row = (cid >> 4) & 63, c = cid & 15;
            const __nv_bfloat16* gp = kvsrc[tile] + (size_t)(kt * 64 + row) * DIM + h * HDIM + c * 8;
            CP_ASYNC16(stb + tile * A_TILEB + row * A_PITCH + c * 16, gp);
        }
    };
    load_stage(0, 0);
    CP_COMMIT();
    load_stage(1, 1);
    CP_COMMIT();

    if (tid < 64) { rm[tid] = -1e30f; rl[tid] = 0.f; }

    float oacc[2][4][4] = {};

    for (int kt = 0; kt < 64; kt++) {
        if (kt < 63) CP_WAIT1(); else CP_WAIT0();
        __syncthreads();
        const uint32_t st  = sb + OFF_KV + (kt & 1) * 4 * A_TILEB;
        const uint32_t sKh = st;
        const uint32_t sKl = st + A_TILEB;
        const uint32_t sVh = st + 2 * A_TILEB;
        const uint32_t sVl = st + 3 * A_TILEB;

        // ---- S = Q @ K^T (bf16x3) ----
        float sacc[2][2][4] = {};
        #pragma unroll
        for (int kk = 0; kk < 8; kk++) {
            uint32_t aqh[8], aql[8], bh[4], bl[4];
            const int rb = warp_m * 32 + (lane & 15);
            const int kc = kk * 16 + ((lane >> 4) << 3);
            ldm_x4(aqh,     sQh + rb * A_PITCH + kc * 2);
            ldm_x4(aqh + 4, sQh + (rb + 16) * A_PITCH + kc * 2);
            ldm_x4(aql,     sQl + rb * A_PITCH + kc * 2);
            ldm_x4(aql + 4, sQl + (rb + 16) * A_PITCH + kc * 2);
            const int nr  = warp_n * 16 + (lane & 7) + ((lane >> 4) << 3);
            const int kc2 = kk * 16 + (((lane >> 3) & 1) << 3);
            ldm_x4(bh, sKh + nr * A_PITCH + kc2 * 2);
            ldm_x4(bl, sKl + nr * A_PITCH + kc2 * 2);
            #pragma unroll
            for (int mt = 0; mt < 2; mt++)
                #pragma unroll
                for (int nt = 0; nt < 2; nt++) {
                    mma_bf16(sacc[mt][nt], aqh + mt * 4, bh[nt * 2], bh[nt * 2 + 1]);
                    mma_bf16(sacc[mt][nt], aqh + mt * 4, bl[nt * 2], bl[nt * 2 + 1]);
                    mma_bf16(sacc[mt][nt], aql + mt * 4, bh[nt * 2], bh[nt * 2 + 1]);
                }
        }
        #pragma unroll
        for (int mt = 0; mt < 2; mt++) {
            const int row = warp_m * 32 + mt * 16 + (lane >> 2);
            #pragma unroll
            for (int nt = 0; nt < 2; nt++) {
                const int col = warp_n * 16 + nt * 8 + ((lane & 3) << 1);
                float2 v0 = { sacc[mt][nt][0] * inv_sqrt_d, sacc[mt][nt][1] * inv_sqrt_d };
                float2 v1 = { sacc[mt][nt][2] * inv_sqrt_d, sacc[mt][nt][3] * inv_sqrt_d };
                *(float2*)&S[row * 66 + col]       = v0;
                *(float2*)&S[(row + 8) * 66 + col] = v1;
            }
        }
        __syncthreads();

        // ---- online softmax, 4 threads per row; write P hi/lo bf16 ----
        {
            const int row  = tid >> 2;
            const int part = tid & 3;
            float* srow = &S[row * 66 + part * 16];
            float mx = -1e30f;
            #pragma unroll
            for (int c = 0; c < 16; c++) mx = fmaxf(mx, srow[c]);
            mx = fmaxf(mx, __shfl_xor_sync(0xFFFFFFFFu, mx, 1));
            mx = fmaxf(mx, __shfl_xor_sync(0xFFFFFFFFu, mx, 2));
            const float mold = rm[row];
            const float mnew = fmaxf(mold, mx);
            float sum = 0.f;
            const uint32_t pb = row * P_PITCH + part * 32;
            #pragma unroll
            for (int c = 0; c < 16; c += 2) {
                float p0 = __expf(srow[c] - mnew);
                float p1 = __expf(srow[c + 1] - mnew);
                sum += p0 + p1;
                __nv_bfloat16 h0, h1, l0, l1;
                split2(p0, h0, l0); split2(p1, h1, l1);
                uint32_t hv = ((uint32_t)__bfloat16_as_ushort(h1) << 16) | __bfloat16_as_ushort(h0);
                uint32_t lv = ((uint32_t)__bfloat16_as_ushort(l1) << 16) | __bfloat16_as_ushort(l0);
                asm volatile("st.shared.b32 [%0], %1;" :: "r"(sPh + pb + c * 2), "r"(hv));
                asm volatile("st.shared.b32 [%0], %1;" :: "r"(sPl + pb + c * 2), "r"(lv));
            }
            sum += __shfl_xor_sync(0xFFFFFFFFu, sum, 1);
            sum += __shfl_xor_sync(0xFFFFFFFFu, sum, 2);
            if (part == 0) {
                const float a = __expf(mold - mnew);
                ral[row] = a;
                rl[row]  = rl[row] * a + sum;
                rm[row]  = mnew;
            }
        }
        __syncthreads();

        // ---- rescale O, then O += P @ V (bf16x3) ----
        #pragma unroll
        for (int mt = 0; mt < 2; mt++) {
            const int r0 = warp_m * 32 + mt * 16 + (lane >> 2);
            const float a0 = ral[r0], a1 = ral[r0 + 8];
            #pragma unroll
            for (int nt = 0; nt < 4; nt++) {
                oacc[mt][nt][0] *= a0; oacc[mt][nt][1] *= a0;
                oacc[mt][nt][2] *= a1; oacc[mt][nt][3] *= a1;
            }
        }
        #pragma unroll
        for (int kk = 0; kk < 4; kk++) {
            uint32_t aph[8], apl[8], bvh[8], bvl[8];
            const int rb = warp_m * 32 + (lane & 15);
            const int kc = kk * 16 + ((lane >> 4) << 3);
            ldm_x4(aph,     sPh + rb * P_PITCH + kc * 2);
            ldm_x4(aph + 4, sPh + (rb + 16) * P_PITCH + kc * 2);
            ldm_x4(apl,     sPl + rb * P_PITCH + kc * 2);
            ldm_x4(apl + 4, sPl + (rb + 16) * P_PITCH + kc * 2);
            const int vr = kk * 16 + (lane & 7) + (((lane >> 3) & 1) << 3);
            const int vc = warp_n * 32 + ((lane >> 4) << 3);
            ldm_x4_t(bvh,     sVh + vr * A_PITCH + vc * 2);
            ldm_x4_t(bvh + 4, sVh + vr * A_PITCH + (vc + 16) * 2);
            ldm_x4_t(bvl,     sVl + vr * A_PITCH + vc * 2);
            ldm_x4_t(bvl + 4, sVl + vr * A_PITCH + (vc + 16) * 2);
            #pragma unroll
            for (int mt = 0; mt < 2; mt++)
                #pragma unroll
                for (int nt = 0; nt < 4; nt++) {
                    mma_bf16(oacc[mt][nt], aph + mt * 4, bvh[nt * 2], bvh[nt * 2 + 1]);
                    mma_bf16(oacc[mt][nt], aph + mt * 4, bvl[nt * 2], bvl[nt * 2 + 1]);
                    mma_bf16(oacc[mt][nt], apl + mt * 4, bvh[nt * 2], bvh[nt * 2 + 1]);
                }
        }
        __syncthreads();

        if (kt + 2 < 64) {
            load_stage(kt + 2, kt & 1);
            CP_COMMIT();
        }
    }

    // ---- epilogue: O /= l, write hi/lo bf16 splits ----
    #pragma unroll
    for (int mt = 0; mt < 2; mt++) {
        const int rloc0 = warp_m * 32 + mt * 16 + (lane >> 2);
        const float inv0 = 1.f / rl[rloc0];
        const float inv1 = 1.f / rl[rloc0 + 8];
        const size_t gr0 = (size_t)(q0 + rloc0) * DIM;
        const size_t gr1 = (size_t)(q0 + rloc0 + 8) * DIM;
        #pragma unroll
        for (int nt = 0; nt < 4; nt++) {
            const int col = h * HDIM + warp_n * 32 + nt * 8 + ((lane & 3) << 1);
            float v0 = oacc[mt][nt][0] * inv0, v1 = oacc[mt][nt][1] * inv0;
            float v2 = oacc[mt][nt][2] * inv1, v3 = oacc[mt][nt][3] * inv1;
            __nv_bfloat16 h0, h1, h2, h3, l0, l1, l2, l3;
            split2(v0, h0, l0); split2(v1, h1, l1);
            split2(v2, h2, l2); split2(v3, h3, l3);
            ushort2 hh0 = { __bfloat16_as_ushort(h0), __bfloat16_as_ushort(h1) };
            ushort2 hh1 = { __bfloat16_as_ushort(h2), __bfloat16_as_ushort(h3) };
            ushort2 ll0 = { __bfloat16_as_ushort(l0), __bfloat16_as_ushort(l1) };
            ushort2 ll1 = { __bfloat16_as_ushort(l2), __bfloat16_as_ushort(l3) };
            *(ushort2*)&Ah_g[gr0 + col] = hh0;
            *(ushort2*)&Ah_g[gr1 + col] = hh1;
            *(ushort2*)&Al_g[gr0 + col] = ll0;
            *(ushort2*)&Al_g[gr1 + col] = ll1;
        }
    }
}

// ---------------------------------------------------------------------------
extern "C" void kernel_launch(void* const* d_in, const int* in_sizes, int n_in,
                              void* d_out, int out_size) {
    const float* x   = (const float*)d_in[0];
    const float* fc  = (const float*)d_in[1];
    const float* fs  = (const float*)d_in[2];
    const float* Wq  = (const float*)d_in[3];
    const float* bq  = (const float*)d_in[4];
    const float* Wk  = (const float*)d_in[5];
    const float* bk  = (const float*)d_in[6];
    const float* Wv  = (const float*)d_in[7];
    const float* bv  = (const float*)d_in[8];
    const float* Wo  = (const float*)d_in[9];
    const float* bo  = (const float*)d_in[10];
    const float* gq  = (const float*)d_in[11];
    const float* gk  = (const float*)d_in[12];
    float* out = (float*)d_out;

    float *dQ, *dK, *dV;
    cudaGetSymbolAddress((void**)&dQ, g_Q);
    cudaGetSymbolAddress((void**)&dK, g_K);
    cudaGetSymbolAddress((void**)&dV, g_V);
    __nv_bfloat16 *xh, *xl, *qh, *ql, *kh, *kl, *vh, *vl, *ah, *al;
    __nv_bfloat16 *wqh, *wql, *wkh, *wkl, *wvh, *wvl, *woh, *wol;
    cudaGetSymbolAddress((void**)&xh, g_xh);
    cudaGetSymbolAddress((void**)&xl, g_xl);
    cudaGetSymbolAddress((void**)&qh, g_Qh);
    cudaGetSymbolAddress((void**)&ql, g_Ql);
    cudaGetSymbolAddress((void**)&kh, g_Kh);
    cudaGetSymbolAddress((void**)&kl, g_Kl);
    cudaGetSymbolAddress((void**)&vh, g_Vh);
    cudaGetSymbolAddress((void**)&vl, g_Vl);
    cudaGetSymbolAddress((void**)&ah, g_Ah);
    cudaGetSymbolAddress((void**)&al, g_Al);
    cudaGetSymbolAddress((void**)&wqh, g_Wqh);
    cudaGetSymbolAddress((void**)&wql, g_Wql);
    cudaGetSymbolAddress((void**)&wkh, g_Wkh);
    cudaGetSymbolAddress((void**)&wkl, g_Wkl);
    cudaGetSymbolAddress((void**)&wvh, g_Wvh);
    cudaGetSymbolAddress((void**)&wvl, g_Wvl);
    cudaGetSymbolAddress((void**)&woh, g_Woh);
    cudaGetSymbolAddress((void**)&wol, g_Wol);

    const int n4x = S_LEN * DIM / 4;
    const int n4w = DIM * DIM / 4;
    split_bf16_kernel<<<(n4x + 255) / 256, 256>>>(x, xh, xl, n4x);
    split_bf16_kernel<<<(n4w + 255) / 256, 256>>>(Wq, wqh, wql, n4w);
    split_bf16_kernel<<<(n4w + 255) / 256, 256>>>(Wk, wkh, wkl, n4w);
    split_bf16_kernel<<<(n4w + 255) / 256, 256>>>(Wv, wvh, wvl, n4w);
    split_bf16_kernel<<<(n4w + 255) / 256, 256>>>(Wo, woh, wol, n4w);

    cudaFuncSetAttribute(gemm_tc_kernel, cudaFuncAttributeMaxDynamicSharedMemorySize, G_SMEM);
    dim3 ggrid(DIM / GBN, S_LEN / GBM);
    gemm_tc_kernel<<<ggrid, 256, G_SMEM>>>(xh, xl, wqh, wql, bq, dQ);
    gemm_tc_kernel<<<ggrid, 256, G_SMEM>>>(xh, xl, wkh, wkl, bk, dK);
    gemm_tc_kernel<<<ggrid, 256, G_SMEM>>>(xh, xl, wvh, wvl, bv, dV);

    rmsnorm_rope_kernel<<<S_LEN, 256>>>(dQ, gq, fc, fs, qh, ql);
    rmsnorm_rope_kernel<<<S_LEN, 256>>>(dK, gk, fc, fs, kh, kl);
    split_bf16_kernel<<<(n4x + 255) / 256, 256>>>(dV, vh, vl, n4x);

    cudaFuncSetAttribute(attn_mma_kernel, cudaFuncAttributeMaxDynamicSharedMemorySize, ATT_SMEM);
    dim3 agrid(S_LEN / 64, NHEAD);
    attn_mma_kernel<<<agrid, 256, ATT_SMEM>>>(qh, ql, kh, kl, vh, vl, ah, al);

    gemm_tc_kernel<<<ggrid, 256, G_SMEM>>>(ah, al, woh, wol, bo, out);
}

// round 5
// speedup vs baseline: 5.6863x; 1.4892x over previous
#include <cuda_runtime.h>
#include <cuda_bf16.h>
#include <cuda_fp16.h>
#include <math.h>
#include <stdint.h>

#define S_LEN 4096
#define DIM   1536
#define NHEAD 12
#define HDIM  128

// ---------------------------------------------------------------------------
// scratch (device globals: no cudaMalloc allowed)
// ---------------------------------------------------------------------------
__device__ float g_Q[S_LEN * DIM];
__device__ float g_K[S_LEN * DIM];
__device__ float g_V[S_LEN * DIM];

__device__ __align__(128) __half g_Qf[S_LEN * DIM];
__device__ __align__(128) __half g_Kf[S_LEN * DIM];
__device__ __align__(128) __half g_Vf[S_LEN * DIM];

__device__ __align__(128) __nv_bfloat16 g_xh[S_LEN * DIM];
__device__ __align__(128) __nv_bfloat16 g_xl[S_LEN * DIM];
__device__ __align__(128) __nv_bfloat16 g_Ah[S_LEN * DIM];
__device__ __align__(128) __nv_bfloat16 g_Al[S_LEN * DIM];
__device__ __align__(128) __nv_bfloat16 g_Wqh[DIM * DIM];
__device__ __align__(128) __nv_bfloat16 g_Wql[DIM * DIM];
__device__ __align__(128) __nv_bfloat16 g_Wkh[DIM * DIM];
__device__ __align__(128) __nv_bfloat16 g_Wkl[DIM * DIM];
__device__ __align__(128) __nv_bfloat16 g_Wvh[DIM * DIM];
__device__ __align__(128) __nv_bfloat16 g_Wvl[DIM * DIM];
__device__ __align__(128) __nv_bfloat16 g_Woh[DIM * DIM];
__device__ __align__(128) __nv_bfloat16 g_Wol[DIM * DIM];

__device__ __forceinline__ uint32_t smem_u32(const void* p) {
    uint32_t a;
    asm("{ .reg .u64 t; cvta.to.shared.u64 t, %1; cvt.u32.u64 %0, t; }"
        : "=r"(a) : "l"(p));
    return a;
}

__device__ __forceinline__ void ldm_x4(uint32_t* r, uint32_t addr) {
    asm volatile("ldmatrix.sync.aligned.m8n8.x4.shared.b16 {%0,%1,%2,%3}, [%4];"
        : "=r"(r[0]), "=r"(r[1]), "=r"(r[2]), "=r"(r[3]) : "r"(addr));
}
__device__ __forceinline__ void ldm_x4_t(uint32_t* r, uint32_t addr) {
    asm volatile("ldmatrix.sync.aligned.m8n8.x4.trans.shared.b16 {%0,%1,%2,%3}, [%4];"
        : "=r"(r[0]), "=r"(r[1]), "=r"(r[2]), "=r"(r[3]) : "r"(addr));
}

__device__ __forceinline__ void mma_bf16(float* c, const uint32_t* a,
                                         uint32_t b0, uint32_t b1) {
    asm volatile(
        "mma.sync.aligned.m16n8k16.row.col.f32.bf16.bf16.f32 "
        "{%0,%1,%2,%3}, {%4,%5,%6,%7}, {%8,%9}, {%0,%1,%2,%3};"
        : "+f"(c[0]), "+f"(c[1]), "+f"(c[2]), "+f"(c[3])
        : "r"(a[0]), "r"(a[1]), "r"(a[2]), "r"(a[3]), "r"(b0), "r"(b1));
}
__device__ __forceinline__ void mma_fp16(float* c, const uint32_t* a,
                                         uint32_t b0, uint32_t b1) {
    asm volatile(
        "mma.sync.aligned.m16n8k16.row.col.f32.f16.f16.f32 "
        "{%0,%1,%2,%3}, {%4,%5,%6,%7}, {%8,%9}, {%0,%1,%2,%3};"
        : "+f"(c[0]), "+f"(c[1]), "+f"(c[2]), "+f"(c[3])
        : "r"(a[0]), "r"(a[1]), "r"(a[2]), "r"(a[3]), "r"(b0), "r"(b1));
}

#define CP_ASYNC16(saddr, gptr) \
    asm volatile("cp.async.cg.shared.global [%0], [%1], 16;" :: "r"(saddr), "l"(gptr))
#define CP_COMMIT()  asm volatile("cp.async.commit_group;" ::: "memory")
#define CP_WAIT1()   asm volatile("cp.async.wait_group 1;" ::: "memory")
#define CP_WAIT0()   asm volatile("cp.async.wait_group 0;" ::: "memory")

__device__ __forceinline__ void split2(float v, __nv_bfloat16& h, __nv_bfloat16& l) {
    h = __float2bfloat16(v);
    l = __float2bfloat16(v - __bfloat162float(h));
}

// ---------------------------------------------------------------------------
// split fp32 -> (bf16 hi, bf16 lo)
// ---------------------------------------------------------------------------
__global__ void split_bf16_kernel(const float* __restrict__ src,
                                  __nv_bfloat16* __restrict__ hi,
                                  __nv_bfloat16* __restrict__ lo, int n4) {
    int i = blockIdx.x * blockDim.x + threadIdx.x;
    if (i >= n4) return;
    float4 v = ((const float4*)src)[i];
    __nv_bfloat16 h0, h1, h2, h3, l0, l1, l2, l3;
    split2(v.x, h0, l0); split2(v.y, h1, l1);
    split2(v.z, h2, l2); split2(v.w, h3, l3);
    ushort4 h4, l4;
    h4.x = __bfloat16_as_ushort(h0); h4.y = __bfloat16_as_ushort(h1);
    h4.z = __bfloat16_as_ushort(h2); h4.w = __bfloat16_as_ushort(h3);
    l4.x = __bfloat16_as_ushort(l0); l4.y = __bfloat16_as_ushort(l1);
    l4.z = __bfloat16_as_ushort(l2); l4.w = __bfloat16_as_ushort(l3);
    *(ushort4*)(hi + 4 * (size_t)i) = h4;
    *(ushort4*)(lo + 4 * (size_t)i) = l4;
}

// fp32 -> fp16 single
__global__ void tofp16_kernel(const float* __restrict__ src,
                              __half* __restrict__ dst, int n4) {
    int i = blockIdx.x * blockDim.x + threadIdx.x;
    if (i >= n4) return;
    float4 v = ((const float4*)src)[i];
    __half2 a = __floats2half2_rn(v.x, v.y);
    __half2 b = __floats2half2_rn(v.z, v.w);
    uint2 o = { *(uint32_t*)&a, *(uint32_t*)&b };
    *(uint2*)(dst + 4 * (size_t)i) = o;
}

// ---------------------------------------------------------------------------
// mma.sync bf16x3 GEMM (verified rounds 3-4, unchanged)
// ---------------------------------------------------------------------------
#define GBM 128
#define GBN 128
#define GBK 32
#define G_NC (DIM / GBK)
#define G_ROWB 80
#define G_TILEB (128 * G_ROWB)
#define G_STAGEB (4 * G_TILEB)
#define G_SMEM (2 * G_STAGEB)

__global__ __launch_bounds__(256)
void gemm_tc_kernel(const __nv_bfloat16* __restrict__ Ah,
                    const __nv_bfloat16* __restrict__ Al,
                    const __nv_bfloat16* __restrict__ Bh,
                    const __nv_bfloat16* __restrict__ Bl,
                    const float* __restrict__ bias,
                    float* __restrict__ C) {
    extern __shared__ char smem[];
    const uint32_t sbase = smem_u32(smem);
    const int tid  = threadIdx.x;
    const int wid  = tid >> 5;
    const int lane = tid & 31;
    const int bm   = blockIdx.y * GBM;
    const int bn   = blockIdx.x * GBN;
    const int warp_m = wid & 1;
    const int warp_n = wid >> 1;

    const __nv_bfloat16* basep[4] = {
        Ah + (size_t)bm * DIM, Al + (size_t)bm * DIM,
        Bh + (size_t)bn * DIM, Bl + (size_t)bn * DIM };

    const int cp_row[2] = { tid >> 2, (tid + 256) >> 2 };
    const int cp_c4     = tid & 3;

    auto copy_chunk = [&](int c, uint32_t stage) {
        #pragma unroll
        for (int t = 0; t < 4; t++) {
            #pragma unroll
            for (int half = 0; half < 2; half++) {
                const int row = cp_row[half];
                const __nv_bfloat16* g = basep[t] + (size_t)row * DIM + c * GBK + cp_c4 * 8;
                uint32_t s = stage + t * G_TILEB + row * G_ROWB + cp_c4 * 16;
                CP_ASYNC16(s, g);
            }
        }
    };

    float acc[4][4][4] = {};

    copy_chunk(0, sbase);
    CP_COMMIT();

    for (int c = 0; c < G_NC; c++) {
        __syncthreads();
        if (c + 1 < G_NC) {
            copy_chunk(c + 1, sbase + ((c + 1) & 1) * G_STAGEB);
            CP_COMMIT();
            CP_WAIT1();
        } else {
            CP_WAIT0();
        }
        __syncthreads();

        const uint32_t st = sbase + (c & 1) * G_STAGEB;
        const uint32_t aH = st;
        const uint32_t aL = st + G_TILEB;
        const uint32_t bH = st + 2 * G_TILEB;
        const uint32_t bL = st + 3 * G_TILEB;

        #pragma unroll
        for (int kk = 0; kk < GBK; kk += 16) {
            uint32_t bhf[8], blf[8];
            #pragma unroll
            for (int nt2 = 0; nt2 < 2; nt2++) {
                const int n  = warp_n * 32 + nt2 * 16 + (lane & 7) + ((lane >> 4) << 3);
                const int kc = kk + (((lane >> 3) & 1) << 3);
                ldm_x4(&bhf[nt2 * 4], bH + n * G_ROWB + kc * 2);
                ldm_x4(&blf[nt2 * 4], bL + n * G_ROWB + kc * 2);
            }
            uint32_t af[16];
            {
                const int rbase = warp_m * 64 + (lane & 15);
                const int kc    = kk + ((lane >> 4) << 3);
                #pragma unroll
                for (int mt = 0; mt < 4; mt++)
                    ldm_x4(&af[mt * 4], aH + (rbase + mt * 16) * G_ROWB + kc * 2);
            }
            #pragma unroll
            for (int mt = 0; mt < 4; mt++)
                #pragma unroll
                for (int nt = 0; nt < 4; nt++) {
                    const int bi = (nt >> 1) * 4 + (nt & 1) * 2;
                    mma_bf16(acc[mt][nt], &af[mt * 4], bhf[bi], bhf[bi + 1]);
                }
            #pragma unroll
            for (int mt = 0; mt < 4; mt++)
                #pragma unroll
                for (int nt = 0; nt < 4; nt++) {
                    const int bi = (nt >> 1) * 4 + (nt & 1) * 2;
                    mma_bf16(acc[mt][nt], &af[mt * 4], blf[bi], blf[bi + 1]);
                }
            {
                const int rbase = warp_m * 64 + (lane & 15);
                const int kc    = kk + ((lane >> 4) << 3);
                #pragma unroll
                for (int mt = 0; mt < 4; mt++)
                    ldm_x4(&af[mt * 4], aL + (rbase + mt * 16) * G_ROWB + kc * 2);
            }
            #pragma unroll
            for (int mt = 0; mt < 4; mt++)
                #pragma unroll
                for (int nt = 0; nt < 4; nt++) {
                    const int bi = (nt >> 1) * 4 + (nt & 1) * 2;
                    mma_bf16(acc[mt][nt], &af[mt * 4], bhf[bi], bhf[bi + 1]);
                }
        }
    }

    #pragma unroll
    for (int mt = 0; mt < 4; mt++) {
        const int row0 = bm + warp_m * 64 + mt * 16 + (lane >> 2);
        #pragma unroll
        for (int nt = 0; nt < 4; nt++) {
            const int col = bn + warp_n * 32 + nt * 8 + ((lane & 3) << 1);
            const float b0 = bias[col], b1 = bias[col + 1];
            float2 v0 = { acc[mt][nt][0] + b0, acc[mt][nt][1] + b1 };
            float2 v1 = { acc[mt][nt][2] + b0, acc[mt][nt][3] + b1 };
            *(float2*)&C[(size_t)row0 * DIM + col]       = v0;
            *(float2*)&C[(size_t)(row0 + 8) * DIM + col] = v1;
        }
    }
}

// ---------------------------------------------------------------------------
// Fused RMSNorm + RoPE, writes fp16 (single)
// ---------------------------------------------------------------------------
__global__ void rmsnorm_rope_kernel(const float* __restrict__ X,
                                    const float* __restrict__ g,
                                    const float* __restrict__ fc,
                                    const float* __restrict__ fs,
                                    __half* __restrict__ O) {
    const int s = blockIdx.x;
    __shared__ float buf[DIM];
    __shared__ float red[8];
    __shared__ float s_scale;

    const float* row = X + (size_t)s * DIM;

    float ss = 0.f;
    for (int i = threadIdx.x; i < DIM; i += blockDim.x) {
        float v = row[i];
        buf[i] = v;
        ss += v * v;
    }
    #pragma unroll
    for (int o = 16; o > 0; o >>= 1) ss += __shfl_xor_sync(0xFFFFFFFFu, ss, o);
    if ((threadIdx.x & 31) == 0) red[threadIdx.x >> 5] = ss;
    __syncthreads();
    if (threadIdx.x == 0) {
        float t = 0.f;
        #pragma unroll
        for (int w = 0; w < 8; w++) t += red[w];
        s_scale = rsqrtf(t / (float)DIM + 1e-6f);
    }
    __syncthreads();
    const float scale = s_scale;

    const float* fcs = fc + (size_t)s * HDIM;
    const float* fss = fs + (size_t)s * HDIM;

    for (int i = threadIdx.x; i < DIM; i += blockDim.x) {
        int j = i & (HDIM - 1);
        float v = buf[i] * scale * g[i];
        float out;
        if (j < HDIM / 2) {
            float other = buf[i + HDIM / 2] * scale * g[i + HDIM / 2];
            out = v * fcs[j] - other * fss[j];
        } else {
            float other = buf[i - HDIM / 2] * scale * g[i - HDIM / 2];
            out = v * fcs[j] + other * fss[j];
        }
        O[(size_t)s * DIM + i] = __float2half(out);
    }
}

// ---------------------------------------------------------------------------
// Flash attention, fp16 single-pass mma. BR=BC=64, 8 warps.
// Q resident; K/V double-buffered (cp.async); S fp32; P fp16;
// online softmax 4 threads/row; epilogue writes bf16 hi/lo for Wo gemm.
// ---------------------------------------------------------------------------
#define A_PITCH 272               // bytes/row, 128-col fp16 tiles
#define A_TILEB (64 * A_PITCH)    // 17408
#define P_PITCH 144               // bytes/row, 64-col fp16 P tile
#define OFF_Q    0
#define OFF_KV   A_TILEB                            // 17408: K0,V0,K1,V1
#define OFF_S    (OFF_KV + 4 * A_TILEB)             // 87040
#define OFF_P    (OFF_S + 64 * 66 * 4)              // 103936
#define OFF_RM   (OFF_P + 64 * P_PITCH)             // 113152
#define OFF_RL   (OFF_RM + 256)
#define OFF_RAL  (OFF_RL + 256)
#define ATT_SMEM (OFF_RAL + 256)                    // 113920

__global__ __launch_bounds__(256)
void attn_mma_kernel(const __half* __restrict__ Q_g,
                     const __half* __restrict__ K_g,
                     const __half* __restrict__ V_g,
                     __nv_bfloat16* __restrict__ Ah_g,
                     __nv_bfloat16* __restrict__ Al_g) {
    extern __shared__ char smem[];
    const uint32_t sb = smem_u32(smem);
    const int tid  = threadIdx.x;
    const int wid  = tid >> 5;
    const int lane = tid & 31;
    const int h    = blockIdx.y;
    const int q0   = blockIdx.x * 64;
    const int warp_m = wid & 1;
    const int warp_n = wid >> 1;
    const float inv_sqrt_d = 0.08838834764831845f;

    const uint32_t sQ = sb + OFF_Q;
    float* S  = (float*)(smem + OFF_S);
    float* rm = (float*)(smem + OFF_RM);
    float* rl = (float*)(smem + OFF_RL);
    float* ral= (float*)(smem + OFF_RAL);
    const uint32_t sP = sb + OFF_P;

    // ---- prologue loads ----
    #pragma unroll
    for (int i = 0; i < 4; i++) {
        int cid = i * 256 + tid;
        int row = cid >> 4, c = cid & 15;
        const __half* gp = Q_g + (size_t)(q0 + row) * DIM + h * HDIM + c * 8;
        CP_ASYNC16(sQ + row * A_PITCH + c * 16, gp);
    }
    const __half* kvsrc[2] = { K_g, V_g };
    auto load_stage = [&](int kt, int s) {
        uint32_t stb = sb + OFF_KV + s * 2 * A_TILEB;
        #pragma unroll
        for (int i = 0; i < 8; i++) {
            int cid = i * 256 + tid;
            int tile = cid >> 10, row = (cid >> 4) & 63, c = cid & 15;
            const __half* gp = kvsrc[tile] + (size_t)(kt * 64 + row) * DIM + h * HDIM + c * 8;
            CP_ASYNC16(stb + tile * A_TILEB + row * A_PITCH + c * 16, gp);
        }
    };
    load_stage(0, 0);
    CP_COMMIT();
    load_stage(1, 1);
    CP_COMMIT();

    if (tid < 64) { rm[tid] = -1e30f; rl[tid] = 0.f; }

    float oacc[2][4][4] = {};

    for (int kt = 0; kt < 64; kt++) {
        if (kt < 63) CP_WAIT1(); else CP_WAIT0();
        __syncthreads();
        const uint32_t st = sb + OFF_KV + (kt & 1) * 2 * A_TILEB;
        const uint32_t sK = st;
        const uint32_t sV = st + A_TILEB;

        // ---- S = Q @ K^T (single fp16 pass) ----
        float sacc[2][2][4] = {};
        #pragma unroll
        for (int kk = 0; kk < 8; kk++) {
            uint32_t aq[8], bk[4];
            const int rb = warp_m * 32 + (lane & 15);
            const int kc = kk * 16 + ((lane >> 4) << 3);
            ldm_x4(aq,     sQ + rb * A_PITCH + kc * 2);
            ldm_x4(aq + 4, sQ + (rb + 16) * A_PITCH + kc * 2);
            const int nr  = warp_n * 16 + (lane & 7) + ((lane >> 4) << 3);
            const int kc2 = kk * 16 + (((lane >> 3) & 1) << 3);
            ldm_x4(bk, sK + nr * A_PITCH + kc2 * 2);
            #pragma unroll
            for (int mt = 0; mt < 2; mt++)
                #pragma unroll
                for (int nt = 0; nt < 2; nt++)
                    mma_fp16(sacc[mt][nt], aq + mt * 4, bk[nt * 2], bk[nt * 2 + 1]);
        }
        #pragma unroll
        for (int mt = 0; mt < 2; mt++) {
            const int row = warp_m * 32 + mt * 16 + (lane >> 2);
            #pragma unroll
            for (int nt = 0; nt < 2; nt++) {
                const int col = warp_n * 16 + nt * 8 + ((lane & 3) << 1);
                float2 v0 = { sacc[mt][nt][0] * inv_sqrt_d, sacc[mt][nt][1] * inv_sqrt_d };
                float2 v1 = { sacc[mt][nt][2] * inv_sqrt_d, sacc[mt][nt][3] * inv_sqrt_d };
                *(float2*)&S[row * 66 + col]       = v0;
                *(float2*)&S[(row + 8) * 66 + col] = v1;
            }
        }
        __syncthreads();

        // ---- online softmax, 4 threads per row; write P fp16 ----
        {
            const int row  = tid >> 2;
            const int part = tid & 3;
            float* srow = &S[row * 66 + part * 16];
            float mx = -1e30f;
            #pragma unroll
            for (int c = 0; c < 16; c++) mx = fmaxf(mx, srow[c]);
            mx = fmaxf(mx, __shfl_xor_sync(0xFFFFFFFFu, mx, 1));
            mx = fmaxf(mx, __shfl_xor_sync(0xFFFFFFFFu, mx, 2));
            const float mold = rm[row];
            const float mnew = fmaxf(mold, mx);
            float sum = 0.f;
            const uint32_t pb = row * P_PITCH + part * 32;
            #pragma unroll
            for (int c = 0; c < 16; c += 2) {
                float p0 = __expf(srow[c] - mnew);
                float p1 = __expf(srow[c + 1] - mnew);
                sum += p0 + p1;
                __half2 hp = __floats2half2_rn(p0, p1);
                uint32_t hv = *(uint32_t*)&hp;
                asm volatile("st.shared.b32 [%0], %1;" :: "r"(sP + pb + c * 2), "r"(hv));
            }
            sum += __shfl_xor_sync(0xFFFFFFFFu, sum, 1);
            sum += __shfl_xor_sync(0xFFFFFFFFu, sum, 2);
            if (part == 0) {
                const float a = __expf(mold - mnew);
                ral[row] = a;
                rl[row]  = rl[row] * a + sum;
                rm[row]  = mnew;
            }
        }
        __syncthreads();

        // ---- rescale O, then O += P @ V (single fp16 pass) ----
        #pragma unroll
        for (int mt = 0; mt < 2; mt++) {
            const int r0 = warp_m * 32 + mt * 16 + (lane >> 2);
            const float a0 = ral[r0], a1 = ral[r0 + 8];
            #pragma unroll
            for (int nt = 0; nt < 4; nt++) {
                oacc[mt][nt][0] *= a0; oacc[mt][nt][1] *= a0;
                oacc[mt][nt][2] *= a1; oacc[mt][nt][3] *= a1;
            }
        }
        #pragma unroll
        for (int kk = 0; kk < 4; kk++) {
            uint32_t ap[8], bv[8];
            const int rb = warp_m * 32 + (lane & 15);
            const int kc = kk * 16 + ((lane >> 4) << 3);
            ldm_x4(ap,     sP + rb * P_PITCH + kc * 2);
            ldm_x4(ap + 4, sP + (rb + 16) * P_PITCH + kc * 2);
            const int vr = kk * 16 + (lane & 7) + (((lane >> 3) & 1) << 3);
            const int vc = warp_n * 32 + ((lane >> 4) << 3);
            ldm_x4_t(bv,     sV + vr * A_PITCH + vc * 2);
            ldm_x4_t(bv + 4, sV + vr * A_PITCH + (vc + 16) * 2);
            #pragma unroll
            for (int mt = 0; mt < 2; mt++)
                #pragma unroll
                for (int nt = 0; nt < 4; nt++)
                    mma_fp16(oacc[mt][nt], ap + mt * 4, bv[nt * 2], bv[nt * 2 + 1]);
        }
        __syncthreads();

        if (kt + 2 < 64) {
            load_stage(kt + 2, kt & 1);
            CP_COMMIT();
        }
    }

    // ---- epilogue: O /= l, write bf16 hi/lo splits ----
    #pragma unroll
    for (int mt = 0; mt < 2; mt++) {
        const int rloc0 = warp_m * 32 + mt * 16 + (lane >> 2);
        const float inv0 = 1.f / rl[rloc0];
        const float inv1 = 1.f / rl[rloc0 + 8];
        const size_t gr0 = (size_t)(q0 + rloc0) * DIM;
        const size_t gr1 = (size_t)(q0 + rloc0 + 8) * DIM;
        #pragma unroll
        for (int nt = 0; nt < 4; nt++) {
            const int col = h * HDIM + warp_n * 32 + nt * 8 + ((lane & 3) << 1);
            float v0 = oacc[mt][nt][0] * inv0, v1 = oacc[mt][nt][1] * inv0;
            float v2 = oacc[mt][nt][2] * inv1, v3 = oacc[mt][nt][3] * inv1;
            __nv_bfloat16 h0, h1, h2, h3, l0, l1, l2, l3;
            split2(v0, h0, l0); split2(v1, h1, l1);
            split2(v2, h2, l2); split2(v3, h3, l3);
            ushort2 hh0 = { __bfloat16_as_ushort(h0), __bfloat16_as_ushort(h1) };
            ushort2 hh1 = { __bfloat16_as_ushort(h2), __bfloat16_as_ushort(h3) };
            ushort2 ll0 = { __bfloat16_as_ushort(l0), __bfloat16_as_ushort(l1) };
            ushort2 ll1 = { __bfloat16_as_ushort(l2), __bfloat16_as_ushort(l3) };
            *(ushort2*)&Ah_g[gr0 + col] = hh0;
            *(ushort2*)&Ah_g[gr1 + col] = hh1;
            *(ushort2*)&Al_g[gr0 + col] = ll0;
            *(ushort2*)&Al_g[gr1 + col] = ll1;
        }
    }
}

// ---------------------------------------------------------------------------
extern "C" void kernel_launch(void* const* d_in, const int* in_sizes, int n_in,
                              void* d_out, int out_size) {
    const float* x   = (const float*)d_in[0];
    const float* fc  = (const float*)d_in[1];
    const float* fs  = (const float*)d_in[2];
    const float* Wq  = (const float*)d_in[3];
    const float* bq  = (const float*)d_in[4];
    const float* Wk  = (const float*)d_in[5];
    const float* bk  = (const float*)d_in[6];
    const float* Wv  = (const float*)d_in[7];
    const float* bv  = (const float*)d_in[8];
    const float* Wo  = (const float*)d_in[9];
    const float* bo  = (const float*)d_in[10];
    const float* gq  = (const float*)d_in[11];
    const float* gk  = (const float*)d_in[12];
    float* out = (float*)d_out;

    float *dQ, *dK, *dV;
    cudaGetSymbolAddress((void**)&dQ, g_Q);
    cudaGetSymbolAddress((void**)&dK, g_K);
    cudaGetSymbolAddress((void**)&dV, g_V);
    __half *qf, *kf, *vf;
    cudaGetSymbolAddress((void**)&qf, g_Qf);
    cudaGetSymbolAddress((void**)&kf, g_Kf);
    cudaGetSymbolAddress((void**)&vf, g_Vf);
    __nv_bfloat16 *xh, *xl, *ah, *al;
    __nv_bfloat16 *wqh, *wql, *wkh, *wkl, *wvh, *wvl, *woh, *wol;
    cudaGetSymbolAddress((void**)&xh, g_xh);
    cudaGetSymbolAddress((void**)&xl, g_xl);
    cudaGetSymbolAddress((void**)&ah, g_Ah);
    cudaGetSymbolAddress((void**)&al, g_Al);
    cudaGetSymbolAddress((void**)&wqh, g_Wqh);
    cudaGetSymbolAddress((void**)&wql, g_Wql);
    cudaGetSymbolAddress((void**)&wkh, g_Wkh);
    cudaGetSymbolAddress((void**)&wkl, g_Wkl);
    cudaGetSymbolAddress((void**)&wvh, g_Wvh);
    cudaGetSymbolAddress((void**)&wvl, g_Wvl);
    cudaGetSymbolAddress((void**)&woh, g_Woh);
    cudaGetSymbolAddress((void**)&wol, g_Wol);

    const int n4x = S_LEN * DIM / 4;
    const int n4w = DIM * DIM / 4;
    split_bf16_kernel<<<(n4x + 255) / 256, 256>>>(x, xh, xl, n4x);
    split_bf16_kernel<<<(n4w + 255) / 256, 256>>>(Wq, wqh, wql, n4w);
    split_bf16_kernel<<<(n4w + 255) / 256, 256>>>(Wk, wkh, wkl, n4w);
    split_bf16_kernel<<<(n4w + 255) / 256, 256>>>(Wv, wvh, wvl, n4w);
    split_bf16_kernel<<<(n4w + 255) / 256, 256>>>(Wo, woh, wol, n4w);

    cudaFuncSetAttribute(gemm_tc_kernel, cudaFuncAttributeMaxDynamicSharedMemorySize, G_SMEM);
    dim3 ggrid(DIM / GBN, S_LEN / GBM);
    gemm_tc_kernel<<<ggrid, 256, G_SMEM>>>(xh, xl, wqh, wql, bq, dQ);
    gemm_tc_kernel<<<ggrid, 256, G_SMEM>>>(xh, xl, wkh, wkl, bk, dK);
    gemm_tc_kernel<<<ggrid, 256, G_SMEM>>>(xh, xl, wvh, wvl, bv, dV);

    rmsnorm_rope_kernel<<<S_LEN, 256>>>(dQ, gq, fc, fs, qf);
    rmsnorm_rope_kernel<<<S_LEN, 256>>>(dK, gk, fc, fs, kf);
    tofp16_kernel<<<(n4x + 255) / 256, 256>>>(dV, vf, n4x);

    cudaFuncSetAttribute(attn_mma_kernel, cudaFuncAttributeMaxDynamicSharedMemorySize, ATT_SMEM);
    dim3 agrid(S_LEN / 64, NHEAD);
    attn_mma_kernel<<<agrid, 256, ATT_SMEM>>>(qf, kf, vf, ah, al);

    gemm_tc_kernel<<<ggrid, 256, G_SMEM>>>(ah, al, woh, wol, bo, out);
}

// round 6
// speedup vs baseline: 6.5774x; 1.1567x over previous
#include <cuda_runtime.h>
#include <cuda_bf16.h>
#include <cuda_fp16.h>
#include <math.h>
#include <stdint.h>

#define S_LEN 4096
#define DIM   1536
#define NHEAD 12
#define HDIM  128

// ---------------------------------------------------------------------------
// scratch (device globals: no cudaMalloc allowed)
// ---------------------------------------------------------------------------
__device__ float g_Q[S_LEN * DIM];
__device__ float g_K[S_LEN * DIM];
__device__ float g_V[S_LEN * DIM];

__device__ __align__(128) __half g_xf[S_LEN * DIM];
__device__ __align__(128) __half g_Af[S_LEN * DIM];
__device__ __align__(128) __half g_Qf[S_LEN * DIM];
__device__ __align__(128) __half g_Kf[S_LEN * DIM];
__device__ __align__(128) __half g_Vf[S_LEN * DIM];

__device__ __align__(128) __half g_Wqh[DIM * DIM];
__device__ __align__(128) __half g_Wql[DIM * DIM];
__device__ __align__(128) __half g_Wkh[DIM * DIM];
__device__ __align__(128) __half g_Wkl[DIM * DIM];
__device__ __align__(128) __half g_Wvh[DIM * DIM];
__device__ __align__(128) __half g_Wvl[DIM * DIM];
__device__ __align__(128) __half g_Woh[DIM * DIM];
__device__ __align__(128) __half g_Wol[DIM * DIM];

__device__ __forceinline__ uint32_t smem_u32(const void* p) {
    uint32_t a;
    asm("{ .reg .u64 t; cvta.to.shared.u64 t, %1; cvt.u32.u64 %0, t; }"
        : "=r"(a) : "l"(p));
    return a;
}

__device__ __forceinline__ void ldm_x4(uint32_t* r, uint32_t addr) {
    asm volatile("ldmatrix.sync.aligned.m8n8.x4.shared.b16 {%0,%1,%2,%3}, [%4];"
        : "=r"(r[0]), "=r"(r[1]), "=r"(r[2]), "=r"(r[3]) : "r"(addr));
}
__device__ __forceinline__ void ldm_x4_t(uint32_t* r, uint32_t addr) {
    asm volatile("ldmatrix.sync.aligned.m8n8.x4.trans.shared.b16 {%0,%1,%2,%3}, [%4];"
        : "=r"(r[0]), "=r"(r[1]), "=r"(r[2]), "=r"(r[3]) : "r"(addr));
}

__device__ __forceinline__ void mma_fp16(float* c, const uint32_t* a,
                                         uint32_t b0, uint32_t b1) {
    asm volatile(
        "mma.sync.aligned.m16n8k16.row.col.f32.f16.f16.f32 "
        "{%0,%1,%2,%3}, {%4,%5,%6,%7}, {%8,%9}, {%0,%1,%2,%3};"
        : "+f"(c[0]), "+f"(c[1]), "+f"(c[2]), "+f"(c[3])
        : "r"(a[0]), "r"(a[1]), "r"(a[2]), "r"(a[3]), "r"(b0), "r"(b1));
}

#define CP_ASYNC16(saddr, gptr) \
    asm volatile("cp.async.cg.shared.global [%0], [%1], 16;" :: "r"(saddr), "l"(gptr))
#define CP_COMMIT()  asm volatile("cp.async.commit_group;" ::: "memory")
#define CP_WAIT1()   asm volatile("cp.async.wait_group 1;" ::: "memory")
#define CP_WAIT0()   asm volatile("cp.async.wait_group 0;" ::: "memory")

// ---------------------------------------------------------------------------
// fp32 -> fp16 single
// ---------------------------------------------------------------------------
__global__ void tofp16_kernel(const float* __restrict__ src,
                              __half* __restrict__ dst, int n4) {
    int i = blockIdx.x * blockDim.x + threadIdx.x;
    if (i >= n4) return;
    float4 v = ((const float4*)src)[i];
    __half2 a = __floats2half2_rn(v.x, v.y);
    __half2 b = __floats2half2_rn(v.z, v.w);
    uint2 o = { *(uint32_t*)&a, *(uint32_t*)&b };
    *(uint2*)(dst + 4 * (size_t)i) = o;
}

// fp32 -> (fp16 hi, fp16 lo)
__global__ void split_fp16_kernel(const float* __restrict__ src,
                                  __half* __restrict__ hi,
                                  __half* __restrict__ lo, int n4) {
    int i = blockIdx.x * blockDim.x + threadIdx.x;
    if (i >= n4) return;
    float4 v = ((const float4*)src)[i];
    float f[4] = { v.x, v.y, v.z, v.w };
    __half h[4], l[4];
    #pragma unroll
    for (int k = 0; k < 4; k++) {
        h[k] = __float2half_rn(f[k]);
        l[k] = __float2half_rn(f[k] - __half2float(h[k]));
    }
    ushort4 h4 = { __half_as_ushort(h[0]), __half_as_ushort(h[1]),
                   __half_as_ushort(h[2]), __half_as_ushort(h[3]) };
    ushort4 l4 = { __half_as_ushort(l[0]), __half_as_ushort(l[1]),
                   __half_as_ushort(l[2]), __half_as_ushort(l[3]) };
    *(ushort4*)(hi + 4 * (size_t)i) = h4;
    *(ushort4*)(lo + 4 * (size_t)i) = l4;
}

// ---------------------------------------------------------------------------
// mma.sync fp16 2-pass GEMM: C = A @ (Bh+Bl)^T + bias
// A single fp16; B split fp16 hi/lo. CTA 128x128, BK=32, 8 warps.
// ---------------------------------------------------------------------------
#define GBM 128
#define GBN 128
#define GBK 32
#define G_NC (DIM / GBK)
#define G_ROWB 80
#define G_TILEB (128 * G_ROWB)
#define G_STAGEB (3 * G_TILEB)   // A, Bh, Bl
#define G_SMEM (2 * G_STAGEB)    // 61440

__global__ __launch_bounds__(256)
void gemm_tc_kernel(const __half* __restrict__ A,
                    const __half* __restrict__ Bh,
                    const __half* __restrict__ Bl,
                    const float* __restrict__ bias,
                    float* __restrict__ C) {
    extern __shared__ char smem[];
    const uint32_t sbase = smem_u32(smem);
    const int tid  = threadIdx.x;
    const int wid  = tid >> 5;
    const int lane = tid & 31;
    const int bm   = blockIdx.y * GBM;
    const int bn   = blockIdx.x * GBN;
    const int warp_m = wid & 1;
    const int warp_n = wid >> 1;

    const __half* basep[3] = {
        A + (size_t)bm * DIM, Bh + (size_t)bn * DIM, Bl + (size_t)bn * DIM };

    const int cp_row[2] = { tid >> 2, (tid + 256) >> 2 };
    const int cp_c4     = tid & 3;

    auto copy_chunk = [&](int c, uint32_t stage) {
        #pragma unroll
        for (int t = 0; t < 3; t++) {
            #pragma unroll
            for (int half = 0; half < 2; half++) {
                const int row = cp_row[half];
                const __half* g = basep[t] + (size_t)row * DIM + c * GBK + cp_c4 * 8;
                uint32_t s = stage + t * G_TILEB + row * G_ROWB + cp_c4 * 16;
                CP_ASYNC16(s, g);
            }
        }
    };

    float acc[4][4][4] = {};

    copy_chunk(0, sbase);
    CP_COMMIT();

    for (int c = 0; c < G_NC; c++) {
        __syncthreads();
        if (c + 1 < G_NC) {
            copy_chunk(c + 1, sbase + ((c + 1) & 1) * G_STAGEB);
            CP_COMMIT();
            CP_WAIT1();
        } else {
            CP_WAIT0();
        }
        __syncthreads();

        const uint32_t st = sbase + (c & 1) * G_STAGEB;
        const uint32_t aT = st;
        const uint32_t bH = st + G_TILEB;
        const uint32_t bL = st + 2 * G_TILEB;

        #pragma unroll
        for (int kk = 0; kk < GBK; kk += 16) {
            uint32_t bhf[8], blf[8];
            #pragma unroll
            for (int nt2 = 0; nt2 < 2; nt2++) {
                const int n  = warp_n * 32 + nt2 * 16 + (lane & 7) + ((lane >> 4) << 3);
                const int kc = kk + (((lane >> 3) & 1) << 3);
                ldm_x4(&bhf[nt2 * 4], bH + n * G_ROWB + kc * 2);
                ldm_x4(&blf[nt2 * 4], bL + n * G_ROWB + kc * 2);
            }
            uint32_t af[16];
            {
                const int rbase = warp_m * 64 + (lane & 15);
                const int kc    = kk + ((lane >> 4) << 3);
                #pragma unroll
                for (int mt = 0; mt < 4; mt++)
                    ldm_x4(&af[mt * 4], aT + (rbase + mt * 16) * G_ROWB + kc * 2);
            }
            #pragma unroll
            for (int mt = 0; mt < 4; mt++)
                #pragma unroll
                for (int nt = 0; nt < 4; nt++) {
                    const int bi = (nt >> 1) * 4 + (nt & 1) * 2;
                    mma_fp16(acc[mt][nt], &af[mt * 4], bhf[bi], bhf[bi + 1]);
                }
            #pragma unroll
            for (int mt = 0; mt < 4; mt++)
                #pragma unroll
                for (int nt = 0; nt < 4; nt++) {
                    const int bi = (nt >> 1) * 4 + (nt & 1) * 2;
                    mma_fp16(acc[mt][nt], &af[mt * 4], blf[bi], blf[bi + 1]);
                }
        }
    }

    #pragma unroll
    for (int mt = 0; mt < 4; mt++) {
        const int row0 = bm + warp_m * 64 + mt * 16 + (lane >> 2);
        #pragma unroll
        for (int nt = 0; nt < 4; nt++) {
            const int col = bn + warp_n * 32 + nt * 8 + ((lane & 3) << 1);
            const float b0 = bias[col], b1 = bias[col + 1];
            float2 v0 = { acc[mt][nt][0] + b0, acc[mt][nt][1] + b1 };
            float2 v1 = { acc[mt][nt][2] + b0, acc[mt][nt][3] + b1 };
            *(float2*)&C[(size_t)row0 * DIM + col]       = v0;
            *(float2*)&C[(size_t)(row0 + 8) * DIM + col] = v1;
        }
    }
}

// ---------------------------------------------------------------------------
// Fused RMSNorm + RoPE, writes fp16
// ---------------------------------------------------------------------------
__global__ void rmsnorm_rope_kernel(const float* __restrict__ X,
                                    const float* __restrict__ g,
                                    const float* __restrict__ fc,
                                    const float* __restrict__ fs,
                                    __half* __restrict__ O) {
    const int s = blockIdx.x;
    __shared__ float buf[DIM];
    __shared__ float red[8];
    __shared__ float s_scale;

    const float* row = X + (size_t)s * DIM;

    float ss = 0.f;
    for (int i = threadIdx.x; i < DIM; i += blockDim.x) {
        float v = row[i];
        buf[i] = v;
        ss += v * v;
    }
    #pragma unroll
    for (int o = 16; o > 0; o >>= 1) ss += __shfl_xor_sync(0xFFFFFFFFu, ss, o);
    if ((threadIdx.x & 31) == 0) red[threadIdx.x >> 5] = ss;
    __syncthreads();
    if (threadIdx.x == 0) {
        float t = 0.f;
        #pragma unroll
        for (int w = 0; w < 8; w++) t += red[w];
        s_scale = rsqrtf(t / (float)DIM + 1e-6f);
    }
    __syncthreads();
    const float scale = s_scale;

    const float* fcs = fc + (size_t)s * HDIM;
    const float* fss = fs + (size_t)s * HDIM;

    for (int i = threadIdx.x; i < DIM; i += blockDim.x) {
        int j = i & (HDIM - 1);
        float v = buf[i] * scale * g[i];
        float out;
        if (j < HDIM / 2) {
            float other = buf[i + HDIM / 2] * scale * g[i + HDIM / 2];
            out = v * fcs[j] - other * fss[j];
        } else {
            float other = buf[i - HDIM / 2] * scale * g[i - HDIM / 2];
            out = v * fcs[j] + other * fss[j];
        }
        O[(size_t)s * DIM + i] = __float2half(out);
    }
}

// ---------------------------------------------------------------------------
// Flash attention, fp16 mma. BR=BC=64, 8 warps. (verified round 5)
// Epilogue now writes single fp16 A.
// ---------------------------------------------------------------------------
#define A_PITCH 272
#define A_TILEB (64 * A_PITCH)
#define P_PITCH 144
#define OFF_Q    0
#define OFF_KV   A_TILEB
#define OFF_S    (OFF_KV + 4 * A_TILEB)
#define OFF_P    (OFF_S + 64 * 66 * 4)
#define OFF_RM   (OFF_P + 64 * P_PITCH)
#define OFF_RL   (OFF_RM + 256)
#define OFF_RAL  (OFF_RL + 256)
#define ATT_SMEM (OFF_RAL + 256)

__global__ __launch_bounds__(256)
void attn_mma_kernel(const __half* __restrict__ Q_g,
                     const __half* __restrict__ K_g,
                     const __half* __restrict__ V_g,
                     __half* __restrict__ A_g) {
    extern __shared__ char smem[];
    const uint32_t sb = smem_u32(smem);
    const int tid  = threadIdx.x;
    const int wid  = tid >> 5;
    const int lane = tid & 31;
    const int h    = blockIdx.y;
    const int q0   = blockIdx.x * 64;
    const int warp_m = wid & 1;
    const int warp_n = wid >> 1;
    const float inv_sqrt_d = 0.08838834764831845f;

    const uint32_t sQ = sb + OFF_Q;
    float* S  = (float*)(smem + OFF_S);
    float* rm = (float*)(smem + OFF_RM);
    float* rl = (float*)(smem + OFF_RL);
    float* ral= (float*)(smem + OFF_RAL);
    const uint32_t sP = sb + OFF_P;

    #pragma unroll
    for (int i = 0; i < 4; i++) {
        int cid = i * 256 + tid;
        int row = cid >> 4, c = cid & 15;
        const __half* gp = Q_g + (size_t)(q0 + row) * DIM + h * HDIM + c * 8;
        CP_ASYNC16(sQ + row * A_PITCH + c * 16, gp);
    }
    const __half* kvsrc[2] = { K_g, V_g };
    auto load_stage = [&](int kt, int s) {
        uint32_t stb = sb + OFF_KV + s * 2 * A_TILEB;
        #pragma unroll
        for (int i = 0; i < 8; i++) {
            int cid = i * 256 + tid;
            int tile = cid >> 10, row = (cid >> 4) & 63, c = cid & 15;
            const __half* gp = kvsrc[tile] + (size_t)(kt * 64 + row) * DIM + h * HDIM + c * 8;
            CP_ASYNC16(stb + tile * A_TILEB + row * A_PITCH + c * 16, gp);
        }
    };
    load_stage(0, 0);
    CP_COMMIT();
    load_stage(1, 1);
    CP_COMMIT();

    if (tid < 64) { rm[tid] = -1e30f; rl[tid] = 0.f; }

    float oacc[2][4][4] = {};

    for (int kt = 0; kt < 64; kt++) {
        if (kt < 63) CP_WAIT1(); else CP_WAIT0();
        __syncthreads();
        const uint32_t st = sb + OFF_KV + (kt & 1) * 2 * A_TILEB;
        const uint32_t sK = st;
        const uint32_t sV = st + A_TILEB;

        float sacc[2][2][4] = {};
        #pragma unroll
        for (int kk = 0; kk < 8; kk++) {
            uint32_t aq[8], bk[4];
            const int rb = warp_m * 32 + (lane & 15);
            const int kc = kk * 16 + ((lane >> 4) << 3);
            ldm_x4(aq,     sQ + rb * A_PITCH + kc * 2);
            ldm_x4(aq + 4, sQ + (rb + 16) * A_PITCH + kc * 2);
            const int nr  = warp_n * 16 + (lane & 7) + ((lane >> 4) << 3);
            const int kc2 = kk * 16 + (((lane >> 3) & 1) << 3);
            ldm_x4(bk, sK + nr * A_PITCH + kc2 * 2);
            #pragma unroll
            for (int mt = 0; mt < 2; mt++)
                #pragma unroll
                for (int nt = 0; nt < 2; nt++)
                    mma_fp16(sacc[mt][nt], aq + mt * 4, bk[nt * 2], bk[nt * 2 + 1]);
        }
        #pragma unroll
        for (int mt = 0; mt < 2; mt++) {
            const int row = warp_m * 32 + mt * 16 + (lane >> 2);
            #pragma unroll
            for (int nt = 0; nt < 2; nt++) {
                const int col = warp_n * 16 + nt * 8 + ((lane & 3) << 1);
                float2 v0 = { sacc[mt][nt][0] * inv_sqrt_d, sacc[mt][nt][1] * inv_sqrt_d };
                float2 v1 = { sacc[mt][nt][2] * inv_sqrt_d, sacc[mt][nt][3] * inv_sqrt_d };
                *(float2*)&S[row * 66 + col]       = v0;
                *(float2*)&S[(row + 8) * 66 + col] = v1;
            }
        }
        __syncthreads();

        {
            const int row  = tid >> 2;
            const int part = tid & 3;
            float* srow = &S[row * 66 + part * 16];
            float mx = -1e30f;
            #pragma unroll
            for (int c = 0; c < 16; c++) mx = fmaxf(mx, srow[c]);
            mx = fmaxf(mx, __shfl_xor_sync(0xFFFFFFFFu, mx, 1));
            mx = fmaxf(mx, __shfl_xor_sync(0xFFFFFFFFu, mx, 2));
            const float mold = rm[row];
            const float mnew = fmaxf(mold, mx);
            float sum = 0.f;
            const uint32_t pb = row * P_PITCH + part * 32;
            #pragma unroll
            for (int c = 0; c < 16; c += 2) {
                float p0 = __expf(srow[c] - mnew);
                float p1 = __expf(srow[c + 1] - mnew);
                sum += p0 + p1;
                __half2 hp = __floats2half2_rn(p0, p1);
                uint32_t hv = *(uint32_t*)&hp;
                asm volatile("st.shared.b32 [%0], %1;" :: "r"(sP + pb + c * 2), "r"(hv));
            }
            sum += __shfl_xor_sync(0xFFFFFFFFu, sum, 1);
            sum += __shfl_xor_sync(0xFFFFFFFFu, sum, 2);
            if (part == 0) {
                const float a = __expf(mold - mnew);
                ral[row] = a;
                rl[row]  = rl[row] * a + sum;
                rm[row]  = mnew;
            }
        }
        __syncthreads();

        #pragma unroll
        for (int mt = 0; mt < 2; mt++) {
            const int r0 = warp_m * 32 + mt * 16 + (lane >> 2);
            const float a0 = ral[r0], a1 = ral[r0 + 8];
            #pragma unroll
            for (int nt = 0; nt < 4; nt++) {
                oacc[mt][nt][0] *= a0; oacc[mt][nt][1] *= a0;
                oacc[mt][nt][2] *= a1; oacc[mt][nt][3] *= a1;
            }
        }
        #pragma unroll
        for (int kk = 0; kk < 4; kk++) {
            uint32_t ap[8], bv[8];
            const int rb = warp_m * 32 + (lane & 15);
            const int kc = kk * 16 + ((lane >> 4) << 3);
            ldm_x4(ap,     sP + rb * P_PITCH + kc * 2);
            ldm_x4(ap + 4, sP + (rb + 16) * P_PITCH + kc * 2);
            const int vr = kk * 16 + (lane & 7) + (((lane >> 3) & 1) << 3);
            const int vc = warp_n * 32 + ((lane >> 4) << 3);
            ldm_x4_t(bv,     sV + vr * A_PITCH + vc * 2);
            ldm_x4_t(bv + 4, sV + vr * A_PITCH + (vc + 16) * 2);
            #pragma unroll
            for (int mt = 0; mt < 2; mt++)
                #pragma unroll
                for (int nt = 0; nt < 4; nt++)
                    mma_fp16(oacc[mt][nt], ap + mt * 4, bv[nt * 2], bv[nt * 2 + 1]);
        }
        __syncthreads();

        if (kt + 2 < 64) {
            load_stage(kt + 2, kt & 1);
            CP_COMMIT();
        }
    }

    // epilogue: O /= l, write single fp16
    #pragma unroll
    for (int mt = 0; mt < 2; mt++) {
        const int rloc0 = warp_m * 32 + mt * 16 + (lane >> 2);
        const float inv0 = 1.f / rl[rloc0];
        const float inv1 = 1.f / rl[rloc0 + 8];
        const size_t gr0 = (size_t)(q0 + rloc0) * DIM;
        const size_t gr1 = (size_t)(q0 + rloc0 + 8) * DIM;
        #pragma unroll
        for (int nt = 0; nt < 4; nt++) {
            const int col = h * HDIM + warp_n * 32 + nt * 8 + ((lane & 3) << 1);
            __half2 p0 = __floats2half2_rn(oacc[mt][nt][0] * inv0, oacc[mt][nt][1] * inv0);
            __half2 p1 = __floats2half2_rn(oacc[mt][nt][2] * inv1, oacc[mt][nt][3] * inv1);
            *(uint32_t*)&A_g[gr0 + col] = *(uint32_t*)&p0;
            *(uint32_t*)&A_g[gr1 + col] = *(uint32_t*)&p1;
        }
    }
}

// ---------------------------------------------------------------------------
extern "C" void kernel_launch(void* const* d_in, const int* in_sizes, int n_in,
                              void* d_out, int out_size) {
    const float* x   = (const float*)d_in[0];
    const float* fc  = (const float*)d_in[1];
    const float* fs  = (const float*)d_in[2];
    const float* Wq  = (const float*)d_in[3];
    const float* bq  = (const float*)d_in[4];
    const float* Wk  = (const float*)d_in[5];
    const float* bk  = (const float*)d_in[6];
    const float* Wv  = (const float*)d_in[7];
    const float* bv  = (const float*)d_in[8];
    const float* Wo  = (const float*)d_in[9];
    const float* bo  = (const float*)d_in[10];
    const float* gq  = (const float*)d_in[11];
    const float* gk  = (const float*)d_in[12];
    float* out = (float*)d_out;

    float *dQ, *dK, *dV;
    cudaGetSymbolAddress((void**)&dQ, g_Q);
    cudaGetSymbolAddress((void**)&dK, g_K);
    cudaGetSymbolAddress((void**)&dV, g_V);
    __half *xf, *af, *qf, *kf, *vf;
    cudaGetSymbolAddress((void**)&xf, g_xf);
    cudaGetSymbolAddress((void**)&af, g_Af);
    cudaGetSymbolAddress((void**)&qf, g_Qf);
    cudaGetSymbolAddress((void**)&kf, g_Kf);
    cudaGetSymbolAddress((void**)&vf, g_Vf);
    __half *wqh, *wql, *wkh, *wkl, *wvh, *wvl, *woh, *wol;
    cudaGetSymbolAddress((void**)&wqh, g_Wqh);
    cudaGetSymbolAddress((void**)&wql, g_Wql);
    cudaGetSymbolAddress((void**)&wkh, g_Wkh);
    cudaGetSymbolAddress((void**)&wkl, g_Wkl);
    cudaGetSymbolAddress((void**)&wvh, g_Wvh);
    cudaGetSymbolAddress((void**)&wvl, g_Wvl);
    cudaGetSymbolAddress((void**)&woh, g_Woh);
    cudaGetSymbolAddress((void**)&wol, g_Wol);

    const int n4x = S_LEN * DIM / 4;
    const int n4w = DIM * DIM / 4;
    tofp16_kernel<<<(n4x + 255) / 256, 256>>>(x, xf, n4x);
    split_fp16_kernel<<<(n4w + 255) / 256, 256>>>(Wq, wqh, wql, n4w);
    split_fp16_kernel<<<(n4w + 255) / 256, 256>>>(Wk, wkh, wkl, n4w);
    split_fp16_kernel<<<(n4w + 255) / 256, 256>>>(Wv, wvh, wvl, n4w);
    split_fp16_kernel<<<(n4w + 255) / 256, 256>>>(Wo, woh, wol, n4w);

    cudaFuncSetAttribute(gemm_tc_kernel, cudaFuncAttributeMaxDynamicSharedMemorySize, G_SMEM);
    dim3 ggrid(DIM / GBN, S_LEN / GBM);
    gemm_tc_kernel<<<ggrid, 256, G_SMEM>>>(xf, wqh, wql, bq, dQ);
    gemm_tc_kernel<<<ggrid, 256, G_SMEM>>>(xf, wkh, wkl, bk, dK);
    gemm_tc_kernel<<<ggrid, 256, G_SMEM>>>(xf, wvh, wvl, bv, dV);

    rmsnorm_rope_kernel<<<S_LEN, 256>>>(dQ, gq, fc, fs, qf);
    rmsnorm_rope_kernel<<<S_LEN, 256>>>(dK, gk, fc, fs, kf);
    tofp16_kernel<<<(n4x + 255) / 256, 256>>>(dV, vf, n4x);

    cudaFuncSetAttribute(attn_mma_kernel, cudaFuncAttributeMaxDynamicSharedMemorySize, ATT_SMEM);
    dim3 agrid(S_LEN / 64, NHEAD);
    attn_mma_kernel<<<agrid, 256, ATT_SMEM>>>(qf, kf, vf, af);

    gemm_tc_kernel<<<ggrid, 256, G_SMEM>>>(af, woh, wol, bo, out);
}

// round 7
// speedup vs baseline: 7.7113x; 1.1724x over previous
#include <cuda_runtime.h>
#include <cuda_bf16.h>
#include <cuda_fp16.h>
#include <math.h>
#include <stdint.h>

#define S_LEN 4096
#define DIM   1536
#define NHEAD 12
#define HDIM  128

// ---------------------------------------------------------------------------
// scratch (device globals: no cudaMalloc allowed)
// ---------------------------------------------------------------------------
__device__ float g_Q[S_LEN * DIM];
__device__ float g_K[S_LEN * DIM];
__device__ float g_V[S_LEN * DIM];

__device__ __align__(128) __half g_xf[S_LEN * DIM];
__device__ __align__(128) __half g_Af[S_LEN * DIM];
__device__ __align__(128) __half g_Qf[S_LEN * DIM];
__device__ __align__(128) __half g_Kf[S_LEN * DIM];
__device__ __align__(128) __half g_Vf[S_LEN * DIM];

__device__ __align__(128) __half g_Wqf[DIM * DIM];
__device__ __align__(128) __half g_Wkf[DIM * DIM];
__device__ __align__(128) __half g_Wvf[DIM * DIM];
__device__ __align__(128) __half g_Woh[DIM * DIM];
__device__ __align__(128) __half g_Wol[DIM * DIM];

__device__ __forceinline__ uint32_t smem_u32(const void* p) {
    uint32_t a;
    asm("{ .reg .u64 t; cvta.to.shared.u64 t, %1; cvt.u32.u64 %0, t; }"
        : "=r"(a) : "l"(p));
    return a;
}

__device__ __forceinline__ void ldm_x4(uint32_t* r, uint32_t addr) {
    asm volatile("ldmatrix.sync.aligned.m8n8.x4.shared.b16 {%0,%1,%2,%3}, [%4];"
        : "=r"(r[0]), "=r"(r[1]), "=r"(r[2]), "=r"(r[3]) : "r"(addr));
}
__device__ __forceinline__ void ldm_x4_t(uint32_t* r, uint32_t addr) {
    asm volatile("ldmatrix.sync.aligned.m8n8.x4.trans.shared.b16 {%0,%1,%2,%3}, [%4];"
        : "=r"(r[0]), "=r"(r[1]), "=r"(r[2]), "=r"(r[3]) : "r"(addr));
}

__device__ __forceinline__ void mma_fp16(float* c, const uint32_t* a,
                                         uint32_t b0, uint32_t b1) {
    asm volatile(
        "mma.sync.aligned.m16n8k16.row.col.f32.f16.f16.f32 "
        "{%0,%1,%2,%3}, {%4,%5,%6,%7}, {%8,%9}, {%0,%1,%2,%3};"
        : "+f"(c[0]), "+f"(c[1]), "+f"(c[2]), "+f"(c[3])
        : "r"(a[0]), "r"(a[1]), "r"(a[2]), "r"(a[3]), "r"(b0), "r"(b1));
}

#define CP_ASYNC16(saddr, gptr) \
    asm volatile("cp.async.cg.shared.global [%0], [%1], 16;" :: "r"(saddr), "l"(gptr))
#define CP_COMMIT()  asm volatile("cp.async.commit_group;" ::: "memory")
#define CP_WAIT1()   asm volatile("cp.async.wait_group 1;" ::: "memory")
#define CP_WAIT0()   asm volatile("cp.async.wait_group 0;" ::: "memory")

// ---------------------------------------------------------------------------
// fp32 -> fp16 single
// ---------------------------------------------------------------------------
__global__ void tofp16_kernel(const float* __restrict__ src,
                              __half* __restrict__ dst, int n4) {
    int i = blockIdx.x * blockDim.x + threadIdx.x;
    if (i >= n4) return;
    float4 v = ((const float4*)src)[i];
    __half2 a = __floats2half2_rn(v.x, v.y);
    __half2 b = __floats2half2_rn(v.z, v.w);
    uint2 o = { *(uint32_t*)&a, *(uint32_t*)&b };
    *(uint2*)(dst + 4 * (size_t)i) = o;
}

// fp32 -> (fp16 hi, fp16 lo)
__global__ void split_fp16_kernel(const float* __restrict__ src,
                                  __half* __restrict__ hi,
                                  __half* __restrict__ lo, int n4) {
    int i = blockIdx.x * blockDim.x + threadIdx.x;
    if (i >= n4) return;
    float4 v = ((const float4*)src)[i];
    float f[4] = { v.x, v.y, v.z, v.w };
    __half h[4], l[4];
    #pragma unroll
    for (int k = 0; k < 4; k++) {
        h[k] = __float2half_rn(f[k]);
        l[k] = __float2half_rn(f[k] - __half2float(h[k]));
    }
    ushort4 h4 = { __half_as_ushort(h[0]), __half_as_ushort(h[1]),
                   __half_as_ushort(h[2]), __half_as_ushort(h[3]) };
    ushort4 l4 = { __half_as_ushort(l[0]), __half_as_ushort(l[1]),
                   __half_as_ushort(l[2]), __half_as_ushort(l[3]) };
    *(ushort4*)(hi + 4 * (size_t)i) = h4;
    *(ushort4*)(lo + 4 * (size_t)i) = l4;
}

// ---------------------------------------------------------------------------
// shared GEMM tiling constants
// ---------------------------------------------------------------------------
#define GBM 128
#define GBN 128
#define GBK 32
#define G_NC (DIM / GBK)
#define G_ROWB 80
#define G_TILEB (128 * G_ROWB)

// ---------------------------------------------------------------------------
// 1-pass fp16 GEMM: C = A @ B^T + bias (A, B single fp16)
// ---------------------------------------------------------------------------
#define G1_STAGEB (2 * G_TILEB)
#define G1_SMEM (2 * G1_STAGEB)   // 40960

__global__ __launch_bounds__(256)
void gemm1_kernel(const __half* __restrict__ A,
                  const __half* __restrict__ B,
                  const float* __restrict__ bias,
                  float* __restrict__ C) {
    extern __shared__ char smem[];
    const uint32_t sbase = smem_u32(smem);
    const int tid  = threadIdx.x;
    const int wid  = tid >> 5;
    const int lane = tid & 31;
    const int bm   = blockIdx.y * GBM;
    const int bn   = blockIdx.x * GBN;
    const int warp_m = wid & 1;
    const int warp_n = wid >> 1;

    const __half* basep[2] = { A + (size_t)bm * DIM, B + (size_t)bn * DIM };
    const int cp_row[2] = { tid >> 2, (tid + 256) >> 2 };
    const int cp_c4     = tid & 3;

    auto copy_chunk = [&](int c, uint32_t stage) {
        #pragma unroll
        for (int t = 0; t < 2; t++) {
            #pragma unroll
            for (int half = 0; half < 2; half++) {
                const int row = cp_row[half];
                const __half* g = basep[t] + (size_t)row * DIM + c * GBK + cp_c4 * 8;
                CP_ASYNC16(stage + t * G_TILEB + row * G_ROWB + cp_c4 * 16, g);
            }
        }
    };

    float acc[4][4][4] = {};
    copy_chunk(0, sbase);
    CP_COMMIT();

    for (int c = 0; c < G_NC; c++) {
        __syncthreads();
        if (c + 1 < G_NC) {
            copy_chunk(c + 1, sbase + ((c + 1) & 1) * G1_STAGEB);
            CP_COMMIT();
            CP_WAIT1();
        } else {
            CP_WAIT0();
        }
        __syncthreads();

        const uint32_t st = sbase + (c & 1) * G1_STAGEB;
        const uint32_t aT = st;
        const uint32_t bT = st + G_TILEB;

        #pragma unroll
        for (int kk = 0; kk < GBK; kk += 16) {
            uint32_t bf[8];
            #pragma unroll
            for (int nt2 = 0; nt2 < 2; nt2++) {
                const int n  = warp_n * 32 + nt2 * 16 + (lane & 7) + ((lane >> 4) << 3);
                const int kc = kk + (((lane >> 3) & 1) << 3);
                ldm_x4(&bf[nt2 * 4], bT + n * G_ROWB + kc * 2);
            }
            uint32_t af[16];
            {
                const int rbase = warp_m * 64 + (lane & 15);
                const int kc    = kk + ((lane >> 4) << 3);
                #pragma unroll
                for (int mt = 0; mt < 4; mt++)
                    ldm_x4(&af[mt * 4], aT + (rbase + mt * 16) * G_ROWB + kc * 2);
            }
            #pragma unroll
            for (int mt = 0; mt < 4; mt++)
                #pragma unroll
                for (int nt = 0; nt < 4; nt++) {
                    const int bi = (nt >> 1) * 4 + (nt & 1) * 2;
                    mma_fp16(acc[mt][nt], &af[mt * 4], bf[bi], bf[bi + 1]);
                }
        }
    }

    #pragma unroll
    for (int mt = 0; mt < 4; mt++) {
        const int row0 = bm + warp_m * 64 + mt * 16 + (lane >> 2);
        #pragma unroll
        for (int nt = 0; nt < 4; nt++) {
            const int col = bn + warp_n * 32 + nt * 8 + ((lane & 3) << 1);
            const float b0 = bias[col], b1 = bias[col + 1];
            float2 v0 = { acc[mt][nt][0] + b0, acc[mt][nt][1] + b1 };
            float2 v1 = { acc[mt][nt][2] + b0, acc[mt][nt][3] + b1 };
            *(float2*)&C[(size_t)row0 * DIM + col]       = v0;
            *(float2*)&C[(size_t)(row0 + 8) * DIM + col] = v1;
        }
    }
}

// ---------------------------------------------------------------------------
// 2-pass fp16 GEMM: C = A @ (Bh+Bl)^T + bias  (for Wo; verified round 6)
// ---------------------------------------------------------------------------
#define G2_STAGEB (3 * G_TILEB)
#define G2_SMEM (2 * G2_STAGEB)   // 61440

__global__ __launch_bounds__(256)
void gemm2_kernel(const __half* __restrict__ A,
                  const __half* __restrict__ Bh,
                  const __half* __restrict__ Bl,
                  const float* __restrict__ bias,
                  float* __restrict__ C) {
    extern __shared__ char smem[];
    const uint32_t sbase = smem_u32(smem);
    const int tid  = threadIdx.x;
    const int wid  = tid >> 5;
    const int lane = tid & 31;
    const int bm   = blockIdx.y * GBM;
    const int bn   = blockIdx.x * GBN;
    const int warp_m = wid & 1;
    const int warp_n = wid >> 1;

    const __half* basep[3] = {
        A + (size_t)bm * DIM, Bh + (size_t)bn * DIM, Bl + (size_t)bn * DIM };
    const int cp_row[2] = { tid >> 2, (tid + 256) >> 2 };
    const int cp_c4     = tid & 3;

    auto copy_chunk = [&](int c, uint32_t stage) {
        #pragma unroll
        for (int t = 0; t < 3; t++) {
            #pragma unroll
            for (int half = 0; half < 2; half++) {
                const int row = cp_row[half];
                const __half* g = basep[t] + (size_t)row * DIM + c * GBK + cp_c4 * 8;
                CP_ASYNC16(stage + t * G_TILEB + row * G_ROWB + cp_c4 * 16, g);
            }
        }
    };

    float acc[4][4][4] = {};
    copy_chunk(0, sbase);
    CP_COMMIT();

    for (int c = 0; c < G_NC; c++) {
        __syncthreads();
        if (c + 1 < G_NC) {
            copy_chunk(c + 1, sbase + ((c + 1) & 1) * G2_STAGEB);
            CP_COMMIT();
            CP_WAIT1();
        } else {
            CP_WAIT0();
        }
        __syncthreads();

        const uint32_t st = sbase + (c & 1) * G2_STAGEB;
        const uint32_t aT = st;
        const uint32_t bH = st + G_TILEB;
        const uint32_t bL = st + 2 * G_TILEB;

        #pragma unroll
        for (int kk = 0; kk < GBK; kk += 16) {
            uint32_t bhf[8], blf[8];
            #pragma unroll
            for (int nt2 = 0; nt2 < 2; nt2++) {
                const int n  = warp_n * 32 + nt2 * 16 + (lane & 7) + ((lane >> 4) << 3);
                const int kc = kk + (((lane >> 3) & 1) << 3);
                ldm_x4(&bhf[nt2 * 4], bH + n * G_ROWB + kc * 2);
                ldm_x4(&blf[nt2 * 4], bL + n * G_ROWB + kc * 2);
            }
            uint32_t af[16];
            {
                const int rbase = warp_m * 64 + (lane & 15);
                const int kc    = kk + ((lane >> 4) << 3);
                #pragma unroll
                for (int mt = 0; mt < 4; mt++)
                    ldm_x4(&af[mt * 4], aT + (rbase + mt * 16) * G_ROWB + kc * 2);
            }
            #pragma unroll
            for (int mt = 0; mt < 4; mt++)
                #pragma unroll
                for (int nt = 0; nt < 4; nt++) {
                    const int bi = (nt >> 1) * 4 + (nt & 1) * 2;
                    mma_fp16(acc[mt][nt], &af[mt * 4], bhf[bi], bhf[bi + 1]);
                }
            #pragma unroll
            for (int mt = 0; mt < 4; mt++)
                #pragma unroll
                for (int nt = 0; nt < 4; nt++) {
                    const int bi = (nt >> 1) * 4 + (nt & 1) * 2;
                    mma_fp16(acc[mt][nt], &af[mt * 4], blf[bi], blf[bi + 1]);
                }
        }
    }

    #pragma unroll
    for (int mt = 0; mt < 4; mt++) {
        const int row0 = bm + warp_m * 64 + mt * 16 + (lane >> 2);
        #pragma unroll
        for (int nt = 0; nt < 4; nt++) {
            const int col = bn + warp_n * 32 + nt * 8 + ((lane & 3) << 1);
            const float b0 = bias[col], b1 = bias[col + 1];
            float2 v0 = { acc[mt][nt][0] + b0, acc[mt][nt][1] + b1 };
            float2 v1 = { acc[mt][nt][2] + b0, acc[mt][nt][3] + b1 };
            *(float2*)&C[(size_t)row0 * DIM + col]       = v0;
            *(float2*)&C[(size_t)(row0 + 8) * DIM + col] = v1;
        }
    }
}

// ---------------------------------------------------------------------------
// Fused RMSNorm + RoPE, writes fp16
// ---------------------------------------------------------------------------
__global__ void rmsnorm_rope_kernel(const float* __restrict__ X,
                                    const float* __restrict__ g,
                                    const float* __restrict__ fc,
                                    const float* __restrict__ fs,
                                    __half* __restrict__ O) {
    const int s = blockIdx.x;
    __shared__ float buf[DIM];
    __shared__ float red[8];
    __shared__ float s_scale;

    const float* row = X + (size_t)s * DIM;

    float ss = 0.f;
    for (int i = threadIdx.x; i < DIM; i += blockDim.x) {
        float v = row[i];
        buf[i] = v;
        ss += v * v;
    }
    #pragma unroll
    for (int o = 16; o > 0; o >>= 1) ss += __shfl_xor_sync(0xFFFFFFFFu, ss, o);
    if ((threadIdx.x & 31) == 0) red[threadIdx.x >> 5] = ss;
    __syncthreads();
    if (threadIdx.x == 0) {
        float t = 0.f;
        #pragma unroll
        for (int w = 0; w < 8; w++) t += red[w];
        s_scale = rsqrtf(t / (float)DIM + 1e-6f);
    }
    __syncthreads();
    const float scale = s_scale;

    const float* fcs = fc + (size_t)s * HDIM;
    const float* fss = fs + (size_t)s * HDIM;

    for (int i = threadIdx.x; i < DIM; i += blockDim.x) {
        int j = i & (HDIM - 1);
        float v = buf[i] * scale * g[i];
        float out;
        if (j < HDIM / 2) {
            float other = buf[i + HDIM / 2] * scale * g[i + HDIM / 2];
            out = v * fcs[j] - other * fss[j];
        } else {
            float other = buf[i - HDIM / 2] * scale * g[i - HDIM / 2];
            out = v * fcs[j] + other * fss[j];
        }
        O[(size_t)s * DIM + i] = __float2half(out);
    }
}

// ---------------------------------------------------------------------------
// Flash attention, fp16 mma. BR=128, BC=64, 512 threads (16 warps).
// warp_m = wid&7 (16 q-rows), warp_n = wid>>3 (32 S-cols / 64 O-cols).
// ---------------------------------------------------------------------------
#define A_PITCH 272
#define Q_TILEB (128 * A_PITCH)     // 34816
#define KV_TILEB (64 * A_PITCH)     // 17408
#define P_PITCH 144
#define OFF_Q    0
#define OFF_KV   Q_TILEB                            // K0,V0,K1,V1
#define OFF_S    (OFF_KV + 4 * KV_TILEB)            // 104448
#define OFF_P    (OFF_S + 128 * 66 * 4)             // 138240
#define OFF_RM   (OFF_P + 128 * P_PITCH)            // 156672
#define OFF_RL   (OFF_RM + 512)
#define OFF_RAL  (OFF_RL + 512)
#define ATT_SMEM (OFF_RAL + 512)                    // 158208

__global__ __launch_bounds__(512)
void attn_mma_kernel(const __half* __restrict__ Q_g,
                     const __half* __restrict__ K_g,
                     const __half* __restrict__ V_g,
                     __half* __restrict__ A_g) {
    extern __shared__ char smem[];
    const uint32_t sb = smem_u32(smem);
    const int tid  = threadIdx.x;
    const int wid  = tid >> 5;
    const int lane = tid & 31;
    const int h    = blockIdx.y;
    const int q0   = blockIdx.x * 128;
    const int warp_m = wid & 7;
    const int warp_n = wid >> 3;
    const float inv_sqrt_d = 0.08838834764831845f;

    const uint32_t sQ = sb + OFF_Q;
    float* S  = (float*)(smem + OFF_S);
    float* rm = (float*)(smem + OFF_RM);
    float* rl = (float*)(smem + OFF_RL);
    float* ral= (float*)(smem + OFF_RAL);
    const uint32_t sP = sb + OFF_P;

    // ---- prologue: Q tile (128 rows) ----
    #pragma unroll
    for (int i = 0; i < 4; i++) {
        int cid = i * 512 + tid;
        int row = cid >> 4, c = cid & 15;
        const __half* gp = Q_g + (size_t)(q0 + row) * DIM + h * HDIM + c * 8;
        CP_ASYNC16(sQ + row * A_PITCH + c * 16, gp);
    }
    const __half* kvsrc[2] = { K_g, V_g };
    auto load_stage = [&](int kt, int s) {
        uint32_t stb = sb + OFF_KV + s * 2 * KV_TILEB;
        #pragma unroll
        for (int i = 0; i < 4; i++) {
            int cid = i * 512 + tid;
            int tile = cid >> 10, row = (cid >> 4) & 63, c = cid & 15;
            const __half* gp = kvsrc[tile] + (size_t)(kt * 64 + row) * DIM + h * HDIM + c * 8;
            CP_ASYNC16(stb + tile * KV_TILEB + row * A_PITCH + c * 16, gp);
        }
    };
    load_stage(0, 0);
    CP_COMMIT();
    load_stage(1, 1);
    CP_COMMIT();

    if (tid < 128) { rm[tid] = -1e30f; rl[tid] = 0.f; }

    float oacc[8][4] = {};

    for (int kt = 0; kt < 64; kt++) {
        if (kt < 63) CP_WAIT1(); else CP_WAIT0();
        __syncthreads();
        const uint32_t st = sb + OFF_KV + (kt & 1) * 2 * KV_TILEB;
        const uint32_t sK = st;
        const uint32_t sV = st + KV_TILEB;

        // ---- S = Q @ K^T ----
        float sacc[4][4] = {};
        #pragma unroll
        for (int kk = 0; kk < 8; kk++) {
            uint32_t aq[4], bk[8];
            const int rb = warp_m * 16 + (lane & 15);
            const int kc = kk * 16 + ((lane >> 4) << 3);
            ldm_x4(aq, sQ + rb * A_PITCH + kc * 2);
            const int nr  = warp_n * 32 + (lane & 7) + ((lane >> 4) << 3);
            const int kc2 = kk * 16 + (((lane >> 3) & 1) << 3);
            ldm_x4(bk,     sK + nr * A_PITCH + kc2 * 2);
            ldm_x4(bk + 4, sK + (nr + 16) * A_PITCH + kc2 * 2);
            #pragma unroll
            for (int nt = 0; nt < 4; nt++) {
                const int bi = (nt >> 1) * 4 + (nt & 1) * 2;
                mma_fp16(sacc[nt], aq, bk[bi], bk[bi + 1]);
            }
        }
        {
            const int row = warp_m * 16 + (lane >> 2);
            #pragma unroll
            for (int nt = 0; nt < 4; nt++) {
                const int col = warp_n * 32 + nt * 8 + ((lane & 3) << 1);
                float2 v0 = { sacc[nt][0] * inv_sqrt_d, sacc[nt][1] * inv_sqrt_d };
                float2 v1 = { sacc[nt][2] * inv_sqrt_d, sacc[nt][3] * inv_sqrt_d };
                *(float2*)&S[row * 66 + col]       = v0;
                *(float2*)&S[(row + 8) * 66 + col] = v1;
            }
        }
        __syncthreads();

        // ---- online softmax: 4 threads/row, 128 rows ----
        {
            const int row  = tid >> 2;
            const int part = tid & 3;
            float* srow = &S[row * 66 + part * 16];
            float mx = -1e30f;
            #pragma unroll
            for (int c = 0; c < 16; c++) mx = fmaxf(mx, srow[c]);
            mx = fmaxf(mx, __shfl_xor_sync(0xFFFFFFFFu, mx, 1));
            mx = fmaxf(mx, __shfl_xor_sync(0xFFFFFFFFu, mx, 2));
            const float mold = rm[row];
            const float mnew = fmaxf(mold, mx);
            float sum = 0.f;
            const uint32_t pb = row * P_PITCH + part * 32;
            #pragma unroll
            for (int c = 0; c < 16; c += 2) {
                float p0 = __expf(srow[c] - mnew);
                float p1 = __expf(srow[c + 1] - mnew);
                sum += p0 + p1;
                __half2 hp = __floats2half2_rn(p0, p1);
                uint32_t hv = *(uint32_t*)&hp;
                asm volatile("st.shared.b32 [%0], %1;" :: "r"(sP + pb + c * 2), "r"(hv));
            }
            sum += __shfl_xor_sync(0xFFFFFFFFu, sum, 1);
            sum += __shfl_xor_sync(0xFFFFFFFFu, sum, 2);
            if (part == 0) {
                const float a = __expf(mold - mnew);
                ral[row] = a;
                rl[row]  = rl[row] * a + sum;
                rm[row]  = mnew;
            }
        }
        __syncthreads();

        // ---- rescale O, then O += P @ V ----
        {
            const int r0 = warp_m * 16 + (lane >> 2);
            const float a0 = ral[r0], a1 = ral[r0 + 8];
            #pragma unroll
            for (int nt = 0; nt < 8; nt++) {
                oacc[nt][0] *= a0; oacc[nt][1] *= a0;
                oacc[nt][2] *= a1; oacc[nt][3] *= a1;
            }
        }
        #pragma unroll
        for (int kk = 0; kk < 4; kk++) {
            uint32_t ap[4], bv[16];
            const int rb = warp_m * 16 + (lane & 15);
            const int kc = kk * 16 + ((lane >> 4) << 3);
            ldm_x4(ap, sP + rb * P_PITCH + kc * 2);
            const int vr = kk * 16 + (lane & 7) + (((lane >> 3) & 1) << 3);
            const int vc = warp_n * 64 + ((lane >> 4) << 3);
            ldm_x4_t(bv,      sV + vr * A_PITCH + vc * 2);
            ldm_x4_t(bv + 4,  sV + vr * A_PITCH + (vc + 16) * 2);
            ldm_x4_t(bv + 8,  sV + vr * A_PITCH + (vc + 32) * 2);
            ldm_x4_t(bv + 12, sV + vr * A_PITCH + (vc + 48) * 2);
            #pragma unroll
            for (int nt = 0; nt < 8; nt++)
                mma_fp16(oacc[nt], ap, bv[nt * 2], bv[nt * 2 + 1]);
        }
        __syncthreads();

        if (kt + 2 < 64) {
            load_stage(kt + 2, kt & 1);
            CP_COMMIT();
        }
    }

    // ---- epilogue: O /= l, write fp16 ----
    {
        const int r = warp_m * 16 + (lane >> 2);
        const float inv0 = 1.f / rl[r];
        const float inv1 = 1.f / rl[r + 8];
        const size_t gr0 = (size_t)(q0 + r) * DIM;
        const size_t gr1 = (size_t)(q0 + r + 8) * DIM;
        #pragma unroll
        for (int nt = 0; nt < 8; nt++) {
            const int col = h * HDIM + warp_n * 64 + nt * 8 + ((lane & 3) << 1);
            __half2 p0 = __floats2half2_rn(oacc[nt][0] * inv0, oacc[nt][1] * inv0);
            __half2 p1 = __floats2half2_rn(oacc[nt][2] * inv1, oacc[nt][3] * inv1);
            *(uint32_t*)&A_g[gr0 + col] = *(uint32_t*)&p0;
            *(uint32_t*)&A_g[gr1 + col] = *(uint32_t*)&p1;
        }
    }
}

// ---------------------------------------------------------------------------
extern "C" void kernel_launch(void* const* d_in, const int* in_sizes, int n_in,
                              void* d_out, int out_size) {
    const float* x   = (const float*)d_in[0];
    const float* fc  = (const float*)d_in[1];
    const float* fs  = (const float*)d_in[2];
    const float* Wq  = (const float*)d_in[3];
    const float* bq  = (const float*)d_in[4];
    const float* Wk  = (const float*)d_in[5];
    const float* bk  = (const float*)d_in[6];
    const float* Wv  = (const float*)d_in[7];
    const float* bv  = (const float*)d_in[8];
    const float* Wo  = (const float*)d_in[9];
    const float* bo  = (const float*)d_in[10];
    const float* gq  = (const float*)d_in[11];
    const float* gk  = (const float*)d_in[12];
    float* out = (float*)d_out;

    float *dQ, *dK, *dV;
    cudaGetSymbolAddress((void**)&dQ, g_Q);
    cudaGetSymbolAddress((void**)&dK, g_K);
    cudaGetSymbolAddress((void**)&dV, g_V);
    __half *xf, *af, *qf, *kf, *vf;
    cudaGetSymbolAddress((void**)&xf, g_xf);
    cudaGetSymbolAddress((void**)&af, g_Af);
    cudaGetSymbolAddress((void**)&qf, g_Qf);
    cudaGetSymbolAddress((void**)&kf, g_Kf);
    cudaGetSymbolAddress((void**)&vf, g_Vf);
    __half *wqf, *wkf, *wvf, *woh, *wol;
    cudaGetSymbolAddress((void**)&wqf, g_Wqf);
    cudaGetSymbolAddress((void**)&wkf, g_Wkf);
    cudaGetSymbolAddress((void**)&wvf, g_Wvf);
    cudaGetSymbolAddress((void**)&woh, g_Woh);
    cudaGetSymbolAddress((void**)&wol, g_Wol);

    const int n4x = S_LEN * DIM / 4;
    const int n4w = DIM * DIM / 4;
    tofp16_kernel<<<(n4x + 255) / 256, 256>>>(x, xf, n4x);
    tofp16_kernel<<<(n4w + 255) / 256, 256>>>(Wq, wqf, n4w);
    tofp16_kernel<<<(n4w + 255) / 256, 256>>>(Wk, wkf, n4w);
    tofp16_kernel<<<(n4w + 255) / 256, 256>>>(Wv, wvf, n4w);
    split_fp16_kernel<<<(n4w + 255) / 256, 256>>>(Wo, woh, wol, n4w);

    cudaFuncSetAttribute(gemm1_kernel, cudaFuncAttributeMaxDynamicSharedMemorySize, G1_SMEM);
    cudaFuncSetAttribute(gemm2_kernel, cudaFuncAttributeMaxDynamicSharedMemorySize, G2_SMEM);
    dim3 ggrid(DIM / GBN, S_LEN / GBM);
    gemm1_kernel<<<ggrid, 256, G1_SMEM>>>(xf, wqf, bq, dQ);
    gemm1_kernel<<<ggrid, 256, G1_SMEM>>>(xf, wkf, bk, dK);
    gemm1_kernel<<<ggrid, 256, G1_SMEM>>>(xf, wvf, bv, dV);

    rmsnorm_rope_kernel<<<S_LEN, 256>>>(dQ, gq, fc, fs, qf);
    rmsnorm_rope_kernel<<<S_LEN, 256>>>(dK, gk, fc, fs, kf);
    tofp16_kernel<<<(n4x + 255) / 256, 256>>>(dV, vf, n4x);

    cudaFuncSetAttribute(attn_mma_kernel, cudaFuncAttributeMaxDynamicSharedMemorySize, ATT_SMEM);
    dim3 agrid(S_LEN / 128, NHEAD);
    attn_mma_kernel<<<agrid, 512, ATT_SMEM>>>(qf, kf, vf, af);

    gemm2_kernel<<<ggrid, 256, G2_SMEM>>>(af, woh, wol, bo, out);
}

// round 8
// speedup vs baseline: 8.5795x; 1.1126x over previous
#include <cuda_runtime.h>
#include <cuda_bf16.h>
#include <cuda_fp16.h>
#include <math.h>
#include <stdint.h>

#define S_LEN 4096
#define DIM   1536
#define NHEAD 12
#define HDIM  128

// ---------------------------------------------------------------------------
// scratch (device globals: no cudaMalloc allowed)
// ---------------------------------------------------------------------------
__device__ float g_Q[S_LEN * DIM];
__device__ float g_K[S_LEN * DIM];

__device__ __align__(128) __half g_xf[S_LEN * DIM];
__device__ __align__(128) __half g_Af[S_LEN * DIM];
__device__ __align__(128) __half g_Qf[S_LEN * DIM];
__device__ __align__(128) __half g_Kf[S_LEN * DIM];
__device__ __align__(128) __half g_Vf[S_LEN * DIM];

__device__ __align__(128) __half g_Wqkv[3 * DIM * DIM];
__device__ __align__(128) __half g_Wof[DIM * DIM];

__device__ __forceinline__ uint32_t smem_u32(const void* p) {
    uint32_t a;
    asm("{ .reg .u64 t; cvta.to.shared.u64 t, %1; cvt.u32.u64 %0, t; }"
        : "=r"(a) : "l"(p));
    return a;
}

__device__ __forceinline__ void ldm_x4(uint32_t* r, uint32_t addr) {
    asm volatile("ldmatrix.sync.aligned.m8n8.x4.shared.b16 {%0,%1,%2,%3}, [%4];"
        : "=r"(r[0]), "=r"(r[1]), "=r"(r[2]), "=r"(r[3]) : "r"(addr));
}
__device__ __forceinline__ void ldm_x4_t(uint32_t* r, uint32_t addr) {
    asm volatile("ldmatrix.sync.aligned.m8n8.x4.trans.shared.b16 {%0,%1,%2,%3}, [%4];"
        : "=r"(r[0]), "=r"(r[1]), "=r"(r[2]), "=r"(r[3]) : "r"(addr));
}

__device__ __forceinline__ void mma_fp16(float* c, const uint32_t* a,
                                         uint32_t b0, uint32_t b1) {
    asm volatile(
        "mma.sync.aligned.m16n8k16.row.col.f32.f16.f16.f32 "
        "{%0,%1,%2,%3}, {%4,%5,%6,%7}, {%8,%9}, {%0,%1,%2,%3};"
        : "+f"(c[0]), "+f"(c[1]), "+f"(c[2]), "+f"(c[3])
        : "r"(a[0]), "r"(a[1]), "r"(a[2]), "r"(a[3]), "r"(b0), "r"(b1));
}

#define CP_ASYNC16(saddr, gptr) \
    asm volatile("cp.async.cg.shared.global [%0], [%1], 16;" :: "r"(saddr), "l"(gptr))
#define CP_COMMIT()  asm volatile("cp.async.commit_group;" ::: "memory")
#define CP_WAIT1()   asm volatile("cp.async.wait_group 1;" ::: "memory")
#define CP_WAIT0()   asm volatile("cp.async.wait_group 0;" ::: "memory")

// ---------------------------------------------------------------------------
// fp32 -> fp16 single
// ---------------------------------------------------------------------------
__global__ void tofp16_kernel(const float* __restrict__ src,
                              __half* __restrict__ dst, int n4) {
    int i = blockIdx.x * blockDim.x + threadIdx.x;
    if (i >= n4) return;
    float4 v = ((const float4*)src)[i];
    __half2 a = __floats2half2_rn(v.x, v.y);
    __half2 b = __floats2half2_rn(v.z, v.w);
    uint2 o = { *(uint32_t*)&a, *(uint32_t*)&b };
    *(uint2*)(dst + 4 * (size_t)i) = o;
}

// ---------------------------------------------------------------------------
// shared GEMM tiling constants
// ---------------------------------------------------------------------------
#define GBM 128
#define GBN 128
#define GBK 32
#define G_NC (DIM / GBK)
#define G_ROWB 80
#define G_TILEB (128 * G_ROWB)
#define G1_STAGEB (2 * G_TILEB)
#define G1_SMEM (2 * G1_STAGEB)   // 40960

// ---------------------------------------------------------------------------
// Fused QKV GEMM: grid.x = 36 (12 per matrix), one launch.
// Q,K written fp32 (for rmsnorm); V written fp16 directly.
// ---------------------------------------------------------------------------
__global__ __launch_bounds__(256)
void gemm_qkv_kernel(const __half* __restrict__ A,
                     const __half* __restrict__ Wqkv,
                     const float* __restrict__ bq,
                     const float* __restrict__ bk,
                     const float* __restrict__ bv,
                     float* __restrict__ Cq,
                     float* __restrict__ Ck,
                     __half* __restrict__ Cv) {
    extern __shared__ char smem[];
    const uint32_t sbase = smem_u32(smem);
    const int tid  = threadIdx.x;
    const int wid  = tid >> 5;
    const int lane = tid & 31;
    const int bm   = blockIdx.y * GBM;
    const int mat  = blockIdx.x / 12;            // 0=Q, 1=K, 2=V
    const int bn   = (blockIdx.x % 12) * GBN;    // local output col base
    const int warp_m = wid & 1;
    const int warp_n = wid >> 1;

    const float* biasv[3] = { bq, bk, bv };
    const float* bias = biasv[mat];

    const __half* basep[2] = {
        A + (size_t)bm * DIM,
        Wqkv + (size_t)blockIdx.x * GBN * DIM };
    const int cp_row[2] = { tid >> 2, (tid + 256) >> 2 };
    const int cp_c4     = tid & 3;

    auto copy_chunk = [&](int c, uint32_t stage) {
        #pragma unroll
        for (int t = 0; t < 2; t++) {
            #pragma unroll
            for (int half = 0; half < 2; half++) {
                const int row = cp_row[half];
                const __half* g = basep[t] + (size_t)row * DIM + c * GBK + cp_c4 * 8;
                CP_ASYNC16(stage + t * G_TILEB + row * G_ROWB + cp_c4 * 16, g);
            }
        }
    };

    float acc[4][4][4] = {};
    copy_chunk(0, sbase);
    CP_COMMIT();

    for (int c = 0; c < G_NC; c++) {
        __syncthreads();
        if (c + 1 < G_NC) {
            copy_chunk(c + 1, sbase + ((c + 1) & 1) * G1_STAGEB);
            CP_COMMIT();
            CP_WAIT1();
        } else {
            CP_WAIT0();
        }
        __syncthreads();

        const uint32_t st = sbase + (c & 1) * G1_STAGEB;
        const uint32_t aT = st;
        const uint32_t bT = st + G_TILEB;

        #pragma unroll
        for (int kk = 0; kk < GBK; kk += 16) {
            uint32_t bf[8];
            #pragma unroll
            for (int nt2 = 0; nt2 < 2; nt2++) {
                const int n  = warp_n * 32 + nt2 * 16 + (lane & 7) + ((lane >> 4) << 3);
                const int kc = kk + (((lane >> 3) & 1) << 3);
                ldm_x4(&bf[nt2 * 4], bT + n * G_ROWB + kc * 2);
            }
            uint32_t af[16];
            {
                const int rbase = warp_m * 64 + (lane & 15);
                const int kc    = kk + ((lane >> 4) << 3);
                #pragma unroll
                for (int mt = 0; mt < 4; mt++)
                    ldm_x4(&af[mt * 4], aT + (rbase + mt * 16) * G_ROWB + kc * 2);
            }
            #pragma unroll
            for (int mt = 0; mt < 4; mt++)
                #pragma unroll
                for (int nt = 0; nt < 4; nt++) {
                    const int bi = (nt >> 1) * 4 + (nt & 1) * 2;
                    mma_fp16(acc[mt][nt], &af[mt * 4], bf[bi], bf[bi + 1]);
                }
        }
    }

    if (mat < 2) {
        float* C = mat ? Ck : Cq;
        #pragma unroll
        for (int mt = 0; mt < 4; mt++) {
            const int row0 = bm + warp_m * 64 + mt * 16 + (lane >> 2);
            #pragma unroll
            for (int nt = 0; nt < 4; nt++) {
                const int col = bn + warp_n * 32 + nt * 8 + ((lane & 3) << 1);
                const float b0 = bias[col], b1 = bias[col + 1];
                float2 v0 = { acc[mt][nt][0] + b0, acc[mt][nt][1] + b1 };
                float2 v1 = { acc[mt][nt][2] + b0, acc[mt][nt][3] + b1 };
                *(float2*)&C[(size_t)row0 * DIM + col]       = v0;
                *(float2*)&C[(size_t)(row0 + 8) * DIM + col] = v1;
            }
        }
    } else {
        #pragma unroll
        for (int mt = 0; mt < 4; mt++) {
            const int row0 = bm + warp_m * 64 + mt * 16 + (lane >> 2);
            #pragma unroll
            for (int nt = 0; nt < 4; nt++) {
                const int col = bn + warp_n * 32 + nt * 8 + ((lane & 3) << 1);
                const float b0 = bias[col], b1 = bias[col + 1];
                __half2 v0 = __floats2half2_rn(acc[mt][nt][0] + b0, acc[mt][nt][1] + b1);
                __half2 v1 = __floats2half2_rn(acc[mt][nt][2] + b0, acc[mt][nt][3] + b1);
                *(uint32_t*)&Cv[(size_t)row0 * DIM + col]       = *(uint32_t*)&v0;
                *(uint32_t*)&Cv[(size_t)(row0 + 8) * DIM + col] = *(uint32_t*)&v1;
            }
        }
    }
}

// ---------------------------------------------------------------------------
// 1-pass fp16 GEMM: C = A @ B^T + bias  (Wo projection)
// ---------------------------------------------------------------------------
__global__ __launch_bounds__(256)
void gemm1_kernel(const __half* __restrict__ A,
                  const __half* __restrict__ B,
                  const float* __restrict__ bias,
                  float* __restrict__ C) {
    extern __shared__ char smem[];
    const uint32_t sbase = smem_u32(smem);
    const int tid  = threadIdx.x;
    const int wid  = tid >> 5;
    const int lane = tid & 31;
    const int bm   = blockIdx.y * GBM;
    const int bn   = blockIdx.x * GBN;
    const int warp_m = wid & 1;
    const int warp_n = wid >> 1;

    const __half* basep[2] = { A + (size_t)bm * DIM, B + (size_t)bn * DIM };
    const int cp_row[2] = { tid >> 2, (tid + 256) >> 2 };
    const int cp_c4     = tid & 3;

    auto copy_chunk = [&](int c, uint32_t stage) {
        #pragma unroll
        for (int t = 0; t < 2; t++) {
            #pragma unroll
            for (int half = 0; half < 2; half++) {
                const int row = cp_row[half];
                const __half* g = basep[t] + (size_t)row * DIM + c * GBK + cp_c4 * 8;
                CP_ASYNC16(stage + t * G_TILEB + row * G_ROWB + cp_c4 * 16, g);
            }
        }
    };

    float acc[4][4][4] = {};
    copy_chunk(0, sbase);
    CP_COMMIT();

    for (int c = 0; c < G_NC; c++) {
        __syncthreads();
        if (c + 1 < G_NC) {
            copy_chunk(c + 1, sbase + ((c + 1) & 1) * G1_STAGEB);
            CP_COMMIT();
            CP_WAIT1();
        } else {
            CP_WAIT0();
        }
        __syncthreads();

        const uint32_t st = sbase + (c & 1) * G1_STAGEB;
        const uint32_t aT = st;
        const uint32_t bT = st + G_TILEB;

        #pragma unroll
        for (int kk = 0; kk < GBK; kk += 16) {
            uint32_t bf[8];
            #pragma unroll
            for (int nt2 = 0; nt2 < 2; nt2++) {
                const int n  = warp_n * 32 + nt2 * 16 + (lane & 7) + ((lane >> 4) << 3);
                const int kc = kk + (((lane >> 3) & 1) << 3);
                ldm_x4(&bf[nt2 * 4], bT + n * G_ROWB + kc * 2);
            }
            uint32_t af[16];
            {
                const int rbase = warp_m * 64 + (lane & 15);
                const int kc    = kk + ((lane >> 4) << 3);
                #pragma unroll
                for (int mt = 0; mt < 4; mt++)
                    ldm_x4(&af[mt * 4], aT + (rbase + mt * 16) * G_ROWB + kc * 2);
            }
            #pragma unroll
            for (int mt = 0; mt < 4; mt++)
                #pragma unroll
                for (int nt = 0; nt < 4; nt++) {
                    const int bi = (nt >> 1) * 4 + (nt & 1) * 2;
                    mma_fp16(acc[mt][nt], &af[mt * 4], bf[bi], bf[bi + 1]);
                }
        }
    }

    #pragma unroll
    for (int mt = 0; mt < 4; mt++) {
        const int row0 = bm + warp_m * 64 + mt * 16 + (lane >> 2);
        #pragma unroll
        for (int nt = 0; nt < 4; nt++) {
            const int col = bn + warp_n * 32 + nt * 8 + ((lane & 3) << 1);
            const float b0 = bias[col], b1 = bias[col + 1];
            float2 v0 = { acc[mt][nt][0] + b0, acc[mt][nt][1] + b1 };
            float2 v1 = { acc[mt][nt][2] + b0, acc[mt][nt][3] + b1 };
            *(float2*)&C[(size_t)row0 * DIM + col]       = v0;
            *(float2*)&C[(size_t)(row0 + 8) * DIM + col] = v1;
        }
    }
}

// ---------------------------------------------------------------------------
// Fused RMSNorm + RoPE, writes fp16
// ---------------------------------------------------------------------------
__global__ void rmsnorm_rope_kernel(const float* __restrict__ X,
                                    const float* __restrict__ g,
                                    const float* __restrict__ fc,
                                    const float* __restrict__ fs,
                                    __half* __restrict__ O) {
    const int s = blockIdx.x;
    __shared__ float buf[DIM];
    __shared__ float red[8];
    __shared__ float s_scale;

    const float* row = X + (size_t)s * DIM;

    float ss = 0.f;
    for (int i = threadIdx.x; i < DIM; i += blockDim.x) {
        float v = row[i];
        buf[i] = v;
        ss += v * v;
    }
    #pragma unroll
    for (int o = 16; o > 0; o >>= 1) ss += __shfl_xor_sync(0xFFFFFFFFu, ss, o);
    if ((threadIdx.x & 31) == 0) red[threadIdx.x >> 5] = ss;
    __syncthreads();
    if (threadIdx.x == 0) {
        float t = 0.f;
        #pragma unroll
        for (int w = 0; w < 8; w++) t += red[w];
        s_scale = rsqrtf(t / (float)DIM + 1e-6f);
    }
    __syncthreads();
    const float scale = s_scale;

    const float* fcs = fc + (size_t)s * HDIM;
    const float* fss = fs + (size_t)s * HDIM;

    for (int i = threadIdx.x; i < DIM; i += blockDim.x) {
        int j = i & (HDIM - 1);
        float v = buf[i] * scale * g[i];
        float out;
        if (j < HDIM / 2) {
            float other = buf[i + HDIM / 2] * scale * g[i + HDIM / 2];
            out = v * fcs[j] - other * fss[j];
        } else {
            float other = buf[i - HDIM / 2] * scale * g[i - HDIM / 2];
            out = v * fcs[j] + other * fss[j];
        }
        O[(size_t)s * DIM + i] = __float2half(out);
    }
}

// ---------------------------------------------------------------------------
// Flash attention, fp16 mma. BR=128, BC=64, 512 threads (verified round 7)
// ---------------------------------------------------------------------------
#define A_PITCH 272
#define Q_TILEB (128 * A_PITCH)
#define KV_TILEB (64 * A_PITCH)
#define P_PITCH 144
#define OFF_Q    0
#define OFF_KV   Q_TILEB
#define OFF_S    (OFF_KV + 4 * KV_TILEB)
#define OFF_P    (OFF_S + 128 * 66 * 4)
#define OFF_RM   (OFF_P + 128 * P_PITCH)
#define OFF_RL   (OFF_RM + 512)
#define OFF_RAL  (OFF_RL + 512)
#define ATT_SMEM (OFF_RAL + 512)

__global__ __launch_bounds__(512)
void attn_mma_kernel(const __half* __restrict__ Q_g,
                     const __half* __restrict__ K_g,
                     const __half* __restrict__ V_g,
                     __half* __restrict__ A_g) {
    extern __shared__ char smem[];
    const uint32_t sb = smem_u32(smem);
    const int tid  = threadIdx.x;
    const int wid  = tid >> 5;
    const int lane = tid & 31;
    const int h    = blockIdx.y;
    const int q0   = blockIdx.x * 128;
    const int warp_m = wid & 7;
    const int warp_n = wid >> 3;
    const float inv_sqrt_d = 0.08838834764831845f;

    const uint32_t sQ = sb + OFF_Q;
    float* S  = (float*)(smem + OFF_S);
    float* rm = (float*)(smem + OFF_RM);
    float* rl = (float*)(smem + OFF_RL);
    float* ral= (float*)(smem + OFF_RAL);
    const uint32_t sP = sb + OFF_P;

    #pragma unroll
    for (int i = 0; i < 4; i++) {
        int cid = i * 512 + tid;
        int row = cid >> 4, c = cid & 15;
        const __half* gp = Q_g + (size_t)(q0 + row) * DIM + h * HDIM + c * 8;
        CP_ASYNC16(sQ + row * A_PITCH + c * 16, gp);
    }
    const __half* kvsrc[2] = { K_g, V_g };
    auto load_stage = [&](int kt, int s) {
        uint32_t stb = sb + OFF_KV + s * 2 * KV_TILEB;
        #pragma unroll
        for (int i = 0; i < 4; i++) {
            int cid = i * 512 + tid;
            int tile = cid >> 10, row = (cid >> 4) & 63, c = cid & 15;
            const __half* gp = kvsrc[tile] + (size_t)(kt * 64 + row) * DIM + h * HDIM + c * 8;
            CP_ASYNC16(stb + tile * KV_TILEB + row * A_PITCH + c * 16, gp);
        }
    };
    load_stage(0, 0);
    CP_COMMIT();
    load_stage(1, 1);
    CP_COMMIT();

    if (tid < 128) { rm[tid] = -1e30f; rl[tid] = 0.f; }

    float oacc[8][4] = {};

    for (int kt = 0; kt < 64; kt++) {
        if (kt < 63) CP_WAIT1(); else CP_WAIT0();
        __syncthreads();
        const uint32_t st = sb + OFF_KV + (kt & 1) * 2 * KV_TILEB;
        const uint32_t sK = st;
        const uint32_t sV = st + KV_TILEB;

        float sacc[4][4] = {};
        #pragma unroll
        for (int kk = 0; kk < 8; kk++) {
            uint32_t aq[4], bk[8];
            const int rb = warp_m * 16 + (lane & 15);
            const int kc = kk * 16 + ((lane >> 4) << 3);
            ldm_x4(aq, sQ + rb * A_PITCH + kc * 2);
            const int nr  = warp_n * 32 + (lane & 7) + ((lane >> 4) << 3);
            const int kc2 = kk * 16 + (((lane >> 3) & 1) << 3);
            ldm_x4(bk,     sK + nr * A_PITCH + kc2 * 2);
            ldm_x4(bk + 4, sK + (nr + 16) * A_PITCH + kc2 * 2);
            #pragma unroll
            for (int nt = 0; nt < 4; nt++) {
                const int bi = (nt >> 1) * 4 + (nt & 1) * 2;
                mma_fp16(sacc[nt], aq, bk[bi], bk[bi + 1]);
            }
        }
        {
            const int row = warp_m * 16 + (lane >> 2);
            #pragma unroll
            for (int nt = 0; nt < 4; nt++) {
                const int col = warp_n * 32 + nt * 8 + ((lane & 3) << 1);
                float2 v0 = { sacc[nt][0] * inv_sqrt_d, sacc[nt][1] * inv_sqrt_d };
                float2 v1 = { sacc[nt][2] * inv_sqrt_d, sacc[nt][3] * inv_sqrt_d };
                *(float2*)&S[row * 66 + col]       = v0;
                *(float2*)&S[(row + 8) * 66 + col] = v1;
            }
        }
        __syncthreads();

        {
            const int row  = tid >> 2;
            const int part = tid & 3;
            float* srow = &S[row * 66 + part * 16];
            float mx = -1e30f;
            #pragma unroll
            for (int c = 0; c < 16; c++) mx = fmaxf(mx, srow[c]);
            mx = fmaxf(mx, __shfl_xor_sync(0xFFFFFFFFu, mx, 1));
            mx = fmaxf(mx, __shfl_xor_sync(0xFFFFFFFFu, mx, 2));
            const float mold = rm[row];
            const float mnew = fmaxf(mold, mx);
            float sum = 0.f;
            const uint32_t pb = row * P_PITCH + part * 32;
            #pragma unroll
            for (int c = 0; c < 16; c += 2) {
                float p0 = __expf(srow[c] - mnew);
                float p1 = __expf(srow[c + 1] - mnew);
                sum += p0 + p1;
                __half2 hp = __floats2half2_rn(p0, p1);
                uint32_t hv = *(uint32_t*)&hp;
                asm volatile("st.shared.b32 [%0], %1;" :: "r"(sP + pb + c * 2), "r"(hv));
            }
            sum += __shfl_xor_sync(0xFFFFFFFFu, sum, 1);
            sum += __shfl_xor_sync(0xFFFFFFFFu, sum, 2);
            if (part == 0) {
                const float a = __expf(mold - mnew);
                ral[row] = a;
                rl[row]  = rl[row] * a + sum;
                rm[row]  = mnew;
            }
        }
        __syncthreads();

        {
            const int r0 = warp_m * 16 + (lane >> 2);
            const float a0 = ral[r0], a1 = ral[r0 + 8];
            #pragma unroll
            for (int nt = 0; nt < 8; nt++) {
                oacc[nt][0] *= a0; oacc[nt][1] *= a0;
                oacc[nt][2] *= a1; oacc[nt][3] *= a1;
            }
        }
        #pragma unroll
        for (int kk = 0; kk < 4; kk++) {
            uint32_t ap[4], bv[16];
            const int rb = warp_m * 16 + (lane & 15);
            const int kc = kk * 16 + ((lane >> 4) << 3);
            ldm_x4(ap, sP + rb * P_PITCH + kc * 2);
            const int vr = kk * 16 + (lane & 7) + (((lane >> 3) & 1) << 3);
            const int vc = warp_n * 64 + ((lane >> 4) << 3);
            ldm_x4_t(bv,      sV + vr * A_PITCH + vc * 2);
            ldm_x4_t(bv + 4,  sV + vr * A_PITCH + (vc + 16) * 2);
            ldm_x4_t(bv + 8,  sV + vr * A_PITCH + (vc + 32) * 2);
            ldm_x4_t(bv + 12, sV + vr * A_PITCH + (vc + 48) * 2);
            #pragma unroll
            for (int nt = 0; nt < 8; nt++)
                mma_fp16(oacc[nt], ap, bv[nt * 2], bv[nt * 2 + 1]);
        }
        __syncthreads();

        if (kt + 2 < 64) {
            load_stage(kt + 2, kt & 1);
            CP_COMMIT();
        }
    }

    {
        const int r = warp_m * 16 + (lane >> 2);
        const float inv0 = 1.f / rl[r];
        const float inv1 = 1.f / rl[r + 8];
        const size_t gr0 = (size_t)(q0 + r) * DIM;
        const size_t gr1 = (size_t)(q0 + r + 8) * DIM;
        #pragma unroll
        for (int nt = 0; nt < 8; nt++) {
            const int col = h * HDIM + warp_n * 64 + nt * 8 + ((lane & 3) << 1);
            __half2 p0 = __floats2half2_rn(oacc[nt][0] * inv0, oacc[nt][1] * inv0);
            __half2 p1 = __floats2half2_rn(oacc[nt][2] * inv1, oacc[nt][3] * inv1);
            *(uint32_t*)&A_g[gr0 + col] = *(uint32_t*)&p0;
            *(uint32_t*)&A_g[gr1 + col] = *(uint32_t*)&p1;
        }
    }
}

// ---------------------------------------------------------------------------
extern "C" void kernel_launch(void* const* d_in, const int* in_sizes, int n_in,
                              void* d_out, int out_size) {
    const float* x   = (const float*)d_in[0];
    const float* fc  = (const float*)d_in[1];
    const float* fs  = (const float*)d_in[2];
    const float* Wq  = (const float*)d_in[3];
    const float* bq  = (const float*)d_in[4];
    const float* Wk  = (const float*)d_in[5];
    const float* bk  = (const float*)d_in[6];
    const float* Wv  = (const float*)d_in[7];
    const float* bv  = (const float*)d_in[8];
    const float* Wo  = (const float*)d_in[9];
    const float* bo  = (const float*)d_in[10];
    const float* gq  = (const float*)d_in[11];
    const float* gk  = (const float*)d_in[12];
    float* out = (float*)d_out;

    float *dQ, *dK;
    cudaGetSymbolAddress((void**)&dQ, g_Q);
    cudaGetSymbolAddress((void**)&dK, g_K);
    __half *xf, *af, *qf, *kf, *vf, *wqkv, *wof;
    cudaGetSymbolAddress((void**)&xf, g_xf);
    cudaGetSymbolAddress((void**)&af, g_Af);
    cudaGetSymbolAddress((void**)&qf, g_Qf);
    cudaGetSymbolAddress((void**)&kf, g_Kf);
    cudaGetSymbolAddress((void**)&vf, g_Vf);
    cudaGetSymbolAddress((void**)&wqkv, g_Wqkv);
    cudaGetSymbolAddress((void**)&wof, g_Wof);

    const int n4x = S_LEN * DIM / 4;
    const int n4w = DIM * DIM / 4;
    tofp16_kernel<<<(n4x + 255) / 256, 256>>>(x, xf, n4x);
    tofp16_kernel<<<(n4w + 255) / 256, 256>>>(Wq, wqkv, n4w);
    tofp16_kernel<<<(n4w + 255) / 256, 256>>>(Wk, wqkv + (size_t)DIM * DIM, n4w);
    tofp16_kernel<<<(n4w + 255) / 256, 256>>>(Wv, wqkv + 2 * (size_t)DIM * DIM, n4w);
    tofp16_kernel<<<(n4w + 255) / 256, 256>>>(Wo, wof, n4w);

    cudaFuncSetAttribute(gemm_qkv_kernel, cudaFuncAttributeMaxDynamicSharedMemorySize, G1_SMEM);
    cudaFuncSetAttribute(gemm1_kernel, cudaFuncAttributeMaxDynamicSharedMemorySize, G1_SMEM);

    dim3 gqkv(3 * DIM / GBN, S_LEN / GBM);   // (36, 32)
    gemm_qkv_kernel<<<gqkv, 256, G1_SMEM>>>(xf, wqkv, bq, bk, bv, dQ, dK, vf);

    rmsnorm_rope_kernel<<<S_LEN, 256>>>(dQ, gq, fc, fs, qf);
    rmsnorm_rope_kernel<<<S_LEN, 256>>>(dK, gk, fc, fs, kf);

    cudaFuncSetAttribute(attn_mma_kernel, cudaFuncAttributeMaxDynamicSharedMemorySize, ATT_SMEM);
    dim3 agrid(S_LEN / 128, NHEAD);
    attn_mma_kernel<<<agrid, 512, ATT_SMEM>>>(qf, kf, vf, af);

    dim3 ggrid(DIM / GBN, S_LEN / GBM);
    gemm1_kernel<<<ggrid, 256, G1_SMEM>>>(af, wof, bo, out);
}

// round 9
// speedup vs baseline: 12.8380x; 1.4964x over previous
#include <cuda_runtime.h>
#include <cuda_bf16.h>
#include <cuda_fp16.h>
#include <math.h>
#include <stdint.h>

#define S_LEN 4096
#define DIM   1536
#define NHEAD 12
#define HDIM  128

// ---------------------------------------------------------------------------
// scratch (device globals: no cudaMalloc allowed)
// ---------------------------------------------------------------------------
__device__ float g_Q[S_LEN * DIM];
__device__ float g_K[S_LEN * DIM];

__device__ __align__(128) __half g_xf[S_LEN * DIM];
__device__ __align__(128) __half g_Af[S_LEN * DIM];
__device__ __align__(128) __half g_Qf[S_LEN * DIM];
__device__ __align__(128) __half g_Kf[S_LEN * DIM];
__device__ __align__(128) __half g_Vf[S_LEN * DIM];

__device__ __align__(128) __half g_Wqkv[3 * DIM * DIM];
__device__ __align__(128) __half g_Wof[DIM * DIM];

__device__ __forceinline__ uint32_t smem_u32(const void* p) {
    uint32_t a;
    asm("{ .reg .u64 t; cvta.to.shared.u64 t, %1; cvt.u32.u64 %0, t; }"
        : "=r"(a) : "l"(p));
    return a;
}

__device__ __forceinline__ void ldm_x4(uint32_t* r, uint32_t addr) {
    asm volatile("ldmatrix.sync.aligned.m8n8.x4.shared.b16 {%0,%1,%2,%3}, [%4];"
        : "=r"(r[0]), "=r"(r[1]), "=r"(r[2]), "=r"(r[3]) : "r"(addr));
}
__device__ __forceinline__ void ldm_x4_t(uint32_t* r, uint32_t addr) {
    asm volatile("ldmatrix.sync.aligned.m8n8.x4.trans.shared.b16 {%0,%1,%2,%3}, [%4];"
        : "=r"(r[0]), "=r"(r[1]), "=r"(r[2]), "=r"(r[3]) : "r"(addr));
}

__device__ __forceinline__ void mma_fp16(float* c, const uint32_t* a,
                                         uint32_t b0, uint32_t b1) {
    asm volatile(
        "mma.sync.aligned.m16n8k16.row.col.f32.f16.f16.f32 "
        "{%0,%1,%2,%3}, {%4,%5,%6,%7}, {%8,%9}, {%0,%1,%2,%3};"
        : "+f"(c[0]), "+f"(c[1]), "+f"(c[2]), "+f"(c[3])
        : "r"(a[0]), "r"(a[1]), "r"(a[2]), "r"(a[3]), "r"(b0), "r"(b1));
}

__device__ __forceinline__ float ex2f(float x) {
    float y;
    asm("ex2.approx.ftz.f32 %0, %1;" : "=f"(y) : "f"(x));
    return y;
}

#define CP_ASYNC16(saddr, gptr) \
    asm volatile("cp.async.cg.shared.global [%0], [%1], 16;" :: "r"(saddr), "l"(gptr))
#define CP_COMMIT()  asm volatile("cp.async.commit_group;" ::: "memory")
#define CP_WAIT1()   asm volatile("cp.async.wait_group 1;" ::: "memory")
#define CP_WAIT0()   asm volatile("cp.async.wait_group 0;" ::: "memory")

// ---------------------------------------------------------------------------
// merged fp32 -> fp16 conversion of x + 4 weights (one launch)
// ---------------------------------------------------------------------------
#define X4 (S_LEN * DIM / 4)   // 1572864
#define W4 (DIM * DIM / 4)     //  589824

__global__ void convert_all_kernel(const float* __restrict__ x,
                                   const float* __restrict__ Wq,
                                   const float* __restrict__ Wk,
                                   const float* __restrict__ Wv,
                                   const float* __restrict__ Wo,
                                   __half* __restrict__ xf,
                                   __half* __restrict__ wqkv,
                                   __half* __restrict__ wof) {
    int i = blockIdx.x * blockDim.x + threadIdx.x;
    const float* src;
    __half* dst;
    int off;
    if (i < X4)               { src = x;  dst = xf;   off = i; }
    else if (i < X4 + W4)     { src = Wq; dst = wqkv; off = i - X4; }
    else if (i < X4 + 2 * W4) { src = Wk; dst = wqkv + (size_t)DIM * DIM;     off = i - X4 - W4; }
    else if (i < X4 + 3 * W4) { src = Wv; dst = wqkv + 2 * (size_t)DIM * DIM; off = i - X4 - 2 * W4; }
    else if (i < X4 + 4 * W4) { src = Wo; dst = wof;  off = i - X4 - 3 * W4; }
    else return;
    float4 v = ((const float4*)src)[off];
    __half2 a = __floats2half2_rn(v.x, v.y);
    __half2 b = __floats2half2_rn(v.z, v.w);
    uint2 o = { *(uint32_t*)&a, *(uint32_t*)&b };
    *(uint2*)(dst + 4 * (size_t)off) = o;
}

// ---------------------------------------------------------------------------
// shared GEMM tiling constants
// ---------------------------------------------------------------------------
#define GBM 128
#define GBN 128
#define GBK 32
#define G_NC (DIM / GBK)
#define G_ROWB 80
#define G_TILEB (128 * G_ROWB)
#define G1_STAGEB (2 * G_TILEB)
#define G1_SMEM (2 * G1_STAGEB)   // 40960

// ---------------------------------------------------------------------------
// Fused QKV GEMM (verified round 8)
// ---------------------------------------------------------------------------
__global__ __launch_bounds__(256)
void gemm_qkv_kernel(const __half* __restrict__ A,
                     const __half* __restrict__ Wqkv,
                     const float* __restrict__ bq,
                     const float* __restrict__ bk,
                     const float* __restrict__ bv,
                     float* __restrict__ Cq,
                     float* __restrict__ Ck,
                     __half* __restrict__ Cv) {
    extern __shared__ char smem[];
    const uint32_t sbase = smem_u32(smem);
    const int tid  = threadIdx.x;
    const int wid  = tid >> 5;
    const int lane = tid & 31;
    const int bm   = blockIdx.y * GBM;
    const int mat  = blockIdx.x / 12;
    const int bn   = (blockIdx.x % 12) * GBN;
    const int warp_m = wid & 1;
    const int warp_n = wid >> 1;

    const float* biasv[3] = { bq, bk, bv };
    const float* bias = biasv[mat];

    const __half* basep[2] = {
        A + (size_t)bm * DIM,
        Wqkv + (size_t)blockIdx.x * GBN * DIM };
    const int cp_row[2] = { tid >> 2, (tid + 256) >> 2 };
    const int cp_c4     = tid & 3;

    auto copy_chunk = [&](int c, uint32_t stage) {
        #pragma unroll
        for (int t = 0; t < 2; t++) {
            #pragma unroll
            for (int half = 0; half < 2; half++) {
                const int row = cp_row[half];
                const __half* g = basep[t] + (size_t)row * DIM + c * GBK + cp_c4 * 8;
                CP_ASYNC16(stage + t * G_TILEB + row * G_ROWB + cp_c4 * 16, g);
            }
        }
    };

    float acc[4][4][4] = {};
    copy_chunk(0, sbase);
    CP_COMMIT();

    for (int c = 0; c < G_NC; c++) {
        __syncthreads();
        if (c + 1 < G_NC) {
            copy_chunk(c + 1, sbase + ((c + 1) & 1) * G1_STAGEB);
            CP_COMMIT();
            CP_WAIT1();
        } else {
            CP_WAIT0();
        }
        __syncthreads();

        const uint32_t st = sbase + (c & 1) * G1_STAGEB;
        const uint32_t aT = st;
        const uint32_t bT = st + G_TILEB;

        #pragma unroll
        for (int kk = 0; kk < GBK; kk += 16) {
            uint32_t bf[8];
            #pragma unroll
            for (int nt2 = 0; nt2 < 2; nt2++) {
                const int n  = warp_n * 32 + nt2 * 16 + (lane & 7) + ((lane >> 4) << 3);
                const int kc = kk + (((lane >> 3) & 1) << 3);
                ldm_x4(&bf[nt2 * 4], bT + n * G_ROWB + kc * 2);
            }
            uint32_t af[16];
            {
                const int rbase = warp_m * 64 + (lane & 15);
                const int kc    = kk + ((lane >> 4) << 3);
                #pragma unroll
                for (int mt = 0; mt < 4; mt++)
                    ldm_x4(&af[mt * 4], aT + (rbase + mt * 16) * G_ROWB + kc * 2);
            }
            #pragma unroll
            for (int mt = 0; mt < 4; mt++)
                #pragma unroll
                for (int nt = 0; nt < 4; nt++) {
                    const int bi = (nt >> 1) * 4 + (nt & 1) * 2;
                    mma_fp16(acc[mt][nt], &af[mt * 4], bf[bi], bf[bi + 1]);
                }
        }
    }

    if (mat < 2) {
        float* C = mat ? Ck : Cq;
        #pragma unroll
        for (int mt = 0; mt < 4; mt++) {
            const int row0 = bm + warp_m * 64 + mt * 16 + (lane >> 2);
            #pragma unroll
            for (int nt = 0; nt < 4; nt++) {
                const int col = bn + warp_n * 32 + nt * 8 + ((lane & 3) << 1);
                const float b0 = bias[col], b1 = bias[col + 1];
                float2 v0 = { acc[mt][nt][0] + b0, acc[mt][nt][1] + b1 };
                float2 v1 = { acc[mt][nt][2] + b0, acc[mt][nt][3] + b1 };
                *(float2*)&C[(size_t)row0 * DIM + col]       = v0;
                *(float2*)&C[(size_t)(row0 + 8) * DIM + col] = v1;
            }
        }
    } else {
        #pragma unroll
        for (int mt = 0; mt < 4; mt++) {
            const int row0 = bm + warp_m * 64 + mt * 16 + (lane >> 2);
            #pragma unroll
            for (int nt = 0; nt < 4; nt++) {
                const int col = bn + warp_n * 32 + nt * 8 + ((lane & 3) << 1);
                const float b0 = bias[col], b1 = bias[col + 1];
                __half2 v0 = __floats2half2_rn(acc[mt][nt][0] + b0, acc[mt][nt][1] + b1);
                __half2 v1 = __floats2half2_rn(acc[mt][nt][2] + b0, acc[mt][nt][3] + b1);
                *(uint32_t*)&Cv[(size_t)row0 * DIM + col]       = *(uint32_t*)&v0;
                *(uint32_t*)&Cv[(size_t)(row0 + 8) * DIM + col] = *(uint32_t*)&v1;
            }
        }
    }
}

// ---------------------------------------------------------------------------
// 1-pass fp16 GEMM (Wo projection, verified round 8)
// ---------------------------------------------------------------------------
__global__ __launch_bounds__(256)
void gemm1_kernel(const __half* __restrict__ A,
                  const __half* __restrict__ B,
                  const float* __restrict__ bias,
                  float* __restrict__ C) {
    extern __shared__ char smem[];
    const uint32_t sbase = smem_u32(smem);
    const int tid  = threadIdx.x;
    const int wid  = tid >> 5;
    const int lane = tid & 31;
    const int bm   = blockIdx.y * GBM;
    const int bn   = blockIdx.x * GBN;
    const int warp_m = wid & 1;
    const int warp_n = wid >> 1;

    const __half* basep[2] = { A + (size_t)bm * DIM, B + (size_t)bn * DIM };
    const int cp_row[2] = { tid >> 2, (tid + 256) >> 2 };
    const int cp_c4     = tid & 3;

    auto copy_chunk = [&](int c, uint32_t stage) {
        #pragma unroll
        for (int t = 0; t < 2; t++) {
            #pragma unroll
            for (int half = 0; half < 2; half++) {
                const int row = cp_row[half];
                const __half* g = basep[t] + (size_t)row * DIM + c * GBK + cp_c4 * 8;
                CP_ASYNC16(stage + t * G_TILEB + row * G_ROWB + cp_c4 * 16, g);
            }
        }
    };

    float acc[4][4][4] = {};
    copy_chunk(0, sbase);
    CP_COMMIT();

    for (int c = 0; c < G_NC; c++) {
        __syncthreads();
        if (c + 1 < G_NC) {
            copy_chunk(c + 1, sbase + ((c + 1) & 1) * G1_STAGEB);
            CP_COMMIT();
            CP_WAIT1();
        } else {
            CP_WAIT0();
        }
        __syncthreads();

        const uint32_t st = sbase + (c & 1) * G1_STAGEB;
        const uint32_t aT = st;
        const uint32_t bT = st + G_TILEB;

        #pragma unroll
        for (int kk = 0; kk < GBK; kk += 16) {
            uint32_t bf[8];
            #pragma unroll
            for (int nt2 = 0; nt2 < 2; nt2++) {
                const int n  = warp_n * 32 + nt2 * 16 + (lane & 7) + ((lane >> 4) << 3);
                const int kc = kk + (((lane >> 3) & 1) << 3);
                ldm_x4(&bf[nt2 * 4], bT + n * G_ROWB + kc * 2);
            }
            uint32_t af[16];
            {
                const int rbase = warp_m * 64 + (lane & 15);
                const int kc    = kk + ((lane >> 4) << 3);
                #pragma unroll
                for (int mt = 0; mt < 4; mt++)
                    ldm_x4(&af[mt * 4], aT + (rbase + mt * 16) * G_ROWB + kc * 2);
            }
            #pragma unroll
            for (int mt = 0; mt < 4; mt++)
                #pragma unroll
                for (int nt = 0; nt < 4; nt++) {
                    const int bi = (nt >> 1) * 4 + (nt & 1) * 2;
                    mma_fp16(acc[mt][nt], &af[mt * 4], bf[bi], bf[bi + 1]);
                }
        }
    }

    #pragma unroll
    for (int mt = 0; mt < 4; mt++) {
        const int row0 = bm + warp_m * 64 + mt * 16 + (lane >> 2);
        #pragma unroll
        for (int nt = 0; nt < 4; nt++) {
            const int col = bn + warp_n * 32 + nt * 8 + ((lane & 3) << 1);
            const float b0 = bias[col], b1 = bias[col + 1];
            float2 v0 = { acc[mt][nt][0] + b0, acc[mt][nt][1] + b1 };
            float2 v1 = { acc[mt][nt][2] + b0, acc[mt][nt][3] + b1 };
            *(float2*)&C[(size_t)row0 * DIM + col]       = v0;
            *(float2*)&C[(size_t)(row0 + 8) * DIM + col] = v1;
        }
    }
}

// ---------------------------------------------------------------------------
// Fused RMSNorm + RoPE, merged Q/K launch (grid.y: 0=Q, 1=K)
// ---------------------------------------------------------------------------
__global__ void rmsnorm_rope_kernel(const float* __restrict__ Xq,
                                    const float* __restrict__ Xk,
                                    const float* __restrict__ gqv,
                                    const float* __restrict__ gkv,
                                    const float* __restrict__ fc,
                                    const float* __restrict__ fs,
                                    __half* __restrict__ Oq,
                                    __half* __restrict__ Ok) {
    const int s = blockIdx.x;
    const int which = blockIdx.y;
    const float* X = which ? Xk : Xq;
    const float* g = which ? gkv : gqv;
    __half* O = which ? Ok : Oq;

    __shared__ float buf[DIM];
    __shared__ float red[8];
    __shared__ float s_scale;

    const float* row = X + (size_t)s * DIM;

    float ss = 0.f;
    for (int i = threadIdx.x; i < DIM; i += blockDim.x) {
        float v = row[i];
        buf[i] = v;
        ss += v * v;
    }
    #pragma unroll
    for (int o = 16; o > 0; o >>= 1) ss += __shfl_xor_sync(0xFFFFFFFFu, ss, o);
    if ((threadIdx.x & 31) == 0) red[threadIdx.x >> 5] = ss;
    __syncthreads();
    if (threadIdx.x == 0) {
        float t = 0.f;
        #pragma unroll
        for (int w = 0; w < 8; w++) t += red[w];
        s_scale = rsqrtf(t / (float)DIM + 1e-6f);
    }
    __syncthreads();
    const float scale = s_scale;

    const float* fcs = fc + (size_t)s * HDIM;
    const float* fss = fs + (size_t)s * HDIM;

    for (int i = threadIdx.x; i < DIM; i += blockDim.x) {
        int j = i & (HDIM - 1);
        float v = buf[i] * scale * g[i];
        float out;
        if (j < HDIM / 2) {
            float other = buf[i + HDIM / 2] * scale * g[i + HDIM / 2];
            out = v * fcs[j] - other * fss[j];
        } else {
            float other = buf[i - HDIM / 2] * scale * g[i - HDIM / 2];
            out = v * fcs[j] + other * fss[j];
        }
        O[(size_t)s * DIM + i] = __float2half(out);
    }
}

// ---------------------------------------------------------------------------
// Flash attention, register-resident softmax (FA2 fragment trick).
// BR=128, BC=64, 256 threads (8 warps); warp owns 16 rows x full 64 S-cols.
// S and P never touch smem; row stats live in registers (4-lane shuffles).
// ---------------------------------------------------------------------------
#define A_PITCH 272
#define Q_TILEB (128 * A_PITCH)     // 34816
#define KV_TILEB (64 * A_PITCH)     // 17408
#define OFF_KV  Q_TILEB
#define ATT_SMEM (OFF_KV + 4 * KV_TILEB)   // 104448

__global__ __launch_bounds__(256, 2)
void attn_mma_kernel(const __half* __restrict__ Q_g,
                     const __half* __restrict__ K_g,
                     const __half* __restrict__ V_g,
                     __half* __restrict__ A_g) {
    extern __shared__ char smem[];
    const uint32_t sb = smem_u32(smem);
    const int tid  = threadIdx.x;
    const int wid  = tid >> 5;
    const int lane = tid & 31;
    const int h    = blockIdx.y;
    const int q0   = blockIdx.x * 128;
    // softmax scale folded into exp2: exp(s/sqrt(d) - m/sqrt(d)) = 2^((s-m)*K2)
    const float K2 = 0.08838834764831845f * 1.4426950408889634f;

    const uint32_t sQ = sb;

    // prologue: Q tile (128 rows x 128 cols fp16) — 8 cp.async per thread
    #pragma unroll
    for (int i = 0; i < 8; i++) {
        int cid = i * 256 + tid;
        int row = cid >> 4, c = cid & 15;
        const __half* gp = Q_g + (size_t)(q0 + row) * DIM + h * HDIM + c * 8;
        CP_ASYNC16(sQ + row * A_PITCH + c * 16, gp);
    }
    const __half* kvsrc[2] = { K_g, V_g };
    auto load_stage = [&](int kt, int s) {
        uint32_t stb = sb + OFF_KV + s * 2 * KV_TILEB;
        #pragma unroll
        for (int i = 0; i < 8; i++) {
            int cid = i * 256 + tid;
            int tile = cid >> 10, row = (cid >> 4) & 63, c = cid & 15;
            const __half* gp = kvsrc[tile] + (size_t)(kt * 64 + row) * DIM + h * HDIM + c * 8;
            CP_ASYNC16(stb + tile * KV_TILEB + row * A_PITCH + c * 16, gp);
        }
    };
    load_stage(0, 0);
    CP_COMMIT();
    load_stage(1, 1);
    CP_COMMIT();

    float m0 = -1e30f, m1 = -1e30f;   // running max (raw logit units), rows r / r+8
    float l0 = 0.f, l1 = 0.f;         // running denom
    float oacc[16][4] = {};           // 16 rows x 128 cols per warp

    const int rb = wid * 16 + (lane & 15);   // ldmatrix row base for Q / A-frags

    for (int kt = 0; kt < 64; kt++) {
        if (kt < 63) CP_WAIT1(); else CP_WAIT0();
        __syncthreads();
        const uint32_t st = sb + OFF_KV + (kt & 1) * 2 * KV_TILEB;
        const uint32_t sK = st;
        const uint32_t sV = st + KV_TILEB;

        // ---- S = Q @ K^T : 16 rows x 64 cols in registers ----
        float sacc[8][4] = {};
        #pragma unroll
        for (int kk = 0; kk < 8; kk++) {
            uint32_t aq[4];
            const int kc = kk * 16 + ((lane >> 4) << 3);
            ldm_x4(aq, sQ + rb * A_PITCH + kc * 2);
            const int kc2 = kk * 16 + (((lane >> 3) & 1) << 3);
            #pragma unroll
            for (int half = 0; half < 2; half++) {
                uint32_t bk[8];
                const int nr = half * 32 + (lane & 7) + ((lane >> 4) << 3);
                ldm_x4(bk,     sK + nr * A_PITCH + kc2 * 2);
                ldm_x4(bk + 4, sK + (nr + 16) * A_PITCH + kc2 * 2);
                #pragma unroll
                for (int j = 0; j < 4; j++)
                    mma_fp16(sacc[half * 4 + j], aq, bk[j * 2], bk[j * 2 + 1]);
            }
        }

        // ---- softmax in registers (4-lane row groups) ----
        float mx0 = -1e30f, mx1 = -1e30f;
        #pragma unroll
        for (int nt = 0; nt < 8; nt++) {
            mx0 = fmaxf(mx0, fmaxf(sacc[nt][0], sacc[nt][1]));
            mx1 = fmaxf(mx1, fmaxf(sacc[nt][2], sacc[nt][3]));
        }
        mx0 = fmaxf(mx0, __shfl_xor_sync(0xFFFFFFFFu, mx0, 1));
        mx0 = fmaxf(mx0, __shfl_xor_sync(0xFFFFFFFFu, mx0, 2));
        mx1 = fmaxf(mx1, __shfl_xor_sync(0xFFFFFFFFu, mx1, 1));
        mx1 = fmaxf(mx1, __shfl_xor_sync(0xFFFFFFFFu, mx1, 2));
        const float mn0 = fmaxf(m0, mx0);
        const float mn1 = fmaxf(m1, mx1);
        const float a0 = ex2f((m0 - mn0) * K2);
        const float a1 = ex2f((m1 - mn1) * K2);
        m0 = mn0; m1 = mn1;

        float s0 = 0.f, s1 = 0.f;
        #pragma unroll
        for (int nt = 0; nt < 8; nt++) {
            float p0 = ex2f((sacc[nt][0] - mn0) * K2);
            float p1 = ex2f((sacc[nt][1] - mn0) * K2);
            float p2 = ex2f((sacc[nt][2] - mn1) * K2);
            float p3 = ex2f((sacc[nt][3] - mn1) * K2);
            sacc[nt][0] = p0; sacc[nt][1] = p1;
            sacc[nt][2] = p2; sacc[nt][3] = p3;
            s0 += p0 + p1; s1 += p2 + p3;
        }
        s0 += __shfl_xor_sync(0xFFFFFFFFu, s0, 1);
        s0 += __shfl_xor_sync(0xFFFFFFFFu, s0, 2);
        s1 += __shfl_xor_sync(0xFFFFFFFFu, s1, 1);
        s1 += __shfl_xor_sync(0xFFFFFFFFu, s1, 2);
        l0 = l0 * a0 + s0;
        l1 = l1 * a1 + s1;

        // ---- rescale O, then O += P @ V (P packed from sacc fragments) ----
        #pragma unroll
        for (int nt = 0; nt < 16; nt++) {
            oacc[nt][0] *= a0; oacc[nt][1] *= a0;
            oacc[nt][2] *= a1; oacc[nt][3] *= a1;
        }
        #pragma unroll
        for (int kk = 0; kk < 4; kk++) {
            uint32_t ap[4];
            {   // C-frag pair (tiles 2kk, 2kk+1) -> A-frag for K=16
                __half2 t0 = __floats2half2_rn(sacc[2 * kk][0],     sacc[2 * kk][1]);
                __half2 t1 = __floats2half2_rn(sacc[2 * kk][2],     sacc[2 * kk][3]);
                __half2 t2 = __floats2half2_rn(sacc[2 * kk + 1][0], sacc[2 * kk + 1][1]);
                __half2 t3 = __floats2half2_rn(sacc[2 * kk + 1][2], sacc[2 * kk + 1][3]);
                ap[0] = *(uint32_t*)&t0; ap[1] = *(uint32_t*)&t1;
                ap[2] = *(uint32_t*)&t2; ap[3] = *(uint32_t*)&t3;
            }
            const int vr = kk * 16 + (lane & 7) + (((lane >> 3) & 1) << 3);
            #pragma unroll
            for (int q = 0; q < 4; q++) {
                uint32_t bv[8];
                const int vc = q * 32 + ((lane >> 4) << 3);
                ldm_x4_t(bv,     sV + vr * A_PITCH + vc * 2);
                ldm_x4_t(bv + 4, sV + vr * A_PITCH + (vc + 16) * 2);
                #pragma unroll
                for (int j = 0; j < 4; j++)
                    mma_fp16(oacc[q * 4 + j], ap, bv[j * 2], bv[j * 2 + 1]);
            }
        }
        __syncthreads();

        if (kt + 2 < 64) {
            load_stage(kt + 2, kt & 1);
            CP_COMMIT();
        }
    }

    // ---- epilogue: O /= l, write fp16 ----
    {
        const int r = wid * 16 + (lane >> 2);
        const float inv0 = 1.f / l0;
        const float inv1 = 1.f / l1;
        const size_t gr0 = (size_t)(q0 + r) * DIM;
        const size_t gr1 = (size_t)(q0 + r + 8) * DIM;
        #pragma unroll
        for (int nt = 0; nt < 16; nt++) {
            const int col = h * HDIM + nt * 8 + ((lane & 3) << 1);
            __half2 p0 = __floats2half2_rn(oacc[nt][0] * inv0, oacc[nt][1] * inv0);
            __half2 p1 = __floats2half2_rn(oacc[nt][2] * inv1, oacc[nt][3] * inv1);
            *(uint32_t*)&A_g[gr0 + col] = *(uint32_t*)&p0;
            *(uint32_t*)&A_g[gr1 + col] = *(uint32_t*)&p1;
        }
    }
}

// ---------------------------------------------------------------------------
extern "C" void kernel_launch(void* const* d_in, const int* in_sizes, int n_in,
                              void* d_out, int out_size) {
    const float* x   = (const float*)d_in[0];
    const float* fc  = (const float*)d_in[1];
    const float* fs  = (const float*)d_in[2];
    const float* Wq  = (const float*)d_in[3];
    const float* bq  = (const float*)d_in[4];
    const float* Wk  = (const float*)d_in[5];
    const float* bk  = (const float*)d_in[6];
    const float* Wv  = (const float*)d_in[7];
    const float* bv  = (const float*)d_in[8];
    const float* Wo  = (const float*)d_in[9];
    const float* bo  = (const float*)d_in[10];
    const float* gq  = (const float*)d_in[11];
    const float* gk  = (const float*)d_in[12];
    float* out = (float*)d_out;

    float *dQ, *dK;
    cudaGetSymbolAddress((void**)&dQ, g_Q);
    cudaGetSymbolAddress((void**)&dK, g_K);
    __half *xf, *af, *qf, *kf, *vf, *wqkv, *wof;
    cudaGetSymbolAddress((void**)&xf, g_xf);
    cudaGetSymbolAddress((void**)&af, g_Af);
    cudaGetSymbolAddress((void**)&qf, g_Qf);
    cudaGetSymbolAddress((void**)&kf, g_Kf);
    cudaGetSymbolAddress((void**)&vf, g_Vf);
    cudaGetSymbolAddress((void**)&wqkv, g_Wqkv);
    cudaGetSymbolAddress((void**)&wof, g_Wof);

    const int nconv = X4 + 4 * W4;
    convert_all_kernel<<<(nconv + 255) / 256, 256>>>(x, Wq, Wk, Wv, Wo, xf, wqkv, wof);

    cudaFuncSetAttribute(gemm_qkv_kernel, cudaFuncAttributeMaxDynamicSharedMemorySize, G1_SMEM);
    cudaFuncSetAttribute(gemm1_kernel, cudaFuncAttributeMaxDynamicSharedMemorySize, G1_SMEM);

    dim3 gqkv(3 * DIM / GBN, S_LEN / GBM);   // (36, 32)
    gemm_qkv_kernel<<<gqkv, 256, G1_SMEM>>>(xf, wqkv, bq, bk, bv, dQ, dK, vf);

    dim3 rgrid(S_LEN, 2);
    rmsnorm_rope_kernel<<<rgrid, 256>>>(dQ, dK, gq, gk, fc, fs, qf, kf);

    cudaFuncSetAttribute(attn_mma_kernel, cudaFuncAttributeMaxDynamicSharedMemorySize, ATT_SMEM);
    dim3 agrid(S_LEN / 128, NHEAD);
    attn_mma_kernel<<<agrid, 256, ATT_SMEM>>>(qf, kf, vf, af);

    dim3 ggrid(DIM / GBN, S_LEN / GBM);
    gemm1_kernel<<<ggrid, 256, G1_SMEM>>>(af, wof, bo, out);
}

// round 10
// speedup vs baseline: 13.4215x; 1.0454x over previous
#include <cuda_runtime.h>
#include <cuda_bf16.h>
#include <cuda_fp16.h>
#include <math.h>
#include <stdint.h>

#define S_LEN 4096
#define DIM   1536
#define NHEAD 12
#define HDIM  128
#define KSPLIT 3

// ---------------------------------------------------------------------------
// scratch (device globals: no cudaMalloc allowed)
// ---------------------------------------------------------------------------
__device__ float g_Q[S_LEN * DIM];
__device__ float g_K[S_LEN * DIM];

__device__ float g_U[KSPLIT * S_LEN * DIM];          // split-K partial numerators
__device__ float g_Sm[KSPLIT * NHEAD * S_LEN];       // per-row running max
__device__ float g_Sl[KSPLIT * NHEAD * S_LEN];       // per-row denom

__device__ __align__(128) __half g_xf[S_LEN * DIM];
__device__ __align__(128) __half g_Af[S_LEN * DIM];
__device__ __align__(128) __half g_Qf[S_LEN * DIM];
__device__ __align__(128) __half g_Kf[S_LEN * DIM];
__device__ __align__(128) __half g_Vf[S_LEN * DIM];

__device__ __align__(128) __half g_Wqkv[3 * DIM * DIM];
__device__ __align__(128) __half g_Wof[DIM * DIM];

__device__ __forceinline__ uint32_t smem_u32(const void* p) {
    uint32_t a;
    asm("{ .reg .u64 t; cvta.to.shared.u64 t, %1; cvt.u32.u64 %0, t; }"
        : "=r"(a) : "l"(p));
    return a;
}

__device__ __forceinline__ void ldm_x4(uint32_t* r, uint32_t addr) {
    asm volatile("ldmatrix.sync.aligned.m8n8.x4.shared.b16 {%0,%1,%2,%3}, [%4];"
        : "=r"(r[0]), "=r"(r[1]), "=r"(r[2]), "=r"(r[3]) : "r"(addr));
}
__device__ __forceinline__ void ldm_x4_t(uint32_t* r, uint32_t addr) {
    asm volatile("ldmatrix.sync.aligned.m8n8.x4.trans.shared.b16 {%0,%1,%2,%3}, [%4];"
        : "=r"(r[0]), "=r"(r[1]), "=r"(r[2]), "=r"(r[3]) : "r"(addr));
}

__device__ __forceinline__ void mma_fp16(float* c, const uint32_t* a,
                                         uint32_t b0, uint32_t b1) {
    asm volatile(
        "mma.sync.aligned.m16n8k16.row.col.f32.f16.f16.f32 "
        "{%0,%1,%2,%3}, {%4,%5,%6,%7}, {%8,%9}, {%0,%1,%2,%3};"
        : "+f"(c[0]), "+f"(c[1]), "+f"(c[2]), "+f"(c[3])
        : "r"(a[0]), "r"(a[1]), "r"(a[2]), "r"(a[3]), "r"(b0), "r"(b1));
}

__device__ __forceinline__ float ex2f(float x) {
    float y;
    asm("ex2.approx.ftz.f32 %0, %1;" : "=f"(y) : "f"(x));
    return y;
}

#define CP_ASYNC16(saddr, gptr) \
    asm volatile("cp.async.cg.shared.global [%0], [%1], 16;" :: "r"(saddr), "l"(gptr))
#define CP_COMMIT()  asm volatile("cp.async.commit_group;" ::: "memory")
#define CP_WAIT1()   asm volatile("cp.async.wait_group 1;" ::: "memory")
#define CP_WAIT0()   asm volatile("cp.async.wait_group 0;" ::: "memory")

#define K2C 0.1275025621249438f   // (1/sqrt(128)) * log2(e)

// ---------------------------------------------------------------------------
// merged fp32 -> fp16 conversion of x + 4 weights (one launch)
// ---------------------------------------------------------------------------
#define X4 (S_LEN * DIM / 4)
#define W4 (DIM * DIM / 4)

__global__ void convert_all_kernel(const float* __restrict__ x,
                                   const float* __restrict__ Wq,
                                   const float* __restrict__ Wk,
                                   const float* __restrict__ Wv,
                                   const float* __restrict__ Wo,
                                   __half* __restrict__ xf,
                                   __half* __restrict__ wqkv,
                                   __half* __restrict__ wof) {
    int i = blockIdx.x * blockDim.x + threadIdx.x;
    const float* src;
    __half* dst;
    int off;
    if (i < X4)               { src = x;  dst = xf;   off = i; }
    else if (i < X4 + W4)     { src = Wq; dst = wqkv; off = i - X4; }
    else if (i < X4 + 2 * W4) { src = Wk; dst = wqkv + (size_t)DIM * DIM;     off = i - X4 - W4; }
    else if (i < X4 + 3 * W4) { src = Wv; dst = wqkv + 2 * (size_t)DIM * DIM; off = i - X4 - 2 * W4; }
    else if (i < X4 + 4 * W4) { src = Wo; dst = wof;  off = i - X4 - 3 * W4; }
    else return;
    float4 v = ((const float4*)src)[off];
    __half2 a = __floats2half2_rn(v.x, v.y);
    __half2 b = __floats2half2_rn(v.z, v.w);
    uint2 o = { *(uint32_t*)&a, *(uint32_t*)&b };
    *(uint2*)(dst + 4 * (size_t)off) = o;
}

// ---------------------------------------------------------------------------
// shared GEMM tiling constants
// ---------------------------------------------------------------------------
#define GBM 128
#define GBN 128
#define GBK 32
#define G_NC (DIM / GBK)
#define G_ROWB 80
#define G_TILEB (128 * G_ROWB)
#define G1_STAGEB (2 * G_TILEB)
#define G1_SMEM (2 * G1_STAGEB)   // 40960

// ---------------------------------------------------------------------------
// Fused QKV GEMM (verified round 8)
// ---------------------------------------------------------------------------
__global__ __launch_bounds__(256)
void gemm_qkv_kernel(const __half* __restrict__ A,
                     const __half* __restrict__ Wqkv,
                     const float* __restrict__ bq,
                     const float* __restrict__ bk,
                     const float* __restrict__ bv,
                     float* __restrict__ Cq,
                     float* __restrict__ Ck,
                     __half* __restrict__ Cv) {
    extern __shared__ char smem[];
    const uint32_t sbase = smem_u32(smem);
    const int tid  = threadIdx.x;
    const int wid  = tid >> 5;
    const int lane = tid & 31;
    const int bm   = blockIdx.y * GBM;
    const int mat  = blockIdx.x / 12;
    const int bn   = (blockIdx.x % 12) * GBN;
    const int warp_m = wid & 1;
    const int warp_n = wid >> 1;

    const float* biasv[3] = { bq, bk, bv };
    const float* bias = biasv[mat];

    const __half* basep[2] = {
        A + (size_t)bm * DIM,
        Wqkv + (size_t)blockIdx.x * GBN * DIM };
    const int cp_row[2] = { tid >> 2, (tid + 256) >> 2 };
    const int cp_c4     = tid & 3;

    auto copy_chunk = [&](int c, uint32_t stage) {
        #pragma unroll
        for (int t = 0; t < 2; t++) {
            #pragma unroll
            for (int half = 0; half < 2; half++) {
                const int row = cp_row[half];
                const __half* g = basep[t] + (size_t)row * DIM + c * GBK + cp_c4 * 8;
                CP_ASYNC16(stage + t * G_TILEB + row * G_ROWB + cp_c4 * 16, g);
            }
        }
    };

    float acc[4][4][4] = {};
    copy_chunk(0, sbase);
    CP_COMMIT();

    for (int c = 0; c < G_NC; c++) {
        __syncthreads();
        if (c + 1 < G_NC) {
            copy_chunk(c + 1, sbase + ((c + 1) & 1) * G1_STAGEB);
            CP_COMMIT();
            CP_WAIT1();
        } else {
            CP_WAIT0();
        }
        __syncthreads();

        const uint32_t st = sbase + (c & 1) * G1_STAGEB;
        const uint32_t aT = st;
        const uint32_t bT = st + G_TILEB;

        #pragma unroll
        for (int kk = 0; kk < GBK; kk += 16) {
            uint32_t bf[8];
            #pragma unroll
            for (int nt2 = 0; nt2 < 2; nt2++) {
                const int n  = warp_n * 32 + nt2 * 16 + (lane & 7) + ((lane >> 4) << 3);
                const int kc = kk + (((lane >> 3) & 1) << 3);
                ldm_x4(&bf[nt2 * 4], bT + n * G_ROWB + kc * 2);
            }
            uint32_t af[16];
            {
                const int rbase = warp_m * 64 + (lane & 15);
                const int kc    = kk + ((lane >> 4) << 3);
                #pragma unroll
                for (int mt = 0; mt < 4; mt++)
                    ldm_x4(&af[mt * 4], aT + (rbase + mt * 16) * G_ROWB + kc * 2);
            }
            #pragma unroll
            for (int mt = 0; mt < 4; mt++)
                #pragma unroll
                for (int nt = 0; nt < 4; nt++) {
                    const int bi = (nt >> 1) * 4 + (nt & 1) * 2;
                    mma_fp16(acc[mt][nt], &af[mt * 4], bf[bi], bf[bi + 1]);
                }
        }
    }

    if (mat < 2) {
        float* C = mat ? Ck : Cq;
        #pragma unroll
        for (int mt = 0; mt < 4; mt++) {
            const int row0 = bm + warp_m * 64 + mt * 16 + (lane >> 2);
            #pragma unroll
            for (int nt = 0; nt < 4; nt++) {
                const int col = bn + warp_n * 32 + nt * 8 + ((lane & 3) << 1);
                const float b0 = bias[col], b1 = bias[col + 1];
                float2 v0 = { acc[mt][nt][0] + b0, acc[mt][nt][1] + b1 };
                float2 v1 = { acc[mt][nt][2] + b0, acc[mt][nt][3] + b1 };
                *(float2*)&C[(size_t)row0 * DIM + col]       = v0;
                *(float2*)&C[(size_t)(row0 + 8) * DIM + col] = v1;
            }
        }
    } else {
        #pragma unroll
        for (int mt = 0; mt < 4; mt++) {
            const int row0 = bm + warp_m * 64 + mt * 16 + (lane >> 2);
            #pragma unroll
            for (int nt = 0; nt < 4; nt++) {
                const int col = bn + warp_n * 32 + nt * 8 + ((lane & 3) << 1);
                const float b0 = bias[col], b1 = bias[col + 1];
                __half2 v0 = __floats2half2_rn(acc[mt][nt][0] + b0, acc[mt][nt][1] + b1);
                __half2 v1 = __floats2half2_rn(acc[mt][nt][2] + b0, acc[mt][nt][3] + b1);
                *(uint32_t*)&Cv[(size_t)row0 * DIM + col]       = *(uint32_t*)&v0;
                *(uint32_t*)&Cv[(size_t)(row0 + 8) * DIM + col] = *(uint32_t*)&v1;
            }
        }
    }
}

// ---------------------------------------------------------------------------
// 1-pass fp16 GEMM (Wo projection, verified round 8)
// ---------------------------------------------------------------------------
__global__ __launch_bounds__(256)
void gemm1_kernel(const __half* __restrict__ A,
                  const __half* __restrict__ B,
                  const float* __restrict__ bias,
                  float* __restrict__ C) {
    extern __shared__ char smem[];
    const uint32_t sbase = smem_u32(smem);
    const int tid  = threadIdx.x;
    const int wid  = tid >> 5;
    const int lane = tid & 31;
    const int bm   = blockIdx.y * GBM;
    const int bn   = blockIdx.x * GBN;
    const int warp_m = wid & 1;
    const int warp_n = wid >> 1;

    const __half* basep[2] = { A + (size_t)bm * DIM, B + (size_t)bn * DIM };
    const int cp_row[2] = { tid >> 2, (tid + 256) >> 2 };
    const int cp_c4     = tid & 3;

    auto copy_chunk = [&](int c, uint32_t stage) {
        #pragma unroll
        for (int t = 0; t < 2; t++) {
            #pragma unroll
            for (int half = 0; half < 2; half++) {
                const int row = cp_row[half];
                const __half* g = basep[t] + (size_t)row * DIM + c * GBK + cp_c4 * 8;
                CP_ASYNC16(stage + t * G_TILEB + row * G_ROWB + cp_c4 * 16, g);
            }
        }
    };

    float acc[4][4][4] = {};
    copy_chunk(0, sbase);
    CP_COMMIT();

    for (int c = 0; c < G_NC; c++) {
        __syncthreads();
        if (c + 1 < G_NC) {
            copy_chunk(c + 1, sbase + ((c + 1) & 1) * G1_STAGEB);
            CP_COMMIT();
            CP_WAIT1();
        } else {
            CP_WAIT0();
        }
        __syncthreads();

        const uint32_t st = sbase + (c & 1) * G1_STAGEB;
        const uint32_t aT = st;
        const uint32_t bT = st + G_TILEB;

        #pragma unroll
        for (int kk = 0; kk < GBK; kk += 16) {
            uint32_t bf[8];
            #pragma unroll
            for (int nt2 = 0; nt2 < 2; nt2++) {
                const int n  = warp_n * 32 + nt2 * 16 + (lane & 7) + ((lane >> 4) << 3);
                const int kc = kk + (((lane >> 3) & 1) << 3);
                ldm_x4(&bf[nt2 * 4], bT + n * G_ROWB + kc * 2);
            }
            uint32_t af[16];
            {
                const int rbase = warp_m * 64 + (lane & 15);
                const int kc    = kk + ((lane >> 4) << 3);
                #pragma unroll
                for (int mt = 0; mt < 4; mt++)
                    ldm_x4(&af[mt * 4], aT + (rbase + mt * 16) * G_ROWB + kc * 2);
            }
            #pragma unroll
            for (int mt = 0; mt < 4; mt++)
                #pragma unroll
                for (int nt = 0; nt < 4; nt++) {
                    const int bi = (nt >> 1) * 4 + (nt & 1) * 2;
                    mma_fp16(acc[mt][nt], &af[mt * 4], bf[bi], bf[bi + 1]);
                }
        }
    }

    #pragma unroll
    for (int mt = 0; mt < 4; mt++) {
        const int row0 = bm + warp_m * 64 + mt * 16 + (lane >> 2);
        #pragma unroll
        for (int nt = 0; nt < 4; nt++) {
            const int col = bn + warp_n * 32 + nt * 8 + ((lane & 3) << 1);
            const float b0 = bias[col], b1 = bias[col + 1];
            float2 v0 = { acc[mt][nt][0] + b0, acc[mt][nt][1] + b1 };
            float2 v1 = { acc[mt][nt][2] + b0, acc[mt][nt][3] + b1 };
            *(float2*)&C[(size_t)row0 * DIM + col]       = v0;
            *(float2*)&C[(size_t)(row0 + 8) * DIM + col] = v1;
        }
    }
}

// ---------------------------------------------------------------------------
// Fused RMSNorm + RoPE, merged Q/K launch
// ---------------------------------------------------------------------------
__global__ void rmsnorm_rope_kernel(const float* __restrict__ Xq,
                                    const float* __restrict__ Xk,
                                    const float* __restrict__ gqv,
                                    const float* __restrict__ gkv,
                                    const float* __restrict__ fc,
                                    const float* __restrict__ fs,
                                    __half* __restrict__ Oq,
                                    __half* __restrict__ Ok) {
    const int s = blockIdx.x;
    const int which = blockIdx.y;
    const float* X = which ? Xk : Xq;
    const float* g = which ? gkv : gqv;
    __half* O = which ? Ok : Oq;

    __shared__ float buf[DIM];
    __shared__ float red[8];
    __shared__ float s_scale;

    const float* row = X + (size_t)s * DIM;

    float ss = 0.f;
    for (int i = threadIdx.x; i < DIM; i += blockDim.x) {
        float v = row[i];
        buf[i] = v;
        ss += v * v;
    }
    #pragma unroll
    for (int o = 16; o > 0; o >>= 1) ss += __shfl_xor_sync(0xFFFFFFFFu, ss, o);
    if ((threadIdx.x & 31) == 0) red[threadIdx.x >> 5] = ss;
    __syncthreads();
    if (threadIdx.x == 0) {
        float t = 0.f;
        #pragma unroll
        for (int w = 0; w < 8; w++) t += red[w];
        s_scale = rsqrtf(t / (float)DIM + 1e-6f);
    }
    __syncthreads();
    const float scale = s_scale;

    const float* fcs = fc + (size_t)s * HDIM;
    const float* fss = fs + (size_t)s * HDIM;

    for (int i = threadIdx.x; i < DIM; i += blockDim.x) {
        int j = i & (HDIM - 1);
        float v = buf[i] * scale * g[i];
        float out;
        if (j < HDIM / 2) {
            float other = buf[i + HDIM / 2] * scale * g[i + HDIM / 2];
            out = v * fcs[j] - other * fss[j];
        } else {
            float other = buf[i - HDIM / 2] * scale * g[i - HDIM / 2];
            out = v * fcs[j] + other * fss[j];
        }
        O[(size_t)s * DIM + i] = __float2half(out);
    }
}

// ---------------------------------------------------------------------------
// Flash attention, register-resident softmax + split-K (3 splits of 64 tiles).
// Emits unnormalized partial numerator U (fp32) + per-row stats (m, l).
// ---------------------------------------------------------------------------
#define A_PITCH 272
#define Q_TILEB (128 * A_PITCH)
#define KV_TILEB (64 * A_PITCH)
#define OFF_KV  Q_TILEB
#define ATT_SMEM (OFF_KV + 4 * KV_TILEB)   // 104448

__global__ __launch_bounds__(256, 2)
void attn_mma_kernel(const __half* __restrict__ Q_g,
                     const __half* __restrict__ K_g,
                     const __half* __restrict__ V_g,
                     float* __restrict__ U,
                     float* __restrict__ Sm,
                     float* __restrict__ Sl) {
    extern __shared__ char smem[];
    const uint32_t sb = smem_u32(smem);
    const int tid  = threadIdx.x;
    const int wid  = tid >> 5;
    const int lane = tid & 31;
    const int h    = blockIdx.y;
    const int q0   = blockIdx.x * 128;
    const int split = blockIdx.z;
    // splits of 64 tiles: 22 / 21 / 21
    const int kt0    = split == 0 ? 0 : (split == 1 ? 22 : 43);
    const int ntiles = split == 0 ? 22 : 21;

    const uint32_t sQ = sb;

    #pragma unroll
    for (int i = 0; i < 8; i++) {
        int cid = i * 256 + tid;
        int row = cid >> 4, c = cid & 15;
        const __half* gp = Q_g + (size_t)(q0 + row) * DIM + h * HDIM + c * 8;
        CP_ASYNC16(sQ + row * A_PITCH + c * 16, gp);
    }
    const __half* kvsrc[2] = { K_g, V_g };
    auto load_stage = [&](int kt, int s) {
        uint32_t stb = sb + OFF_KV + s * 2 * KV_TILEB;
        #pragma unroll
        for (int i = 0; i < 8; i++) {
            int cid = i * 256 + tid;
            int tile = cid >> 10, row = (cid >> 4) & 63, c = cid & 15;
            const __half* gp = kvsrc[tile] + (size_t)(kt * 64 + row) * DIM + h * HDIM + c * 8;
            CP_ASYNC16(stb + tile * KV_TILEB + row * A_PITCH + c * 16, gp);
        }
    };
    load_stage(kt0, 0);
    CP_COMMIT();
    load_stage(kt0 + 1, 1);
    CP_COMMIT();

    float m0 = -1e30f, m1 = -1e30f;
    float l0 = 0.f, l1 = 0.f;
    float oacc[16][4] = {};

    const int rb = wid * 16 + (lane & 15);

    for (int t = 0; t < ntiles; t++) {
        if (t < ntiles - 1) CP_WAIT1(); else CP_WAIT0();
        __syncthreads();
        const uint32_t st = sb + OFF_KV + (t & 1) * 2 * KV_TILEB;
        const uint32_t sK = st;
        const uint32_t sV = st + KV_TILEB;

        // ---- S = Q @ K^T ----
        float sacc[8][4] = {};
        #pragma unroll
        for (int kk = 0; kk < 8; kk++) {
            uint32_t aq[4];
            const int kc = kk * 16 + ((lane >> 4) << 3);
            ldm_x4(aq, sQ + rb * A_PITCH + kc * 2);
            const int kc2 = kk * 16 + (((lane >> 3) & 1) << 3);
            #pragma unroll
            for (int half = 0; half < 2; half++) {
                uint32_t bk[8];
                const int nr = half * 32 + (lane & 7) + ((lane >> 4) << 3);
                ldm_x4(bk,     sK + nr * A_PITCH + kc2 * 2);
                ldm_x4(bk + 4, sK + (nr + 16) * A_PITCH + kc2 * 2);
                #pragma unroll
                for (int j = 0; j < 4; j++)
                    mma_fp16(sacc[half * 4 + j], aq, bk[j * 2], bk[j * 2 + 1]);
            }
        }

        // ---- softmax in registers ----
        float mx0 = -1e30f, mx1 = -1e30f;
        #pragma unroll
        for (int nt = 0; nt < 8; nt++) {
            mx0 = fmaxf(mx0, fmaxf(sacc[nt][0], sacc[nt][1]));
            mx1 = fmaxf(mx1, fmaxf(sacc[nt][2], sacc[nt][3]));
        }
        mx0 = fmaxf(mx0, __shfl_xor_sync(0xFFFFFFFFu, mx0, 1));
        mx0 = fmaxf(mx0, __shfl_xor_sync(0xFFFFFFFFu, mx0, 2));
        mx1 = fmaxf(mx1, __shfl_xor_sync(0xFFFFFFFFu, mx1, 1));
        mx1 = fmaxf(mx1, __shfl_xor_sync(0xFFFFFFFFu, mx1, 2));
        const float mn0 = fmaxf(m0, mx0);
        const float mn1 = fmaxf(m1, mx1);
        const float a0 = ex2f((m0 - mn0) * K2C);
        const float a1 = ex2f((m1 - mn1) * K2C);
        m0 = mn0; m1 = mn1;

        float s0 = 0.f, s1 = 0.f;
        #pragma unroll
        for (int nt = 0; nt < 8; nt++) {
            float p0 = ex2f((sacc[nt][0] - mn0) * K2C);
            float p1 = ex2f((sacc[nt][1] - mn0) * K2C);
            float p2 = ex2f((sacc[nt][2] - mn1) * K2C);
            float p3 = ex2f((sacc[nt][3] - mn1) * K2C);
            sacc[nt][0] = p0; sacc[nt][1] = p1;
            sacc[nt][2] = p2; sacc[nt][3] = p3;
            s0 += p0 + p1; s1 += p2 + p3;
        }
        s0 += __shfl_xor_sync(0xFFFFFFFFu, s0, 1);
        s0 += __shfl_xor_sync(0xFFFFFFFFu, s0, 2);
        s1 += __shfl_xor_sync(0xFFFFFFFFu, s1, 1);
        s1 += __shfl_xor_sync(0xFFFFFFFFu, s1, 2);
        l0 = l0 * a0 + s0;
        l1 = l1 * a1 + s1;

        // ---- rescale O, then O += P @ V ----
        #pragma unroll
        for (int nt = 0; nt < 16; nt++) {
            oacc[nt][0] *= a0; oacc[nt][1] *= a0;
            oacc[nt][2] *= a1; oacc[nt][3] *= a1;
        }
        #pragma unroll
        for (int kk = 0; kk < 4; kk++) {
            uint32_t ap[4];
            {
                __half2 t0 = __floats2half2_rn(sacc[2 * kk][0],     sacc[2 * kk][1]);
                __half2 t1 = __floats2half2_rn(sacc[2 * kk][2],     sacc[2 * kk][3]);
                __half2 t2 = __floats2half2_rn(sacc[2 * kk + 1][0], sacc[2 * kk + 1][1]);
                __half2 t3 = __floats2half2_rn(sacc[2 * kk + 1][2], sacc[2 * kk + 1][3]);
                ap[0] = *(uint32_t*)&t0; ap[1] = *(uint32_t*)&t1;
                ap[2] = *(uint32_t*)&t2; ap[3] = *(uint32_t*)&t3;
            }
            const int vr = kk * 16 + (lane & 7) + (((lane >> 3) & 1) << 3);
            #pragma unroll
            for (int q = 0; q < 4; q++) {
                uint32_t bv[8];
                const int vc = q * 32 + ((lane >> 4) << 3);
                ldm_x4_t(bv,     sV + vr * A_PITCH + vc * 2);
                ldm_x4_t(bv + 4, sV + vr * A_PITCH + (vc + 16) * 2);
                #pragma unroll
                for (int j = 0; j < 4; j++)
                    mma_fp16(oacc[q * 4 + j], ap, bv[j * 2], bv[j * 2 + 1]);
            }
        }
        __syncthreads();

        if (t + 2 < ntiles) {
            load_stage(kt0 + t + 2, t & 1);
            CP_COMMIT();
        }
    }

    // ---- epilogue: write partial numerator U (fp32) + stats ----
    {
        const int r = wid * 16 + (lane >> 2);
        const int row0 = q0 + r, row1 = q0 + r + 8;
        if ((lane & 3) == 0) {
            const int sbp = (split * NHEAD + h) * S_LEN;
            Sm[sbp + row0] = m0; Sl[sbp + row0] = l0;
            Sm[sbp + row1] = m1; Sl[sbp + row1] = l1;
        }
        float* Ub = U + (size_t)split * S_LEN * DIM;
        const size_t gr0 = (size_t)row0 * DIM;
        const size_t gr1 = (size_t)row1 * DIM;
        #pragma unroll
        for (int nt = 0; nt < 16; nt++) {
            const int col = h * HDIM + nt * 8 + ((lane & 3) << 1);
            float2 u0 = { oacc[nt][0], oacc[nt][1] };
            float2 u1 = { oacc[nt][2], oacc[nt][3] };
            *(float2*)&U[(size_t)split * S_LEN * DIM + gr0 + col] = u0;
            *(float2*)&U[(size_t)split * S_LEN * DIM + gr1 + col] = u1;
        }
        (void)Ub;
    }
}

// ---------------------------------------------------------------------------
// split-K combine: A = (Σ_i U_i w_i) / (Σ_i l_i w_i),  w_i = 2^{(m_i - M) K2}
// 4 elements per thread.
// ---------------------------------------------------------------------------
__global__ void combine_kernel(const float* __restrict__ U,
                               const float* __restrict__ Sm,
                               const float* __restrict__ Sl,
                               __half* __restrict__ A) {
    int idx = blockIdx.x * blockDim.x + threadIdx.x;
    int e = idx * 4;
    if (e >= S_LEN * DIM) return;
    const int row = e / DIM;
    const int col = e % DIM;
    const int h = col >> 7;

    const int s0 = (0 * NHEAD + h) * S_LEN + row;
    const int s1 = (1 * NHEAD + h) * S_LEN + row;
    const int s2 = (2 * NHEAD + h) * S_LEN + row;
    const float m0 = Sm[s0], m1 = Sm[s1], m2 = Sm[s2];
    const float M = fmaxf(m0, fmaxf(m1, m2));
    const float w0 = ex2f((m0 - M) * K2C);
    const float w1 = ex2f((m1 - M) * K2C);
    const float w2 = ex2f((m2 - M) * K2C);
    const float inv = 1.f / (Sl[s0] * w0 + Sl[s1] * w1 + Sl[s2] * w2);

    const size_t stride = (size_t)S_LEN * DIM;
    float4 u0 = *(const float4*)&U[e];
    float4 u1 = *(const float4*)&U[stride + e];
    float4 u2 = *(const float4*)&U[2 * stride + e];
    float o0 = (u0.x * w0 + u1.x * w1 + u2.x * w2) * inv;
    float o1 = (u0.y * w0 + u1.y * w1 + u2.y * w2) * inv;
    float o2 = (u0.z * w0 + u1.z * w1 + u2.z * w2) * inv;
    float o3 = (u0.w * w0 + u1.w * w1 + u2.w * w2) * inv;
    __half2 p0 = __floats2half2_rn(o0, o1);
    __half2 p1 = __floats2half2_rn(o2, o3);
    uint2 o = { *(uint32_t*)&p0, *(uint32_t*)&p1 };
    *(uint2*)&A[e] = o;
}

// ---------------------------------------------------------------------------
extern "C" void kernel_launch(void* const* d_in, const int* in_sizes, int n_in,
                              void* d_out, int out_size) {
    const float* x   = (const float*)d_in[0];
    const float* fc  = (const float*)d_in[1];
    const float* fs  = (const float*)d_in[2];
    const float* Wq  = (const float*)d_in[3];
    const float* bq  = (const float*)d_in[4];
    const float* Wk  = (const float*)d_in[5];
    const float* bk  = (const float*)d_in[6];
    const float* Wv  = (const float*)d_in[7];
    const float* bv  = (const float*)d_in[8];
    const float* Wo  = (const float*)d_in[9];
    const float* bo  = (const float*)d_in[10];
    const float* gq  = (const float*)d_in[11];
    const float* gk  = (const float*)d_in[12];
    float* out = (float*)d_out;

    float *dQ, *dK, *dU, *dSm, *dSl;
    cudaGetSymbolAddress((void**)&dQ, g_Q);
    cudaGetSymbolAddress((void**)&dK, g_K);
    cudaGetSymbolAddress((void**)&dU, g_U);
    cudaGetSymbolAddress((void**)&dSm, g_Sm);
    cudaGetSymbolAddress((void**)&dSl, g_Sl);
    __half *xf, *af, *qf, *kf, *vf, *wqkv, *wof;
    cudaGetSymbolAddress((void**)&xf, g_xf);
    cudaGetSymbolAddress((void**)&af, g_Af);
    cudaGetSymbolAddress((void**)&qf, g_Qf);
    cudaGetSymbolAddress((void**)&kf, g_Kf);
    cudaGetSymbolAddress((void**)&vf, g_Vf);
    cudaGetSymbolAddress((void**)&wqkv, g_Wqkv);
    cudaGetSymbolAddress((void**)&wof, g_Wof);

    const int nconv = X4 + 4 * W4;
    convert_all_kernel<<<(nconv + 255) / 256, 256>>>(x, Wq, Wk, Wv, Wo, xf, wqkv, wof);

    cudaFuncSetAttribute(gemm_qkv_kernel, cudaFuncAttributeMaxDynamicSharedMemorySize, G1_SMEM);
    cudaFuncSetAttribute(gemm1_kernel, cudaFuncAttributeMaxDynamicSharedMemorySize, G1_SMEM);

    dim3 gqkv(3 * DIM / GBN, S_LEN / GBM);
    gemm_qkv_kernel<<<gqkv, 256, G1_SMEM>>>(xf, wqkv, bq, bk, bv, dQ, dK, vf);

    dim3 rgrid(S_LEN, 2);
    rmsnorm_rope_kernel<<<rgrid, 256>>>(dQ, dK, gq, gk, fc, fs, qf, kf);

    cudaFuncSetAttribute(attn_mma_kernel, cudaFuncAttributeMaxDynamicSharedMemorySize, ATT_SMEM);
    dim3 agrid(S_LEN / 128, NHEAD, KSPLIT);   // (32, 12, 3) = 1152 CTAs
    attn_mma_kernel<<<agrid, 256, ATT_SMEM>>>(qf, kf, vf, dU, dSm, dSl);

    combine_kernel<<<(S_LEN * DIM / 4 + 255) / 256, 256>>>(dU, dSm, dSl, af);

    dim3 ggrid(DIM / GBN, S_LEN / GBM);
    gemm1_kernel<<<ggrid, 256, G1_SMEM>>>(af, wof, bo, out);
}